// round 1
// baseline (speedup 1.0000x reference)
#include <cuda_runtime.h>
#include <cuda_bf16.h>
#include <math.h>

// Problem constants
#define QLEN 512
#define MLEN 512
#define KLEN 1024      // QLEN + MLEN
#define RLEN 1536      // KLEN + QLEN
#define BATCH 4
#define DM 1024
#define NH 16
#define DH 64
#define SCALE 0.125f   // 1/sqrt(64)
#define LN_EPS 1e-3f

// Scratch (device globals; no allocation allowed)
__device__ float g_q [2048 * 1024];   // q_head  [i*4+b][n*64+d]
__device__ float g_k [4096 * 1024];   // k_head  [j*4+b][n*64+d]
__device__ float g_v [4096 * 1024];   // v_head
__device__ float g_kr[6144 * 1024];   // k_r     [m*4+b][n*64+d]
__device__ float g_e [2 * 512 * 4 * 16]; // ef1  [s][i][b][n]
__device__ unsigned char g_code[512 * 1024 * 4]; // bit0 = seg id, bit1 = mask
__device__ float g_av[2048 * 1024];   // attn_vec
__device__ float g_ao[2048 * 1024];   // attn_out (pre-LN)

// ---------------------------------------------------------------------------
// Projection GEMM: one launch does all 4 projections.
// Logical rows [0,2048)=h@wq -> g_q; [2048,6144)=cat@wk -> g_k;
// [6144,10240)=cat@wv -> g_v; [10240,16384)=r@wr -> g_kr.
// Tile 128x128, 256 threads, 8x8 per thread, k-step 8.
// ---------------------------------------------------------------------------
__global__ __launch_bounds__(256) void proj_gemm(
    const float* __restrict__ h, const float* __restrict__ mems,
    const float* __restrict__ r,
    const float* __restrict__ wq, const float* __restrict__ wk,
    const float* __restrict__ wv, const float* __restrict__ wr)
{
    const int K = 1024, N = 1024;
    const int rowbase = blockIdx.y * 128;
    const int colbase = blockIdx.x * 128;

    const float* W; float* C; int segbase, seg;
    if (rowbase < 2048)        { seg = 0; segbase = 0;     W = wq; C = g_q;  }
    else if (rowbase < 6144)   { seg = 1; segbase = 2048;  W = wk; C = g_k;  }
    else if (rowbase < 10240)  { seg = 2; segbase = 6144;  W = wv; C = g_v;  }
    else                       { seg = 3; segbase = 10240; W = wr; C = g_kr; }
    const int crb = rowbase - segbase;

    const int tid = threadIdx.x;
    const int trow = tid >> 1, tc4 = (tid & 1) * 4;     // A-tile loader
    const int wrk  = tid >> 5, wc4 = (tid & 31) * 4;    // W-tile loader
    const int tx = tid & 15, ty = tid >> 4;

    int lrow = crb + trow;
    const float* arow;
    if (seg == 0)      arow = h + (size_t)lrow * K;
    else if (seg == 3) arow = r + (size_t)lrow * K;
    else arow = (lrow < 2048) ? (mems + (size_t)lrow * K)
                              : (h + (size_t)(lrow - 2048) * K);

    __shared__ float As[8][132];
    __shared__ float Bs[8][132];

    float acc[8][8];
#pragma unroll
    for (int i = 0; i < 8; i++)
#pragma unroll
        for (int j = 0; j < 8; j++) acc[i][j] = 0.f;

    for (int k0 = 0; k0 < K; k0 += 8) {
        float4 av = *(const float4*)(arow + k0 + tc4);
        As[tc4 + 0][trow] = av.x;
        As[tc4 + 1][trow] = av.y;
        As[tc4 + 2][trow] = av.z;
        As[tc4 + 3][trow] = av.w;
        float4 bv = *(const float4*)(W + (size_t)(k0 + wrk) * N + colbase + wc4);
        *(float4*)&Bs[wrk][wc4] = bv;
        __syncthreads();
#pragma unroll
        for (int kk = 0; kk < 8; kk++) {
            float a[8], b[8];
#pragma unroll
            for (int i = 0; i < 8; i++) a[i] = As[kk][ty + 16 * i];
#pragma unroll
            for (int j = 0; j < 8; j++) b[j] = Bs[kk][tx + 16 * j];
#pragma unroll
            for (int i = 0; i < 8; i++)
#pragma unroll
                for (int j = 0; j < 8; j++) acc[i][j] += a[i] * b[j];
        }
        __syncthreads();
    }
#pragma unroll
    for (int i = 0; i < 8; i++)
#pragma unroll
        for (int j = 0; j < 8; j++)
            C[(size_t)(crb + ty + 16 * i) * N + colbase + tx + 16 * j] = acc[i][j];
}

// ---------------------------------------------------------------------------
// Output GEMM: g_ao[2048,1024] = g_av[2048,1024] @ wo^T  (wo is [1024, 1024] row-major,
// row = model dim h, col = n*64+d). C = A * B^T.
// ---------------------------------------------------------------------------
__global__ __launch_bounds__(256) void out_gemm(const float* __restrict__ wo)
{
    const int K = 1024, N = 1024;
    const int rowbase = blockIdx.y * 128;
    const int colbase = blockIdx.x * 128;
    const int tid = threadIdx.x;
    const int trow = tid >> 1, tc4 = (tid & 1) * 4;
    const int tx = tid & 15, ty = tid >> 4;

    const float* arow = g_av + (size_t)(rowbase + trow) * K;
    const float* brow = wo + (size_t)(colbase + trow) * K; // B row = output col

    __shared__ float As[8][132];
    __shared__ float Bs[8][132];

    float acc[8][8];
#pragma unroll
    for (int i = 0; i < 8; i++)
#pragma unroll
        for (int j = 0; j < 8; j++) acc[i][j] = 0.f;

    for (int k0 = 0; k0 < K; k0 += 8) {
        float4 av = *(const float4*)(arow + k0 + tc4);
        As[tc4 + 0][trow] = av.x;
        As[tc4 + 1][trow] = av.y;
        As[tc4 + 2][trow] = av.z;
        As[tc4 + 3][trow] = av.w;
        float4 bv = *(const float4*)(brow + k0 + tc4);   // transposed store
        Bs[tc4 + 0][trow] = bv.x;
        Bs[tc4 + 1][trow] = bv.y;
        Bs[tc4 + 2][trow] = bv.z;
        Bs[tc4 + 3][trow] = bv.w;
        __syncthreads();
#pragma unroll
        for (int kk = 0; kk < 8; kk++) {
            float a[8], b[8];
#pragma unroll
            for (int i = 0; i < 8; i++) a[i] = As[kk][ty + 16 * i];
#pragma unroll
            for (int j = 0; j < 8; j++) b[j] = Bs[kk][tx + 16 * j];
#pragma unroll
            for (int i = 0; i < 8; i++)
#pragma unroll
                for (int j = 0; j < 8; j++) acc[i][j] += a[i] * b[j];
        }
        __syncthreads();
    }
#pragma unroll
    for (int i = 0; i < 8; i++)
#pragma unroll
        for (int j = 0; j < 8; j++)
            g_ao[(size_t)(rowbase + ty + 16 * i) * N + colbase + tx + 16 * j] = acc[i][j];
}

// ---------------------------------------------------------------------------
// ef head projections: e[s,i,b,n] = sum_d (q[i,b,n,d] + r_s_bias[n,d]) * seg_embed[s,n,d]
// blockIdx.x = i*4+b, warp = n, lanes cover d & d+32.
// ---------------------------------------------------------------------------
__global__ __launch_bounds__(512) void e_kernel(
    const float* __restrict__ rsb, const float* __restrict__ seg_embed)
{
    const int row = blockIdx.x;                 // i*4+b
    const int i = row >> 2, b = row & 3;
    const int n = threadIdx.x >> 5, lane = threadIdx.x & 31;

    float q1 = g_q[(size_t)row * 1024 + n * 64 + lane]      + rsb[n * 64 + lane];
    float q2 = g_q[(size_t)row * 1024 + n * 64 + lane + 32] + rsb[n * 64 + lane + 32];
    float p0 = q1 * seg_embed[(0 * 16 + n) * 64 + lane] + q2 * seg_embed[(0 * 16 + n) * 64 + lane + 32];
    float p1 = q1 * seg_embed[(1 * 16 + n) * 64 + lane] + q2 * seg_embed[(1 * 16 + n) * 64 + lane + 32];
#pragma unroll
    for (int o = 16; o; o >>= 1) {
        p0 += __shfl_xor_sync(0xffffffffu, p0, o);
        p1 += __shfl_xor_sync(0xffffffffu, p1, o);
    }
    if (lane == 0) {
        g_e[((size_t)(0 * 512 + i) * 4 + b) * 16 + n] = p0;
        g_e[((size_t)(512 + i) * 4 + b) * 16 + n] = p1;
    }
}

// ---------------------------------------------------------------------------
// Pack seg-bit + mask-bit into one byte per (i,j,b).
// ---------------------------------------------------------------------------
__global__ __launch_bounds__(256) void code_kernel(
    const float* __restrict__ seg_mat, const float* __restrict__ attn_mask)
{
    int idx = blockIdx.x * 256 + threadIdx.x;   // (i*1024+j)*4+b
    if (idx < 512 * 1024 * 4) {
        unsigned char c = (seg_mat[(size_t)idx * 2 + 1] != 0.f) ? 1 : 0;
        if (attn_mask[idx] != 0.f) c |= 2;
        g_code[idx] = c;
    }
}

// ---------------------------------------------------------------------------
// Fused attention: flash-style online softmax over j (klen), computing
//   s(i,j) = ( qw[i].k[j] + qr[i].k_r[j-i+512] + e_{seg(i,j)}[i] ) * SCALE - 1e30*mask
// then attn_vec = softmax_j(s) @ v.
// Grid: x = b*16+n (64), y = i-tile of 64 (8). Block 256 (8 warps x 8 i-rows).
// Lane owns j-cols {lane, lane+32} of each 64-wide j-tile, and d-cols {lane, lane+32}
// of the output accumulator.
// ---------------------------------------------------------------------------
#define ATT_SMEM_FLOATS (5 * 64 * 65 + 128 * 65)
__global__ __launch_bounds__(256) void attn_kernel(
    const float* __restrict__ rwb, const float* __restrict__ rrb)
{
    extern __shared__ float sm[];
    float* qw  = sm;               // 64 x 65
    float* qr  = qw  + 64 * 65;    // 64 x 65
    float* ks  = qr  + 64 * 65;    // 64 x 65
    float* vs  = ks  + 64 * 65;    // 64 x 65
    float* Ps  = vs  + 64 * 65;    // 64 x 65
    float* krs = Ps  + 64 * 65;    // 128 x 65

    const int bn = blockIdx.x;
    const int b = bn >> 4, n = bn & 15;
    const int i0 = blockIdx.y * 64;
    const int tid = threadIdx.x;
    const int w = tid >> 5, lane = tid & 31;

    // Load q tiles with both biases folded.
    for (int t = tid; t < 64 * 16; t += 256) {
        int row = t >> 4, c4 = (t & 15) * 4;
        float4 qv = *(const float4*)(g_q + ((size_t)(i0 + row) * 4 + b) * 1024 + n * 64 + c4);
        float4 w1 = *(const float4*)(rwb + n * 64 + c4);
        float4 w2 = *(const float4*)(rrb + n * 64 + c4);
        qw[row * 65 + c4 + 0] = qv.x + w1.x;
        qw[row * 65 + c4 + 1] = qv.y + w1.y;
        qw[row * 65 + c4 + 2] = qv.z + w1.z;
        qw[row * 65 + c4 + 3] = qv.w + w1.w;
        qr[row * 65 + c4 + 0] = qv.x + w2.x;
        qr[row * 65 + c4 + 1] = qv.y + w2.y;
        qr[row * 65 + c4 + 2] = qv.z + w2.z;
        qr[row * 65 + c4 + 3] = qv.w + w2.w;
    }

    float e0v[8], e1v[8];
#pragma unroll
    for (int ii = 0; ii < 8; ii++) {
        int i = i0 + w * 8 + ii;
        e0v[ii] = g_e[((size_t)i * 4 + b) * 16 + n];
        e1v[ii] = g_e[((size_t)(512 + i) * 4 + b) * 16 + n];
    }

    float Oa[8][2], rmax[8], rsum[8];
#pragma unroll
    for (int ii = 0; ii < 8; ii++) {
        Oa[ii][0] = Oa[ii][1] = 0.f;
        rmax[ii] = -3.0e38f;
        rsum[ii] = 0.f;
    }

    for (int j0 = 0; j0 < KLEN; j0 += 64) {
        __syncthreads();
        // k / v tiles
        for (int t = tid; t < 64 * 16; t += 256) {
            int row = t >> 4, c4 = (t & 15) * 4;
            size_t goff = ((size_t)(j0 + row) * 4 + b) * 1024 + n * 64 + c4;
            float4 kv = *(const float4*)(g_k + goff);
            float4 vv = *(const float4*)(g_v + goff);
            ks[row * 65 + c4 + 0] = kv.x; ks[row * 65 + c4 + 1] = kv.y;
            ks[row * 65 + c4 + 2] = kv.z; ks[row * 65 + c4 + 3] = kv.w;
            vs[row * 65 + c4 + 0] = vv.x; vs[row * 65 + c4 + 1] = vv.y;
            vs[row * 65 + c4 + 2] = vv.z; vs[row * 65 + c4 + 3] = vv.w;
        }
        // k_r band: rows base..base+127, base = j0-i0+448 (always in [0,1536))
        int base = j0 - i0 + 448;
        for (int t = tid; t < 128 * 16; t += 256) {
            int row = t >> 4, c4 = (t & 15) * 4;
            float4 kv = *(const float4*)(g_kr + ((size_t)(base + row) * 4 + b) * 1024 + n * 64 + c4);
            krs[row * 65 + c4 + 0] = kv.x; krs[row * 65 + c4 + 1] = kv.y;
            krs[row * 65 + c4 + 2] = kv.z; krs[row * 65 + c4 + 3] = kv.w;
        }
        __syncthreads();

        float s[8][2];
#pragma unroll
        for (int ii = 0; ii < 8; ii++) { s[ii][0] = 0.f; s[ii][1] = 0.f; }

        // ac = qw . k
#pragma unroll 8
        for (int d = 0; d < 64; d++) {
            float k0v = ks[lane * 65 + d];
            float k1v = ks[(lane + 32) * 65 + d];
#pragma unroll
            for (int ii = 0; ii < 8; ii++) {
                float qv = qw[(w * 8 + ii) * 65 + d];
                s[ii][0] += qv * k0v;
                s[ii][1] += qv * k1v;
            }
        }
        // bd = qr . k_r[j-i+512] (banded, depends on both i and j)
#pragma unroll
        for (int ii = 0; ii < 8; ii++) {
            int r0 = (lane - (w * 8 + ii) + 64) * 65;
            int r1 = r0 + 32 * 65;
            const float* qrp = qr + (w * 8 + ii) * 65;
            float b0 = 0.f, b1 = 0.f;
#pragma unroll 16
            for (int d = 0; d < 64; d++) {
                float qv = qrp[d];
                b0 += qv * krs[r0 + d];
                b1 += qv * krs[r1 + d];
            }
            s[ii][0] += b0;
            s[ii][1] += b1;
        }

        // ef + mask + scale + online softmax
#pragma unroll
        for (int ii = 0; ii < 8; ii++) {
            int i = i0 + w * 8 + ii;
            unsigned char c0 = g_code[((size_t)i * 1024 + j0 + lane) * 4 + b];
            unsigned char c1 = g_code[((size_t)i * 1024 + j0 + lane + 32) * 4 + b];
            float s0 = (s[ii][0] + ((c0 & 1) ? e1v[ii] : e0v[ii])) * SCALE;
            float s1 = (s[ii][1] + ((c1 & 1) ? e1v[ii] : e0v[ii])) * SCALE;
            if (c0 & 2) s0 -= 1e30f;
            if (c1 & 2) s1 -= 1e30f;
            float m = fmaxf(s0, s1);
#pragma unroll
            for (int o = 16; o; o >>= 1) m = fmaxf(m, __shfl_xor_sync(0xffffffffu, m, o));
            float nm = fmaxf(rmax[ii], m);
            float corr = __expf(rmax[ii] - nm);
            rmax[ii] = nm;
            float p0 = __expf(s0 - nm);
            float p1 = __expf(s1 - nm);
            float rs = p0 + p1;
#pragma unroll
            for (int o = 16; o; o >>= 1) rs += __shfl_xor_sync(0xffffffffu, rs, o);
            rsum[ii] = rsum[ii] * corr + rs;
            Oa[ii][0] *= corr;
            Oa[ii][1] *= corr;
            Ps[(w * 8 + ii) * 65 + lane] = p0;
            Ps[(w * 8 + ii) * 65 + lane + 32] = p1;
        }
        __syncwarp();
        // O += P @ V  (lane owns d = lane, lane+32)
#pragma unroll 8
        for (int j = 0; j < 64; j++) {
            float v0 = vs[j * 65 + lane];
            float v1 = vs[j * 65 + lane + 32];
#pragma unroll
            for (int ii = 0; ii < 8; ii++) {
                float p = Ps[(w * 8 + ii) * 65 + j];
                Oa[ii][0] += p * v0;
                Oa[ii][1] += p * v1;
            }
        }
    }

#pragma unroll
    for (int ii = 0; ii < 8; ii++) {
        float inv = 1.f / rsum[ii];
        int i = i0 + w * 8 + ii;
        float* o = g_av + ((size_t)i * 4 + b) * 1024 + n * 64;
        o[lane]      = Oa[ii][0] * inv;
        o[lane + 32] = Oa[ii][1] * inv;
    }
}

// ---------------------------------------------------------------------------
// Residual + LayerNorm: out = LN(g_ao + h) * gamma + beta (per 1024-row)
// ---------------------------------------------------------------------------
__global__ __launch_bounds__(256) void ln_kernel(
    const float* __restrict__ hres, const float* __restrict__ gamma,
    const float* __restrict__ beta, float* __restrict__ out)
{
    __shared__ float xb[1024];
    __shared__ float red[8];
    const int row = blockIdx.x;
    const int tid = threadIdx.x;
    const float* ao = g_ao + (size_t)row * 1024;
    const float* hh = hres + (size_t)row * 1024;

    float s = 0.f;
    for (int c = tid; c < 1024; c += 256) {
        float x = ao[c] + hh[c];
        xb[c] = x;
        s += x;
    }
#pragma unroll
    for (int o = 16; o; o >>= 1) s += __shfl_xor_sync(0xffffffffu, s, o);
    if ((tid & 31) == 0) red[tid >> 5] = s;
    __syncthreads();
    float tot = 0.f;
#pragma unroll
    for (int k = 0; k < 8; k++) tot += red[k];
    const float mean = tot * (1.f / 1024.f);
    __syncthreads();

    float s2 = 0.f;
    for (int c = tid; c < 1024; c += 256) {
        float dx = xb[c] - mean;
        s2 += dx * dx;
    }
#pragma unroll
    for (int o = 16; o; o >>= 1) s2 += __shfl_xor_sync(0xffffffffu, s2, o);
    if ((tid & 31) == 0) red[tid >> 5] = s2;
    __syncthreads();
    float tot2 = 0.f;
#pragma unroll
    for (int k = 0; k < 8; k++) tot2 += red[k];
    const float inv = rsqrtf(tot2 * (1.f / 1024.f) + LN_EPS);

    for (int c = tid; c < 1024; c += 256)
        out[(size_t)row * 1024 + c] = (xb[c] - mean) * inv * gamma[c] + beta[c];
}

// ---------------------------------------------------------------------------
extern "C" void kernel_launch(void* const* d_in, const int* in_sizes, int n_in,
                              void* d_out, int out_size)
{
    const float* rwb       = (const float*)d_in[0];
    const float* rsb       = (const float*)d_in[1];
    const float* rrb       = (const float*)d_in[2];
    const float* seg_embed = (const float*)d_in[3];
    const float* h         = (const float*)d_in[4];
    const float* r         = (const float*)d_in[5];
    const float* mems      = (const float*)d_in[6];
    const float* seg_mat   = (const float*)d_in[7];
    const float* attn_mask = (const float*)d_in[8];
    const float* wq        = (const float*)d_in[9];
    const float* wk        = (const float*)d_in[10];
    const float* wv        = (const float*)d_in[11];
    const float* wr        = (const float*)d_in[12];
    const float* wo        = (const float*)d_in[13];
    const float* gamma     = (const float*)d_in[14];
    const float* beta      = (const float*)d_in[15];

    const int att_smem = ATT_SMEM_FLOATS * (int)sizeof(float); // 116480 B
    cudaFuncSetAttribute(attn_kernel, cudaFuncAttributeMaxDynamicSharedMemorySize, att_smem);

    proj_gemm<<<dim3(8, 128), 256>>>(h, mems, r, wq, wk, wv, wr);
    e_kernel<<<2048, 512>>>(rsb, seg_embed);
    code_kernel<<<8192, 256>>>(seg_mat, attn_mask);
    attn_kernel<<<dim3(64, 8), 256, att_smem>>>(rwb, rrb);
    out_gemm<<<dim3(8, 16), 256>>>(wo);
    ln_kernel<<<2048, 256>>>(h, gamma, beta, (float*)d_out);
}

// round 2
// speedup vs baseline: 1.5558x; 1.5558x over previous
#include <cuda_runtime.h>
#include <cuda_bf16.h>
#include <math.h>

// Problem constants
#define QLEN 512
#define MLEN 512
#define KLEN 1024
#define RLEN 1536
#define BATCH 4
#define DM 1024
#define NH 16
#define DH 64
#define SCALE 0.125f
#define LN_EPS 1e-3f

// Scratch (device globals; no allocation allowed)
__device__ float g_q [2048 * 1024];   // q_head  [i*4+b][n*64+d]
__device__ float g_k [4096 * 1024];   // k_head  [j*4+b][n*64+d]
__device__ float g_v [4096 * 1024];   // v_head
__device__ float g_kr[6144 * 1024];   // k_r     [m*4+b][n*64+d]
__device__ float g_e [2 * 512 * 4 * 16];   // ef  [s][i][b][n]
__device__ float g_u [4096 * 16];     // rwb·k   [(j*4+b)*16+n]
__device__ float g_t [6144 * 16];     // rrb·kr  [(m*4+b)*16+n]
__device__ unsigned char g_code[512 * 1024 * 4]; // bit0=seg, bit1=mask
__device__ float g_av[2048 * 1024];   // attn_vec
__device__ float g_ao[2048 * 1024];   // attn_out (pre-LN)

// ---------------------------------------------------------------------------
// tf32 helpers
// ---------------------------------------------------------------------------
__device__ __forceinline__ unsigned f2tf(float x) {
    unsigned r; asm("cvt.rna.tf32.f32 %0, %1;" : "=r"(r) : "f"(x)); return r;
}
__device__ __forceinline__ float f2tff(float x) { return __uint_as_float(f2tf(x)); }

__device__ __forceinline__ void mma_tf32(float* d, const unsigned* a,
                                         const unsigned* b) {
    asm volatile(
        "mma.sync.aligned.m16n8k8.row.col.f32.tf32.tf32.f32 "
        "{%0,%1,%2,%3}, {%4,%5,%6,%7}, {%8,%9}, {%0,%1,%2,%3};\n"
        : "+f"(d[0]), "+f"(d[1]), "+f"(d[2]), "+f"(d[3])
        : "r"(a[0]), "r"(a[1]), "r"(a[2]), "r"(a[3]),
          "r"(b[0]), "r"(b[1]));
}

// ---------------------------------------------------------------------------
// Projection GEMM (tf32 tensor cores). One launch does all 4 projections.
// Rows [0,2048)=h@wq -> g_q; [2048,6144)=cat@wk -> g_k;
// [6144,10240)=cat@wv -> g_v; [10240,16384)=r@wr -> g_kr.
// Block tile 128x128, 8 warps (4m x 2n), warp tile 32x64, k-chunk 16.
// ---------------------------------------------------------------------------
__global__ __launch_bounds__(256, 2) void proj_mma(
    const float* __restrict__ h, const float* __restrict__ mems,
    const float* __restrict__ r,
    const float* __restrict__ wq, const float* __restrict__ wk,
    const float* __restrict__ wv, const float* __restrict__ wr)
{
    const int rowbase = blockIdx.y * 128;
    const int colbase = blockIdx.x * 128;

    const float* W; float* C; int segbase, seg;
    if (rowbase < 2048)        { seg = 0; segbase = 0;     W = wq; C = g_q;  }
    else if (rowbase < 6144)   { seg = 1; segbase = 2048;  W = wk; C = g_k;  }
    else if (rowbase < 10240)  { seg = 2; segbase = 6144;  W = wv; C = g_v;  }
    else                       { seg = 3; segbase = 10240; W = wr; C = g_kr; }
    const int crb = rowbase - segbase;

    const int tid = threadIdx.x;
    const int lane = tid & 31, warp = tid >> 5;
    const int wm = warp & 3, wn = warp >> 2;
    const int grp = lane >> 2, thr = lane & 3;

    __shared__ float As[16][132];
    __shared__ float Bs[16][132];

    // A loader: m = tid&127, k-offset 8*(tid>>7)
    const int am = tid & 127;
    const int akq = tid >> 7;
    // B loader: rows bkr, bkr+8 ; cols bc4..bc4+3
    const int bc4 = (tid & 31) * 4;
    const int bkr = tid >> 5;

    int lrow = crb + am;
    const float* arow;
    if (seg == 0)      arow = h + (size_t)lrow * 1024;
    else if (seg == 3) arow = r + (size_t)lrow * 1024;
    else arow = (lrow < 2048) ? (mems + (size_t)lrow * 1024)
                              : (h + (size_t)(lrow - 2048) * 1024);

    float acc[2][8][4];
#pragma unroll
    for (int mf = 0; mf < 2; mf++)
#pragma unroll
        for (int nf = 0; nf < 8; nf++)
#pragma unroll
            for (int q = 0; q < 4; q++) acc[mf][nf][q] = 0.f;

    float4 ra0 = *(const float4*)(arow + akq * 8);
    float4 ra1 = *(const float4*)(arow + akq * 8 + 4);
    float4 rb0 = *(const float4*)(W + (size_t)bkr * 1024 + colbase + bc4);
    float4 rb1 = *(const float4*)(W + (size_t)(bkr + 8) * 1024 + colbase + bc4);

    for (int k0 = 0; k0 < 1024; k0 += 16) {
        __syncthreads();
        As[akq * 8 + 0][am] = f2tff(ra0.x);
        As[akq * 8 + 1][am] = f2tff(ra0.y);
        As[akq * 8 + 2][am] = f2tff(ra0.z);
        As[akq * 8 + 3][am] = f2tff(ra0.w);
        As[akq * 8 + 4][am] = f2tff(ra1.x);
        As[akq * 8 + 5][am] = f2tff(ra1.y);
        As[akq * 8 + 6][am] = f2tff(ra1.z);
        As[akq * 8 + 7][am] = f2tff(ra1.w);
        float4 cb;
        cb.x = f2tff(rb0.x); cb.y = f2tff(rb0.y); cb.z = f2tff(rb0.z); cb.w = f2tff(rb0.w);
        *(float4*)&Bs[bkr][bc4] = cb;
        cb.x = f2tff(rb1.x); cb.y = f2tff(rb1.y); cb.z = f2tff(rb1.z); cb.w = f2tff(rb1.w);
        *(float4*)&Bs[bkr + 8][bc4] = cb;
        __syncthreads();
        if (k0 + 16 < 1024) {
            ra0 = *(const float4*)(arow + k0 + 16 + akq * 8);
            ra1 = *(const float4*)(arow + k0 + 16 + akq * 8 + 4);
            rb0 = *(const float4*)(W + (size_t)(k0 + 16 + bkr) * 1024 + colbase + bc4);
            rb1 = *(const float4*)(W + (size_t)(k0 + 24 + bkr) * 1024 + colbase + bc4);
        }
#pragma unroll
        for (int ks = 0; ks < 2; ks++) {
            const int kb = ks * 8 + thr;
            unsigned a[2][4], bb[8][2];
#pragma unroll
            for (int mf = 0; mf < 2; mf++) {
                int rr = wm * 32 + mf * 16 + grp;
                a[mf][0] = __float_as_uint(As[kb][rr]);
                a[mf][1] = __float_as_uint(As[kb][rr + 8]);
                a[mf][2] = __float_as_uint(As[kb + 4][rr]);
                a[mf][3] = __float_as_uint(As[kb + 4][rr + 8]);
            }
#pragma unroll
            for (int nf = 0; nf < 8; nf++) {
                int cc = wn * 64 + nf * 8 + grp;
                bb[nf][0] = __float_as_uint(Bs[kb][cc]);
                bb[nf][1] = __float_as_uint(Bs[kb + 4][cc]);
            }
#pragma unroll
            for (int mf = 0; mf < 2; mf++)
#pragma unroll
                for (int nf = 0; nf < 8; nf++)
                    mma_tf32(acc[mf][nf], a[mf], bb[nf]);
        }
    }
#pragma unroll
    for (int mf = 0; mf < 2; mf++)
#pragma unroll
        for (int nf = 0; nf < 8; nf++) {
            int rr = crb + wm * 32 + mf * 16 + grp;
            int cc = colbase + wn * 64 + nf * 8 + thr * 2;
            *(float2*)&C[(size_t)rr * 1024 + cc] = make_float2(acc[mf][nf][0], acc[mf][nf][1]);
            *(float2*)&C[(size_t)(rr + 8) * 1024 + cc] = make_float2(acc[mf][nf][2], acc[mf][nf][3]);
        }
}

// ---------------------------------------------------------------------------
// Output GEMM (tf32): g_ao[2048,1024] = g_av @ wo^T.
// ---------------------------------------------------------------------------
__global__ __launch_bounds__(256, 2) void out_mma(const float* __restrict__ wo)
{
    const int rowbase = blockIdx.y * 128;
    const int colbase = blockIdx.x * 128;
    const int tid = threadIdx.x;
    const int lane = tid & 31, warp = tid >> 5;
    const int wm = warp & 3, wn = warp >> 2;
    const int grp = lane >> 2, thr = lane & 3;

    __shared__ float As[16][132];
    __shared__ float Bs[16][132];

    const int am = tid & 127;
    const int akq = tid >> 7;
    const int bn = tid & 127;
    const int bkq = tid >> 7;

    const float* arow = g_av + (size_t)(rowbase + am) * 1024;
    const float* brow = wo + (size_t)(colbase + bn) * 1024;

    float acc[2][8][4];
#pragma unroll
    for (int mf = 0; mf < 2; mf++)
#pragma unroll
        for (int nf = 0; nf < 8; nf++)
#pragma unroll
            for (int q = 0; q < 4; q++) acc[mf][nf][q] = 0.f;

    float4 ra0 = *(const float4*)(arow + akq * 8);
    float4 ra1 = *(const float4*)(arow + akq * 8 + 4);
    float4 rb0 = *(const float4*)(brow + bkq * 8);
    float4 rb1 = *(const float4*)(brow + bkq * 8 + 4);

    for (int k0 = 0; k0 < 1024; k0 += 16) {
        __syncthreads();
        As[akq * 8 + 0][am] = f2tff(ra0.x);
        As[akq * 8 + 1][am] = f2tff(ra0.y);
        As[akq * 8 + 2][am] = f2tff(ra0.z);
        As[akq * 8 + 3][am] = f2tff(ra0.w);
        As[akq * 8 + 4][am] = f2tff(ra1.x);
        As[akq * 8 + 5][am] = f2tff(ra1.y);
        As[akq * 8 + 6][am] = f2tff(ra1.z);
        As[akq * 8 + 7][am] = f2tff(ra1.w);
        Bs[bkq * 8 + 0][bn] = f2tff(rb0.x);
        Bs[bkq * 8 + 1][bn] = f2tff(rb0.y);
        Bs[bkq * 8 + 2][bn] = f2tff(rb0.z);
        Bs[bkq * 8 + 3][bn] = f2tff(rb0.w);
        Bs[bkq * 8 + 4][bn] = f2tff(rb1.x);
        Bs[bkq * 8 + 5][bn] = f2tff(rb1.y);
        Bs[bkq * 8 + 6][bn] = f2tff(rb1.z);
        Bs[bkq * 8 + 7][bn] = f2tff(rb1.w);
        __syncthreads();
        if (k0 + 16 < 1024) {
            ra0 = *(const float4*)(arow + k0 + 16 + akq * 8);
            ra1 = *(const float4*)(arow + k0 + 16 + akq * 8 + 4);
            rb0 = *(const float4*)(brow + k0 + 16 + bkq * 8);
            rb1 = *(const float4*)(brow + k0 + 16 + bkq * 8 + 4);
        }
#pragma unroll
        for (int ks = 0; ks < 2; ks++) {
            const int kb = ks * 8 + thr;
            unsigned a[2][4], bb[8][2];
#pragma unroll
            for (int mf = 0; mf < 2; mf++) {
                int rr = wm * 32 + mf * 16 + grp;
                a[mf][0] = __float_as_uint(As[kb][rr]);
                a[mf][1] = __float_as_uint(As[kb][rr + 8]);
                a[mf][2] = __float_as_uint(As[kb + 4][rr]);
                a[mf][3] = __float_as_uint(As[kb + 4][rr + 8]);
            }
#pragma unroll
            for (int nf = 0; nf < 8; nf++) {
                int cc = wn * 64 + nf * 8 + grp;
                bb[nf][0] = __float_as_uint(Bs[kb][cc]);
                bb[nf][1] = __float_as_uint(Bs[kb + 4][cc]);
            }
#pragma unroll
            for (int mf = 0; mf < 2; mf++)
#pragma unroll
                for (int nf = 0; nf < 8; nf++)
                    mma_tf32(acc[mf][nf], a[mf], bb[nf]);
        }
    }
#pragma unroll
    for (int mf = 0; mf < 2; mf++)
#pragma unroll
        for (int nf = 0; nf < 8; nf++) {
            int rr = rowbase + wm * 32 + mf * 16 + grp;
            int cc = colbase + wn * 64 + nf * 8 + thr * 2;
            *(float2*)&g_ao[(size_t)rr * 1024 + cc] = make_float2(acc[mf][nf][0], acc[mf][nf][1]);
            *(float2*)&g_ao[(size_t)(rr + 8) * 1024 + cc] = make_float2(acc[mf][nf][2], acc[mf][nf][3]);
        }
}

// ---------------------------------------------------------------------------
// ef head projections: e[s,i,b,n] = sum_d (q + r_s_bias) * seg_embed[s]
// ---------------------------------------------------------------------------
__global__ __launch_bounds__(512) void e_kernel(
    const float* __restrict__ rsb, const float* __restrict__ seg_embed)
{
    const int row = blockIdx.x;                 // i*4+b
    const int i = row >> 2, b = row & 3;
    const int n = threadIdx.x >> 5, lane = threadIdx.x & 31;

    float q1 = g_q[(size_t)row * 1024 + n * 64 + lane]      + rsb[n * 64 + lane];
    float q2 = g_q[(size_t)row * 1024 + n * 64 + lane + 32] + rsb[n * 64 + lane + 32];
    float p0 = q1 * seg_embed[(0 * 16 + n) * 64 + lane] + q2 * seg_embed[(0 * 16 + n) * 64 + lane + 32];
    float p1 = q1 * seg_embed[(1 * 16 + n) * 64 + lane] + q2 * seg_embed[(1 * 16 + n) * 64 + lane + 32];
#pragma unroll
    for (int o = 16; o; o >>= 1) {
        p0 += __shfl_xor_sync(0xffffffffu, p0, o);
        p1 += __shfl_xor_sync(0xffffffffu, p1, o);
    }
    if (lane == 0) {
        g_e[((size_t)(0 * 512 + i) * 4 + b) * 16 + n] = p0;
        g_e[((size_t)(512 + i) * 4 + b) * 16 + n] = p1;
    }
}

// ---------------------------------------------------------------------------
// u[j,b,n] = rwb[n]·k[j,b,n]  (rows < 4096) ;  t[m,b,n] = rrb[n]·kr[m,b,n]
// ---------------------------------------------------------------------------
__global__ __launch_bounds__(512) void ut_kernel(
    const float* __restrict__ rwb, const float* __restrict__ rrb)
{
    int row = blockIdx.x;
    const float* src; const float* bias; float* dst;
    if (row < 4096) { src = g_k + (size_t)row * 1024;  bias = rwb; dst = g_u + (size_t)row * 16; }
    else { row -= 4096; src = g_kr + (size_t)row * 1024; bias = rrb; dst = g_t + (size_t)row * 16; }
    const int n = threadIdx.x >> 5, lane = threadIdx.x & 31;
    float p = src[n * 64 + lane] * bias[n * 64 + lane]
            + src[n * 64 + lane + 32] * bias[n * 64 + lane + 32];
#pragma unroll
    for (int o = 16; o; o >>= 1) p += __shfl_xor_sync(0xffffffffu, p, o);
    if (lane == 0) dst[n] = p;
}

// ---------------------------------------------------------------------------
// Pack seg-bit + mask-bit into one byte per (i,j,b).
// ---------------------------------------------------------------------------
__global__ __launch_bounds__(256) void code_kernel(
    const float* __restrict__ seg_mat, const float* __restrict__ attn_mask)
{
    int idx = blockIdx.x * 256 + threadIdx.x;
    if (idx < 512 * 1024 * 4) {
        unsigned char c = (seg_mat[(size_t)idx * 2 + 1] != 0.f) ? 1 : 0;
        if (attn_mask[idx] != 0.f) c |= 2;
        g_code[idx] = c;
    }
}

// ---------------------------------------------------------------------------
// Fused attention (flash-style, fp32):
//  s(i,j) = ( q·k[j] + q·kr[j-i+512] + u[j] + t[j-i+512] + e_sel(i,j) )*SCALE - mask
// smem: q 64x68, ks 64x68, Ps 64x68, krs 128x68, vs 64x64, ub 64, tb 128
// = 26048 floats = 104,192 B -> 2 blocks/SM.
// ---------------------------------------------------------------------------
#define AT_STRIDE 68
#define ATT_SMEM_FLOATS (3 * 64 * AT_STRIDE + 128 * AT_STRIDE + 64 * 64 + 64 + 128)

__global__ __launch_bounds__(256, 2) void attn_kernel()
{
    extern __shared__ float sm[];
    float* q   = sm;                         // 64 x 68
    float* ks  = q  + 64 * AT_STRIDE;        // 64 x 68
    float* Ps  = ks + 64 * AT_STRIDE;        // 64 x 68
    float* krs = Ps + 64 * AT_STRIDE;        // 128 x 68
    float* vs  = krs + 128 * AT_STRIDE;      // 64 x 64 (no pad: column reads)
    float* ub  = vs + 64 * 64;               // 64
    float* tb  = ub + 64;                    // 128

    const int bn = blockIdx.x;
    const int b = bn >> 4, n = bn & 15;
    const int i0 = blockIdx.y * 64;
    const int tid = threadIdx.x;
    const int w = tid >> 5, lane = tid & 31;

    // q tile (once)
    for (int t = tid; t < 64 * 16; t += 256) {
        int row = t >> 4, c4 = (t & 15) * 4;
        *(float4*)&q[row * AT_STRIDE + c4] =
            *(const float4*)(g_q + ((size_t)(i0 + row) * 4 + b) * 1024 + n * 64 + c4);
    }

    float e0v[8], e1v[8];
#pragma unroll
    for (int ii = 0; ii < 8; ii++) {
        int i = i0 + w * 8 + ii;
        e0v[ii] = g_e[((size_t)i * 4 + b) * 16 + n];
        e1v[ii] = g_e[((size_t)(512 + i) * 4 + b) * 16 + n];
    }

    float Oa0[8], Oa1[8], rmax[8], rsum[8];
#pragma unroll
    for (int ii = 0; ii < 8; ii++) {
        Oa0[ii] = Oa1[ii] = 0.f;
        rmax[ii] = -3.0e38f;
        rsum[ii] = 0.f;
    }

    for (int j0 = 0; j0 < KLEN; j0 += 64) {
        __syncthreads();
        for (int t = tid; t < 64 * 16; t += 256) {
            int row = t >> 4, c4 = (t & 15) * 4;
            size_t goff = ((size_t)(j0 + row) * 4 + b) * 1024 + n * 64 + c4;
            *(float4*)&ks[row * AT_STRIDE + c4] = *(const float4*)(g_k + goff);
            *(float4*)&vs[row * 64 + c4]       = *(const float4*)(g_v + goff);
        }
        const int base = j0 - i0 + 448;
        for (int t = tid; t < 128 * 16; t += 256) {
            int row = t >> 4, c4 = (t & 15) * 4;
            *(float4*)&krs[row * AT_STRIDE + c4] =
                *(const float4*)(g_kr + ((size_t)(base + row) * 4 + b) * 1024 + n * 64 + c4);
        }
        if (tid < 64) ub[tid] = g_u[((size_t)(j0 + tid) * 4 + b) * 16 + n];
        else if (tid < 192) {
            int m = tid - 64;
            tb[m] = g_t[((size_t)(base + m) * 4 + b) * 16 + n];
        }
        __syncthreads();

        float s0[8], s1[8];
#pragma unroll
        for (int ii = 0; ii < 8; ii++) { s0[ii] = 0.f; s1[ii] = 0.f; }

        // ac = q . k
#pragma unroll 4
        for (int d4 = 0; d4 < 64; d4 += 4) {
            float4 k0 = *(float4*)&ks[lane * AT_STRIDE + d4];
            float4 k1 = *(float4*)&ks[(lane + 32) * AT_STRIDE + d4];
#pragma unroll
            for (int ii = 0; ii < 8; ii++) {
                float4 qv = *(float4*)&q[(w * 8 + ii) * AT_STRIDE + d4];
                s0[ii] += qv.x * k0.x + qv.y * k0.y + qv.z * k0.z + qv.w * k0.w;
                s1[ii] += qv.x * k1.x + qv.y * k1.y + qv.z * k1.z + qv.w * k1.w;
            }
        }
        // bd = q . kr[banded]
#pragma unroll
        for (int ii = 0; ii < 8; ii++) {
            const int il = w * 8 + ii;
            const float* krp = krs + (lane - il + 64) * AT_STRIDE;
            const float* qp  = q + il * AT_STRIDE;
            float b0 = 0.f, b1 = 0.f;
#pragma unroll 8
            for (int d4 = 0; d4 < 64; d4 += 4) {
                float4 qv = *(const float4*)(qp + d4);
                float4 r0 = *(const float4*)(krp + d4);
                float4 r1 = *(const float4*)(krp + 32 * AT_STRIDE + d4);
                b0 += qv.x * r0.x + qv.y * r0.y + qv.z * r0.z + qv.w * r0.w;
                b1 += qv.x * r1.x + qv.y * r1.y + qv.z * r1.z + qv.w * r1.w;
            }
            s0[ii] += b0;
            s1[ii] += b1;
        }

        // bias terms + ef + mask + scale + online softmax
#pragma unroll
        for (int ii = 0; ii < 8; ii++) {
            const int il = w * 8 + ii;
            const int i = i0 + il;
            unsigned char c0 = g_code[((size_t)i * 1024 + j0 + lane) * 4 + b];
            unsigned char c1 = g_code[((size_t)i * 1024 + j0 + lane + 32) * 4 + b];
            float sc0 = (s0[ii] + ub[lane] + tb[lane - il + 64]
                         + ((c0 & 1) ? e1v[ii] : e0v[ii])) * SCALE;
            float sc1 = (s1[ii] + ub[lane + 32] + tb[lane - il + 96]
                         + ((c1 & 1) ? e1v[ii] : e0v[ii])) * SCALE;
            if (c0 & 2) sc0 -= 1e30f;
            if (c1 & 2) sc1 -= 1e30f;
            float m = fmaxf(sc0, sc1);
#pragma unroll
            for (int o = 16; o; o >>= 1) m = fmaxf(m, __shfl_xor_sync(0xffffffffu, m, o));
            float nm = fmaxf(rmax[ii], m);
            float corr = __expf(rmax[ii] - nm);
            rmax[ii] = nm;
            float p0 = __expf(sc0 - nm);
            float p1 = __expf(sc1 - nm);
            float rs = p0 + p1;
#pragma unroll
            for (int o = 16; o; o >>= 1) rs += __shfl_xor_sync(0xffffffffu, rs, o);
            rsum[ii] = rsum[ii] * corr + rs;
            Oa0[ii] *= corr;
            Oa1[ii] *= corr;
            Ps[il * AT_STRIDE + lane] = p0;
            Ps[il * AT_STRIDE + lane + 32] = p1;
        }
        __syncwarp();
        // O += P @ V  (lane owns d = lane, lane+32)
#pragma unroll 4
        for (int j4 = 0; j4 < 64; j4 += 4) {
            float v00 = vs[(j4 + 0) * 64 + lane], v01 = vs[(j4 + 0) * 64 + lane + 32];
            float v10 = vs[(j4 + 1) * 64 + lane], v11 = vs[(j4 + 1) * 64 + lane + 32];
            float v20 = vs[(j4 + 2) * 64 + lane], v21 = vs[(j4 + 2) * 64 + lane + 32];
            float v30 = vs[(j4 + 3) * 64 + lane], v31 = vs[(j4 + 3) * 64 + lane + 32];
#pragma unroll
            for (int ii = 0; ii < 8; ii++) {
                float4 p = *(float4*)&Ps[(w * 8 + ii) * AT_STRIDE + j4];
                Oa0[ii] += p.x * v00 + p.y * v10 + p.z * v20 + p.w * v30;
                Oa1[ii] += p.x * v01 + p.y * v11 + p.z * v21 + p.w * v31;
            }
        }
    }

#pragma unroll
    for (int ii = 0; ii < 8; ii++) {
        float inv = 1.f / rsum[ii];
        int i = i0 + w * 8 + ii;
        float* o = g_av + ((size_t)i * 4 + b) * 1024 + n * 64;
        o[lane]      = Oa0[ii] * inv;
        o[lane + 32] = Oa1[ii] * inv;
    }
}

// ---------------------------------------------------------------------------
// Residual + LayerNorm
// ---------------------------------------------------------------------------
__global__ __launch_bounds__(256) void ln_kernel(
    const float* __restrict__ hres, const float* __restrict__ gamma,
    const float* __restrict__ beta, float* __restrict__ out)
{
    __shared__ float xb[1024];
    __shared__ float red[8];
    const int row = blockIdx.x;
    const int tid = threadIdx.x;
    const float* ao = g_ao + (size_t)row * 1024;
    const float* hh = hres + (size_t)row * 1024;

    float s = 0.f;
    for (int c = tid; c < 1024; c += 256) {
        float x = ao[c] + hh[c];
        xb[c] = x;
        s += x;
    }
#pragma unroll
    for (int o = 16; o; o >>= 1) s += __shfl_xor_sync(0xffffffffu, s, o);
    if ((tid & 31) == 0) red[tid >> 5] = s;
    __syncthreads();
    float tot = 0.f;
#pragma unroll
    for (int k = 0; k < 8; k++) tot += red[k];
    const float mean = tot * (1.f / 1024.f);
    __syncthreads();

    float s2 = 0.f;
    for (int c = tid; c < 1024; c += 256) {
        float dx = xb[c] - mean;
        s2 += dx * dx;
    }
#pragma unroll
    for (int o = 16; o; o >>= 1) s2 += __shfl_xor_sync(0xffffffffu, s2, o);
    if ((tid & 31) == 0) red[tid >> 5] = s2;
    __syncthreads();
    float tot2 = 0.f;
#pragma unroll
    for (int k = 0; k < 8; k++) tot2 += red[k];
    const float inv = rsqrtf(tot2 * (1.f / 1024.f) + LN_EPS);

    for (int c = tid; c < 1024; c += 256)
        out[(size_t)row * 1024 + c] = (xb[c] - mean) * inv * gamma[c] + beta[c];
}

// ---------------------------------------------------------------------------
extern "C" void kernel_launch(void* const* d_in, const int* in_sizes, int n_in,
                              void* d_out, int out_size)
{
    const float* rwb       = (const float*)d_in[0];
    const float* rsb       = (const float*)d_in[1];
    const float* rrb       = (const float*)d_in[2];
    const float* seg_embed = (const float*)d_in[3];
    const float* h         = (const float*)d_in[4];
    const float* r         = (const float*)d_in[5];
    const float* mems      = (const float*)d_in[6];
    const float* seg_mat   = (const float*)d_in[7];
    const float* attn_mask = (const float*)d_in[8];
    const float* wq        = (const float*)d_in[9];
    const float* wk        = (const float*)d_in[10];
    const float* wv        = (const float*)d_in[11];
    const float* wr        = (const float*)d_in[12];
    const float* wo        = (const float*)d_in[13];
    const float* gamma     = (const float*)d_in[14];
    const float* beta      = (const float*)d_in[15];

    const int att_smem = ATT_SMEM_FLOATS * (int)sizeof(float); // 104192 B
    cudaFuncSetAttribute(attn_kernel, cudaFuncAttributeMaxDynamicSharedMemorySize, att_smem);

    proj_mma<<<dim3(8, 128), 256>>>(h, mems, r, wq, wk, wv, wr);
    e_kernel<<<2048, 512>>>(rsb, seg_embed);
    ut_kernel<<<10240, 512>>>(rwb, rrb);
    code_kernel<<<8192, 256>>>(seg_mat, attn_mask);
    attn_kernel<<<dim3(64, 8), 256, att_smem>>>();
    out_mma<<<dim3(8, 16), 256>>>(wo);
    ln_kernel<<<2048, 256>>>(h, gamma, beta, (float*)d_out);
}

// round 4
// speedup vs baseline: 2.3674x; 1.5217x over previous
#include <cuda_runtime.h>
#include <cuda_bf16.h>
#include <math.h>

// Problem constants
#define QLEN 512
#define MLEN 512
#define KLEN 1024
#define RLEN 1536
#define BATCH 4
#define DM 1024
#define NH 16
#define DH 64
#define SCALE 0.125f
#define LN_EPS 1e-3f

// Scratch (device globals; no allocation allowed)
__device__ float g_q [2048 * 1024];   // q_head  [i*4+b][n*64+d]   (tf32-rounded)
__device__ float g_k [4096 * 1024];   // k_head                    (tf32-rounded)
__device__ float g_v [4096 * 1024];   // v_head                    (tf32-rounded)
__device__ float g_kr[6144 * 1024];   // k_r                       (tf32-rounded)
__device__ float g_e [2 * 512 * 4 * 16];   // ef  [s][i][b][n]
__device__ float g_u [4096 * 16];     // rwb·k   [(j*4+b)*16+n]
__device__ float g_t [6144 * 16];     // rrb·kr  [(m*4+b)*16+n]
__device__ unsigned char g_code[4 * 512 * 1024]; // [b][i][j]: bit0=seg, bit1=mask
__device__ float g_av[2048 * 1024];   // attn_vec
__device__ float g_ao[2048 * 1024];   // attn_out (pre-LN)

// ---------------------------------------------------------------------------
// tf32 helpers
// ---------------------------------------------------------------------------
__device__ __forceinline__ unsigned f2tf(float x) {
    unsigned r; asm("cvt.rna.tf32.f32 %0, %1;" : "=r"(r) : "f"(x)); return r;
}
__device__ __forceinline__ float f2tff(float x) { return __uint_as_float(f2tf(x)); }

__device__ __forceinline__ void mma_tf32(float* d, const unsigned* a,
                                         const unsigned* b) {
    asm volatile(
        "mma.sync.aligned.m16n8k8.row.col.f32.tf32.tf32.f32 "
        "{%0,%1,%2,%3}, {%4,%5,%6,%7}, {%8,%9}, {%0,%1,%2,%3};\n"
        : "+f"(d[0]), "+f"(d[1]), "+f"(d[2]), "+f"(d[3])
        : "r"(a[0]), "r"(a[1]), "r"(a[2]), "r"(a[3]),
          "r"(b[0]), "r"(b[1]));
}

// ---------------------------------------------------------------------------
// Projection GEMM (tf32). One launch does all 4 projections; outputs rounded
// to tf32 so the attention kernel feeds MMA without conversion.
// ---------------------------------------------------------------------------
__global__ __launch_bounds__(256, 2) void proj_mma(
    const float* __restrict__ h, const float* __restrict__ mems,
    const float* __restrict__ r,
    const float* __restrict__ wq, const float* __restrict__ wk,
    const float* __restrict__ wv, const float* __restrict__ wr)
{
    const int rowbase = blockIdx.y * 128;
    const int colbase = blockIdx.x * 128;

    const float* W; float* C; int segbase, seg;
    if (rowbase < 2048)        { seg = 0; segbase = 0;     W = wq; C = g_q;  }
    else if (rowbase < 6144)   { seg = 1; segbase = 2048;  W = wk; C = g_k;  }
    else if (rowbase < 10240)  { seg = 2; segbase = 6144;  W = wv; C = g_v;  }
    else                       { seg = 3; segbase = 10240; W = wr; C = g_kr; }
    const int crb = rowbase - segbase;

    const int tid = threadIdx.x;
    const int lane = tid & 31, warp = tid >> 5;
    const int wm = warp & 3, wn = warp >> 2;
    const int grp = lane >> 2, thr = lane & 3;

    __shared__ float As[16][132];
    __shared__ float Bs[16][132];

    const int am = tid & 127;
    const int akq = tid >> 7;
    const int bc4 = (tid & 31) * 4;
    const int bkr = tid >> 5;

    int lrow = crb + am;
    const float* arow;
    if (seg == 0)      arow = h + (size_t)lrow * 1024;
    else if (seg == 3) arow = r + (size_t)lrow * 1024;
    else arow = (lrow < 2048) ? (mems + (size_t)lrow * 1024)
                              : (h + (size_t)(lrow - 2048) * 1024);

    float acc[2][8][4];
#pragma unroll
    for (int mf = 0; mf < 2; mf++)
#pragma unroll
        for (int nf = 0; nf < 8; nf++)
#pragma unroll
            for (int q = 0; q < 4; q++) acc[mf][nf][q] = 0.f;

    float4 ra0 = *(const float4*)(arow + akq * 8);
    float4 ra1 = *(const float4*)(arow + akq * 8 + 4);
    float4 rb0 = *(const float4*)(W + (size_t)bkr * 1024 + colbase + bc4);
    float4 rb1 = *(const float4*)(W + (size_t)(bkr + 8) * 1024 + colbase + bc4);

    for (int k0 = 0; k0 < 1024; k0 += 16) {
        __syncthreads();
        As[akq * 8 + 0][am] = f2tff(ra0.x);
        As[akq * 8 + 1][am] = f2tff(ra0.y);
        As[akq * 8 + 2][am] = f2tff(ra0.z);
        As[akq * 8 + 3][am] = f2tff(ra0.w);
        As[akq * 8 + 4][am] = f2tff(ra1.x);
        As[akq * 8 + 5][am] = f2tff(ra1.y);
        As[akq * 8 + 6][am] = f2tff(ra1.z);
        As[akq * 8 + 7][am] = f2tff(ra1.w);
        float4 cb;
        cb.x = f2tff(rb0.x); cb.y = f2tff(rb0.y); cb.z = f2tff(rb0.z); cb.w = f2tff(rb0.w);
        *(float4*)&Bs[bkr][bc4] = cb;
        cb.x = f2tff(rb1.x); cb.y = f2tff(rb1.y); cb.z = f2tff(rb1.z); cb.w = f2tff(rb1.w);
        *(float4*)&Bs[bkr + 8][bc4] = cb;
        __syncthreads();
        if (k0 + 16 < 1024) {
            ra0 = *(const float4*)(arow + k0 + 16 + akq * 8);
            ra1 = *(const float4*)(arow + k0 + 16 + akq * 8 + 4);
            rb0 = *(const float4*)(W + (size_t)(k0 + 16 + bkr) * 1024 + colbase + bc4);
            rb1 = *(const float4*)(W + (size_t)(k0 + 24 + bkr) * 1024 + colbase + bc4);
        }
#pragma unroll
        for (int ks = 0; ks < 2; ks++) {
            const int kb = ks * 8 + thr;
            unsigned a[2][4], bb[8][2];
#pragma unroll
            for (int mf = 0; mf < 2; mf++) {
                int rr = wm * 32 + mf * 16 + grp;
                a[mf][0] = __float_as_uint(As[kb][rr]);
                a[mf][1] = __float_as_uint(As[kb][rr + 8]);
                a[mf][2] = __float_as_uint(As[kb + 4][rr]);
                a[mf][3] = __float_as_uint(As[kb + 4][rr + 8]);
            }
#pragma unroll
            for (int nf = 0; nf < 8; nf++) {
                int cc = wn * 64 + nf * 8 + grp;
                bb[nf][0] = __float_as_uint(Bs[kb][cc]);
                bb[nf][1] = __float_as_uint(Bs[kb + 4][cc]);
            }
#pragma unroll
            for (int mf = 0; mf < 2; mf++)
#pragma unroll
                for (int nf = 0; nf < 8; nf++)
                    mma_tf32(acc[mf][nf], a[mf], bb[nf]);
        }
    }
#pragma unroll
    for (int mf = 0; mf < 2; mf++)
#pragma unroll
        for (int nf = 0; nf < 8; nf++) {
            int rr = crb + wm * 32 + mf * 16 + grp;
            int cc = colbase + wn * 64 + nf * 8 + thr * 2;
            *(float2*)&C[(size_t)rr * 1024 + cc] =
                make_float2(f2tff(acc[mf][nf][0]), f2tff(acc[mf][nf][1]));
            *(float2*)&C[(size_t)(rr + 8) * 1024 + cc] =
                make_float2(f2tff(acc[mf][nf][2]), f2tff(acc[mf][nf][3]));
        }
}

// ---------------------------------------------------------------------------
// Output GEMM (tf32): g_ao[2048,1024] = g_av @ wo^T.
// ---------------------------------------------------------------------------
__global__ __launch_bounds__(256, 2) void out_mma(const float* __restrict__ wo)
{
    const int rowbase = blockIdx.y * 128;
    const int colbase = blockIdx.x * 128;
    const int tid = threadIdx.x;
    const int lane = tid & 31, warp = tid >> 5;
    const int wm = warp & 3, wn = warp >> 2;
    const int grp = lane >> 2, thr = lane & 3;

    __shared__ float As[16][132];
    __shared__ float Bs[16][132];

    const int am = tid & 127;
    const int akq = tid >> 7;
    const int bn = tid & 127;
    const int bkq = tid >> 7;

    const float* arow = g_av + (size_t)(rowbase + am) * 1024;
    const float* brow = wo + (size_t)(colbase + bn) * 1024;

    float acc[2][8][4];
#pragma unroll
    for (int mf = 0; mf < 2; mf++)
#pragma unroll
        for (int nf = 0; nf < 8; nf++)
#pragma unroll
            for (int q = 0; q < 4; q++) acc[mf][nf][q] = 0.f;

    float4 ra0 = *(const float4*)(arow + akq * 8);
    float4 ra1 = *(const float4*)(arow + akq * 8 + 4);
    float4 rb0 = *(const float4*)(brow + bkq * 8);
    float4 rb1 = *(const float4*)(brow + bkq * 8 + 4);

    for (int k0 = 0; k0 < 1024; k0 += 16) {
        __syncthreads();
        As[akq * 8 + 0][am] = f2tff(ra0.x);
        As[akq * 8 + 1][am] = f2tff(ra0.y);
        As[akq * 8 + 2][am] = f2tff(ra0.z);
        As[akq * 8 + 3][am] = f2tff(ra0.w);
        As[akq * 8 + 4][am] = f2tff(ra1.x);
        As[akq * 8 + 5][am] = f2tff(ra1.y);
        As[akq * 8 + 6][am] = f2tff(ra1.z);
        As[akq * 8 + 7][am] = f2tff(ra1.w);
        Bs[bkq * 8 + 0][bn] = f2tff(rb0.x);
        Bs[bkq * 8 + 1][bn] = f2tff(rb0.y);
        Bs[bkq * 8 + 2][bn] = f2tff(rb0.z);
        Bs[bkq * 8 + 3][bn] = f2tff(rb0.w);
        Bs[bkq * 8 + 4][bn] = f2tff(rb1.x);
        Bs[bkq * 8 + 5][bn] = f2tff(rb1.y);
        Bs[bkq * 8 + 6][bn] = f2tff(rb1.z);
        Bs[bkq * 8 + 7][bn] = f2tff(rb1.w);
        __syncthreads();
        if (k0 + 16 < 1024) {
            ra0 = *(const float4*)(arow + k0 + 16 + akq * 8);
            ra1 = *(const float4*)(arow + k0 + 16 + akq * 8 + 4);
            rb0 = *(const float4*)(brow + k0 + 16 + bkq * 8);
            rb1 = *(const float4*)(brow + k0 + 16 + bkq * 8 + 4);
        }
#pragma unroll
        for (int ks = 0; ks < 2; ks++) {
            const int kb = ks * 8 + thr;
            unsigned a[2][4], bb[8][2];
#pragma unroll
            for (int mf = 0; mf < 2; mf++) {
                int rr = wm * 32 + mf * 16 + grp;
                a[mf][0] = __float_as_uint(As[kb][rr]);
                a[mf][1] = __float_as_uint(As[kb][rr + 8]);
                a[mf][2] = __float_as_uint(As[kb + 4][rr]);
                a[mf][3] = __float_as_uint(As[kb + 4][rr + 8]);
            }
#pragma unroll
            for (int nf = 0; nf < 8; nf++) {
                int cc = wn * 64 + nf * 8 + grp;
                bb[nf][0] = __float_as_uint(Bs[kb][cc]);
                bb[nf][1] = __float_as_uint(Bs[kb + 4][cc]);
            }
#pragma unroll
            for (int mf = 0; mf < 2; mf++)
#pragma unroll
                for (int nf = 0; nf < 8; nf++)
                    mma_tf32(acc[mf][nf], a[mf], bb[nf]);
        }
    }
#pragma unroll
    for (int mf = 0; mf < 2; mf++)
#pragma unroll
        for (int nf = 0; nf < 8; nf++) {
            int rr = rowbase + wm * 32 + mf * 16 + grp;
            int cc = colbase + wn * 64 + nf * 8 + thr * 2;
            *(float2*)&g_ao[(size_t)rr * 1024 + cc] = make_float2(acc[mf][nf][0], acc[mf][nf][1]);
            *(float2*)&g_ao[(size_t)(rr + 8) * 1024 + cc] = make_float2(acc[mf][nf][2], acc[mf][nf][3]);
        }
}

// ---------------------------------------------------------------------------
// ef head projections
// ---------------------------------------------------------------------------
__global__ __launch_bounds__(512) void e_kernel(
    const float* __restrict__ rsb, const float* __restrict__ seg_embed)
{
    const int row = blockIdx.x;                 // i*4+b
    const int i = row >> 2, b = row & 3;
    const int n = threadIdx.x >> 5, lane = threadIdx.x & 31;

    float q1 = g_q[(size_t)row * 1024 + n * 64 + lane]      + rsb[n * 64 + lane];
    float q2 = g_q[(size_t)row * 1024 + n * 64 + lane + 32] + rsb[n * 64 + lane + 32];
    float p0 = q1 * seg_embed[(0 * 16 + n) * 64 + lane] + q2 * seg_embed[(0 * 16 + n) * 64 + lane + 32];
    float p1 = q1 * seg_embed[(1 * 16 + n) * 64 + lane] + q2 * seg_embed[(1 * 16 + n) * 64 + lane + 32];
#pragma unroll
    for (int o = 16; o; o >>= 1) {
        p0 += __shfl_xor_sync(0xffffffffu, p0, o);
        p1 += __shfl_xor_sync(0xffffffffu, p1, o);
    }
    if (lane == 0) {
        g_e[((size_t)(0 * 512 + i) * 4 + b) * 16 + n] = p0;
        g_e[((size_t)(512 + i) * 4 + b) * 16 + n] = p1;
    }
}

// ---------------------------------------------------------------------------
// u = rwb·k ; t = rrb·kr
// ---------------------------------------------------------------------------
__global__ __launch_bounds__(512) void ut_kernel(
    const float* __restrict__ rwb, const float* __restrict__ rrb)
{
    int row = blockIdx.x;
    const float* src; const float* bias; float* dst;
    if (row < 4096) { src = g_k + (size_t)row * 1024;  bias = rwb; dst = g_u + (size_t)row * 16; }
    else { row -= 4096; src = g_kr + (size_t)row * 1024; bias = rrb; dst = g_t + (size_t)row * 16; }
    const int n = threadIdx.x >> 5, lane = threadIdx.x & 31;
    float p = src[n * 64 + lane] * bias[n * 64 + lane]
            + src[n * 64 + lane + 32] * bias[n * 64 + lane + 32];
#pragma unroll
    for (int o = 16; o; o >>= 1) p += __shfl_xor_sync(0xffffffffu, p, o);
    if (lane == 0) dst[n] = p;
}

// ---------------------------------------------------------------------------
// Pack seg-bit + mask-bit into one byte, layout [b][i][j].
// ---------------------------------------------------------------------------
__global__ __launch_bounds__(256) void code_kernel(
    const float* __restrict__ seg_mat, const float* __restrict__ attn_mask)
{
    int idx = blockIdx.x * 256 + threadIdx.x;   // (i*1024 + j)*4 + b
    if (idx < 512 * 1024 * 4) {
        int b = idx & 3;
        int ij = idx >> 2;                      // i*1024 + j
        unsigned char c = (seg_mat[(size_t)idx * 2 + 1] != 0.f) ? 1 : 0;
        if (attn_mask[idx] != 0.f) c |= 2;
        g_code[((size_t)b << 19) + ij] = c;
    }
}

// ---------------------------------------------------------------------------
// Fused attention on tf32 tensor cores (flash style).
// Block: (b,n) x i-tile of 64. 8 warps: wm = warp&3 (16-row band),
// wn = warp>>2 (column half).
// smem floats: ks 64x68, krs 128x68, vs 64x72, Gs 64x136 (Ps aliases Gs),
//              ub 64, tb 128, red 256  = 26816 floats = 107,264 B (2 blk/SM)
// Liveness of the alias: Gs is read only in the logit-assembly phase, which
// is separated from Ps writes by the "maxes ready" __syncthreads; previous-
// iteration Ps reads (P@V) are separated from next Gs writes by the
// top-of-loop __syncthreads.
// ---------------------------------------------------------------------------
#define KST 68
#define VST 72
#define GST 136
#define ATT_SMEM_FLOATS (64*KST + 128*KST + 64*VST + 64*GST + 64 + 128 + 256)

__global__ __launch_bounds__(256, 2) void attn_kernel()
{
    extern __shared__ float sm[];
    float* ks  = sm;                  // 64 x 68
    float* krs = ks  + 64 * KST;      // 128 x 68
    float* vs  = krs + 128 * KST;     // 64 x 72
    float* Gs  = vs  + 64 * VST;      // 64 x 136  (bd band tile)
    float* Ps  = Gs;                  // 64 x 68   (aliases Gs; see liveness note)
    float* ub  = Gs  + 64 * GST;      // 64
    float* tb  = ub  + 64;            // 128
    float* red = tb  + 128;           // [0:128) max halves, [128:256) sum halves

    const int bnix = blockIdx.x;
    const int b = bnix >> 4, n = bnix & 15;
    const int i0 = blockIdx.y * 64;
    const int tid = threadIdx.x;
    const int warp = tid >> 5, lane = tid & 31;
    const int wm = warp & 3, wn = warp >> 2;
    const int grp = lane >> 2, thr = lane & 3;
    const int r0 = wm * 16 + grp;      // local rows r0, r0+8

    // ---- stage q through ks buffer, load A-fragments, keep in regs ----
    unsigned qa[8][4];
    {
        for (int t = tid; t < 64 * 16; t += 256) {
            int row = t >> 4, c4 = (t & 15) * 4;
            *(float4*)&ks[row * KST + c4] =
                *(const float4*)(g_q + ((size_t)(i0 + row) * 4 + b) * 1024 + n * 64 + c4);
        }
        __syncthreads();
#pragma unroll
        for (int kc = 0; kc < 8; kc++) {
            qa[kc][0] = __float_as_uint(ks[r0 * KST + kc * 8 + thr]);
            qa[kc][1] = __float_as_uint(ks[(r0 + 8) * KST + kc * 8 + thr]);
            qa[kc][2] = __float_as_uint(ks[r0 * KST + kc * 8 + thr + 4]);
            qa[kc][3] = __float_as_uint(ks[(r0 + 8) * KST + kc * 8 + thr + 4]);
        }
    }

    float e0[2], e1[2];
    e0[0] = g_e[((size_t)(i0 + r0) * 4 + b) * 16 + n];
    e0[1] = g_e[((size_t)(i0 + r0 + 8) * 4 + b) * 16 + n];
    e1[0] = g_e[((size_t)(512 + i0 + r0) * 4 + b) * 16 + n];
    e1[1] = g_e[((size_t)(512 + i0 + r0 + 8) * 4 + b) * 16 + n];

    float oacc[4][4];
#pragma unroll
    for (int nt = 0; nt < 4; nt++)
#pragma unroll
        for (int q = 0; q < 4; q++) oacc[nt][q] = 0.f;
    float rmax[2] = {-3.0e38f, -3.0e38f};
    float rsum[2] = {0.f, 0.f};

    const unsigned char* codeRow0 = g_code + ((size_t)b << 19) + (size_t)(i0 + r0) * 1024;
    const unsigned char* codeRow1 = codeRow0 + 8 * 1024;

    for (int j0 = 0; j0 < KLEN; j0 += 64) {
        __syncthreads();
        // ---- load tiles ----
        for (int t = tid; t < 64 * 16; t += 256) {
            int row = t >> 4, c4 = (t & 15) * 4;
            size_t goff = ((size_t)(j0 + row) * 4 + b) * 1024 + n * 64 + c4;
            *(float4*)&ks[row * KST + c4] = *(const float4*)(g_k + goff);
            *(float4*)&vs[row * VST + c4] = *(const float4*)(g_v + goff);
        }
        const int base = j0 - i0 + 448;
        for (int t = tid; t < 128 * 16; t += 256) {
            int row = t >> 4, c4 = (t & 15) * 4;
            *(float4*)&krs[row * KST + c4] =
                *(const float4*)(g_kr + ((size_t)(base + row) * 4 + b) * 1024 + n * 64 + c4);
        }
        if (tid < 64) ub[tid] = g_u[((size_t)(j0 + tid) * 4 + b) * 16 + n];
        else if (tid < 192) {
            int m = tid - 64;
            tb[m] = g_t[((size_t)(base + m) * 4 + b) * 16 + n];
        }
        __syncthreads();

        // ---- S = q @ k^T (warp's 32-col half) ----
        float sacc[4][4];
#pragma unroll
        for (int nt = 0; nt < 4; nt++)
#pragma unroll
            for (int q = 0; q < 4; q++) sacc[nt][q] = 0.f;
#pragma unroll
        for (int kc = 0; kc < 8; kc++) {
#pragma unroll
            for (int nt = 0; nt < 4; nt++) {
                unsigned bb[2];
                int jc = wn * 32 + nt * 8 + grp;
                bb[0] = __float_as_uint(ks[jc * KST + kc * 8 + thr]);
                bb[1] = __float_as_uint(ks[jc * KST + kc * 8 + thr + 4]);
                mma_tf32(sacc[nt], qa[kc], bb);
            }
        }

        // ---- G = q @ krs^T (warp's 64-col half of 128), +tb on store ----
#pragma unroll
        for (int gh = 0; gh < 2; gh++) {
            float gacc[4][4];
#pragma unroll
            for (int nt = 0; nt < 4; nt++)
#pragma unroll
                for (int q = 0; q < 4; q++) gacc[nt][q] = 0.f;
#pragma unroll
            for (int kc = 0; kc < 8; kc++) {
#pragma unroll
                for (int nt = 0; nt < 4; nt++) {
                    unsigned bb[2];
                    int mc = wn * 64 + gh * 32 + nt * 8 + grp;
                    bb[0] = __float_as_uint(krs[mc * KST + kc * 8 + thr]);
                    bb[1] = __float_as_uint(krs[mc * KST + kc * 8 + thr + 4]);
                    mma_tf32(gacc[nt], qa[kc], bb);
                }
            }
#pragma unroll
            for (int nt = 0; nt < 4; nt++) {
                int c = wn * 64 + gh * 32 + nt * 8 + 2 * thr;
                float t0 = tb[c], t1 = tb[c + 1];
                *(float2*)&Gs[r0 * GST + c] = make_float2(gacc[nt][0] + t0, gacc[nt][1] + t1);
                *(float2*)&Gs[(r0 + 8) * GST + c] = make_float2(gacc[nt][2] + t0, gacc[nt][3] + t1);
            }
        }
        __syncthreads();   // Gs ready (cross-warp reads)

        // ---- assemble logits in sacc, per-thread row maxes ----
        float mx0 = -3.0e38f, mx1 = -3.0e38f;
#pragma unroll
        for (int nt = 0; nt < 4; nt++) {
            int c = wn * 32 + nt * 8 + 2 * thr;
            unsigned char cc00 = codeRow0[j0 + c], cc01 = codeRow0[j0 + c + 1];
            unsigned char cc10 = codeRow1[j0 + c], cc11 = codeRow1[j0 + c + 1];
            float u0 = ub[c], u1 = ub[c + 1];
            float v;
            v = (sacc[nt][0] + Gs[r0 * GST + c     - r0 + 64] + u0 + ((cc00 & 1) ? e1[0] : e0[0])) * SCALE;
            if (cc00 & 2) v -= 1e30f;
            sacc[nt][0] = v; mx0 = fmaxf(mx0, v);
            v = (sacc[nt][1] + Gs[r0 * GST + c + 1 - r0 + 64] + u1 + ((cc01 & 1) ? e1[0] : e0[0])) * SCALE;
            if (cc01 & 2) v -= 1e30f;
            sacc[nt][1] = v; mx0 = fmaxf(mx0, v);
            v = (sacc[nt][2] + Gs[(r0 + 8) * GST + c     - r0 + 56] + u0 + ((cc10 & 1) ? e1[1] : e0[1])) * SCALE;
            if (cc10 & 2) v -= 1e30f;
            sacc[nt][2] = v; mx1 = fmaxf(mx1, v);
            v = (sacc[nt][3] + Gs[(r0 + 8) * GST + c + 1 - r0 + 56] + u1 + ((cc11 & 1) ? e1[1] : e0[1])) * SCALE;
            if (cc11 & 2) v -= 1e30f;
            sacc[nt][3] = v; mx1 = fmaxf(mx1, v);
        }
#pragma unroll
        for (int o = 1; o < 4; o <<= 1) {
            mx0 = fmaxf(mx0, __shfl_xor_sync(0xffffffffu, mx0, o));
            mx1 = fmaxf(mx1, __shfl_xor_sync(0xffffffffu, mx1, o));
        }
        if (thr == 0) {
            red[wn * 64 + wm * 16 + grp] = mx0;
            red[wn * 64 + wm * 16 + grp + 8] = mx1;
        }
        __syncthreads();   // maxes ready; Gs reads all done -> Ps may overwrite

        float tm0 = fmaxf(red[wm * 16 + grp], red[64 + wm * 16 + grp]);
        float tm1 = fmaxf(red[wm * 16 + grp + 8], red[64 + wm * 16 + grp + 8]);
        float nm0 = fmaxf(rmax[0], tm0);
        float nm1 = fmaxf(rmax[1], tm1);
        float corr0 = __expf(rmax[0] - nm0);
        float corr1 = __expf(rmax[1] - nm1);
        rmax[0] = nm0; rmax[1] = nm1;

        float sum0 = 0.f, sum1 = 0.f;
#pragma unroll
        for (int nt = 0; nt < 4; nt++) {
            int c = wn * 32 + nt * 8 + 2 * thr;
            float p0 = __expf(sacc[nt][0] - nm0);
            float p1 = __expf(sacc[nt][1] - nm0);
            float p2 = __expf(sacc[nt][2] - nm1);
            float p3 = __expf(sacc[nt][3] - nm1);
            sum0 += p0 + p1; sum1 += p2 + p3;
            *(float2*)&Ps[r0 * KST + c] = make_float2(f2tff(p0), f2tff(p1));
            *(float2*)&Ps[(r0 + 8) * KST + c] = make_float2(f2tff(p2), f2tff(p3));
        }
#pragma unroll
        for (int o = 1; o < 4; o <<= 1) {
            sum0 += __shfl_xor_sync(0xffffffffu, sum0, o);
            sum1 += __shfl_xor_sync(0xffffffffu, sum1, o);
        }
        if (thr == 0) {
            red[128 + wn * 64 + wm * 16 + grp] = sum0;
            red[128 + wn * 64 + wm * 16 + grp + 8] = sum1;
        }
        __syncthreads();   // Ps + sums ready

        rsum[0] = rsum[0] * corr0 + red[128 + wm * 16 + grp] + red[192 + wm * 16 + grp];
        rsum[1] = rsum[1] * corr1 + red[128 + wm * 16 + grp + 8] + red[192 + wm * 16 + grp + 8];

        // ---- O = O*corr + P @ V ----
#pragma unroll
        for (int nt = 0; nt < 4; nt++) {
            oacc[nt][0] *= corr0; oacc[nt][1] *= corr0;
            oacc[nt][2] *= corr1; oacc[nt][3] *= corr1;
        }
#pragma unroll
        for (int kc = 0; kc < 8; kc++) {
            unsigned a[4];
            a[0] = __float_as_uint(Ps[r0 * KST + kc * 8 + thr]);
            a[1] = __float_as_uint(Ps[(r0 + 8) * KST + kc * 8 + thr]);
            a[2] = __float_as_uint(Ps[r0 * KST + kc * 8 + thr + 4]);
            a[3] = __float_as_uint(Ps[(r0 + 8) * KST + kc * 8 + thr + 4]);
#pragma unroll
            for (int nt = 0; nt < 4; nt++) {
                unsigned bb[2];
                int dc = wn * 32 + nt * 8 + grp;
                bb[0] = __float_as_uint(vs[(kc * 8 + thr) * VST + dc]);
                bb[1] = __float_as_uint(vs[(kc * 8 + thr + 4) * VST + dc]);
                mma_tf32(oacc[nt], a, bb);
            }
        }
    }

    // ---- write normalized output ----
    float inv0 = 1.f / rsum[0];
    float inv1 = 1.f / rsum[1];
#pragma unroll
    for (int nt = 0; nt < 4; nt++) {
        int d = wn * 32 + nt * 8 + 2 * thr;
        *(float2*)&g_av[((size_t)(i0 + r0) * 4 + b) * 1024 + n * 64 + d] =
            make_float2(oacc[nt][0] * inv0, oacc[nt][1] * inv0);
        *(float2*)&g_av[((size_t)(i0 + r0 + 8) * 4 + b) * 1024 + n * 64 + d] =
            make_float2(oacc[nt][2] * inv1, oacc[nt][3] * inv1);
    }
}

// ---------------------------------------------------------------------------
// Residual + LayerNorm
// ---------------------------------------------------------------------------
__global__ __launch_bounds__(256) void ln_kernel(
    const float* __restrict__ hres, const float* __restrict__ gamma,
    const float* __restrict__ beta, float* __restrict__ out)
{
    __shared__ float xb[1024];
    __shared__ float red[8];
    const int row = blockIdx.x;
    const int tid = threadIdx.x;
    const float* ao = g_ao + (size_t)row * 1024;
    const float* hh = hres + (size_t)row * 1024;

    float s = 0.f;
    for (int c = tid; c < 1024; c += 256) {
        float x = ao[c] + hh[c];
        xb[c] = x;
        s += x;
    }
#pragma unroll
    for (int o = 16; o; o >>= 1) s += __shfl_xor_sync(0xffffffffu, s, o);
    if ((tid & 31) == 0) red[tid >> 5] = s;
    __syncthreads();
    float tot = 0.f;
#pragma unroll
    for (int k = 0; k < 8; k++) tot += red[k];
    const float mean = tot * (1.f / 1024.f);
    __syncthreads();

    float s2 = 0.f;
    for (int c = tid; c < 1024; c += 256) {
        float dx = xb[c] - mean;
        s2 += dx * dx;
    }
#pragma unroll
    for (int o = 16; o; o >>= 1) s2 += __shfl_xor_sync(0xffffffffu, s2, o);
    if ((tid & 31) == 0) red[tid >> 5] = s2;
    __syncthreads();
    float tot2 = 0.f;
#pragma unroll
    for (int k = 0; k < 8; k++) tot2 += red[k];
    const float inv = rsqrtf(tot2 * (1.f / 1024.f) + LN_EPS);

    for (int c = tid; c < 1024; c += 256)
        out[(size_t)row * 1024 + c] = (xb[c] - mean) * inv * gamma[c] + beta[c];
}

// ---------------------------------------------------------------------------
extern "C" void kernel_launch(void* const* d_in, const int* in_sizes, int n_in,
                              void* d_out, int out_size)
{
    const float* rwb       = (const float*)d_in[0];
    const float* rsb       = (const float*)d_in[1];
    const float* rrb       = (const float*)d_in[2];
    const float* seg_embed = (const float*)d_in[3];
    const float* h         = (const float*)d_in[4];
    const float* r         = (const float*)d_in[5];
    const float* mems      = (const float*)d_in[6];
    const float* seg_mat   = (const float*)d_in[7];
    const float* attn_mask = (const float*)d_in[8];
    const float* wq        = (const float*)d_in[9];
    const float* wk        = (const float*)d_in[10];
    const float* wv        = (const float*)d_in[11];
    const float* wr        = (const float*)d_in[12];
    const float* wo        = (const float*)d_in[13];
    const float* gamma     = (const float*)d_in[14];
    const float* beta      = (const float*)d_in[15];

    const int att_smem = ATT_SMEM_FLOATS * (int)sizeof(float); // 107264 B
    cudaFuncSetAttribute(attn_kernel, cudaFuncAttributeMaxDynamicSharedMemorySize, att_smem);

    proj_mma<<<dim3(8, 128), 256>>>(h, mems, r, wq, wk, wv, wr);
    e_kernel<<<2048, 512>>>(rsb, seg_embed);
    ut_kernel<<<10240, 512>>>(rwb, rrb);
    code_kernel<<<8192, 256>>>(seg_mat, attn_mask);
    attn_kernel<<<dim3(64, 8), 256, att_smem>>>();
    out_mma<<<dim3(8, 16), 256>>>(wo);
    ln_kernel<<<2048, 256>>>(h, gamma, beta, (float*)d_out);
}

// round 6
// speedup vs baseline: 3.0664x; 1.2952x over previous
#include <cuda_runtime.h>
#include <cuda_bf16.h>
#include <math.h>

// Problem constants
#define QLEN 512
#define MLEN 512
#define KLEN 1024
#define RLEN 1536
#define BATCH 4
#define DM 1024
#define NH 16
#define DH 64
#define SCALE 0.125f
#define LN_EPS 1e-3f

// Scratch (device globals; no allocation allowed)
__device__ float g_q [2048 * 1024];   // q_head  [i*4+b][n*64+d]
__device__ float g_k [4096 * 1024];   // k_head
__device__ float g_v [4096 * 1024];   // v_head
__device__ float g_kr[6144 * 1024];   // k_r
__device__ float g_e [2 * 512 * 4 * 16];   // ef  [s][i][b][n]
__device__ float g_u [4096 * 16];     // rwb·k   [(j*4+b)*16+n]
__device__ float g_t [6144 * 16];     // rrb·kr  [(m*4+b)*16+n]
__device__ unsigned char g_code[4 * 512 * 1024]; // [b][i][j]: bit0=seg, bit1=mask
__device__ float g_av[2048 * 1024];   // attn_vec
__device__ float g_ao[2048 * 1024];   // attn_out (pre-LN)

// ---------------------------------------------------------------------------
// helpers
// ---------------------------------------------------------------------------
__device__ __forceinline__ unsigned f2tf(float x) {
    unsigned r; asm("cvt.rna.tf32.f32 %0, %1;" : "=r"(r) : "f"(x)); return r;
}
__device__ __forceinline__ float f2tff(float x) { return __uint_as_float(f2tf(x)); }

__device__ __forceinline__ void mma_tf32(float* d, const unsigned* a,
                                         const unsigned* b) {
    asm volatile(
        "mma.sync.aligned.m16n8k8.row.col.f32.tf32.tf32.f32 "
        "{%0,%1,%2,%3}, {%4,%5,%6,%7}, {%8,%9}, {%0,%1,%2,%3};\n"
        : "+f"(d[0]), "+f"(d[1]), "+f"(d[2]), "+f"(d[3])
        : "r"(a[0]), "r"(a[1]), "r"(a[2]), "r"(a[3]),
          "r"(b[0]), "r"(b[1]));
}

__device__ __forceinline__ void cpa16(void* dst, const void* src) {
    unsigned d = (unsigned)__cvta_generic_to_shared(dst);
    asm volatile("cp.async.cg.shared.global [%0], [%1], 16;\n" :: "r"(d), "l"(src));
}
#define CP_COMMIT() asm volatile("cp.async.commit_group;\n")
#define CP_WAIT0()  asm volatile("cp.async.wait_group 0;\n")
#define CP_WAIT1()  asm volatile("cp.async.wait_group 1;\n")

// ---------------------------------------------------------------------------
// Projection GEMM (tf32, cp.async 3-stage). One launch does all 4 projections.
// A stage: [128 m][20 k-pad] ; B stage: [16 k][132 n-pad]
// ---------------------------------------------------------------------------
#define PSTG 3
#define PA_ELT (128 * 20)
#define PB_ELT (16 * 132)
#define PROJ_SMEM ((PSTG * (PA_ELT + PB_ELT)) * 4)   // 56,064 B

__global__ __launch_bounds__(256, 2) void proj_mma(
    const float* __restrict__ h, const float* __restrict__ mems,
    const float* __restrict__ r,
    const float* __restrict__ wq, const float* __restrict__ wk,
    const float* __restrict__ wv, const float* __restrict__ wr)
{
    extern __shared__ float psm[];
    float* Asm = psm;                       // [PSTG][128][20]
    float* Bsm = psm + PSTG * PA_ELT;       // [PSTG][16][132]

    const int rowbase = blockIdx.y * 128;
    const int colbase = blockIdx.x * 128;

    const float* W; float* C; int segbase, seg;
    if (rowbase < 2048)        { seg = 0; segbase = 0;     W = wq; C = g_q;  }
    else if (rowbase < 6144)   { seg = 1; segbase = 2048;  W = wk; C = g_k;  }
    else if (rowbase < 10240)  { seg = 2; segbase = 6144;  W = wv; C = g_v;  }
    else                       { seg = 3; segbase = 10240; W = wr; C = g_kr; }
    const int crb = rowbase - segbase;

    const int tid = threadIdx.x;
    const int lane = tid & 31, warp = tid >> 5;
    const int wm = warp & 3, wn = warp >> 2;
    const int grp = lane >> 2, thr = lane & 3;

    const int arw = tid >> 1;
    const int akc = (tid & 1) * 8;
    const int bkw = tid >> 4;
    const int bnc = (tid & 15) * 8;

    int lrow = crb + arw;
    const float* arow;
    if (seg == 0)      arow = h + (size_t)lrow * 1024;
    else if (seg == 3) arow = r + (size_t)lrow * 1024;
    else arow = (lrow < 2048) ? (mems + (size_t)lrow * 1024)
                              : (h + (size_t)(lrow - 2048) * 1024);
    const float* brow = W + (size_t)bkw * 1024 + colbase + bnc;

    float acc[2][8][4];
#pragma unroll
    for (int mf = 0; mf < 2; mf++)
#pragma unroll
        for (int nf = 0; nf < 8; nf++)
#pragma unroll
            for (int q = 0; q < 4; q++) acc[mf][nf][q] = 0.f;

#define PROJ_ISSUE(it)                                                        \
    {                                                                         \
        int s_ = (it) % PSTG;                                                 \
        int k0_ = (it) * 16;                                                  \
        float* ad = Asm + s_ * PA_ELT + arw * 20 + akc;                       \
        cpa16(ad,     arow + k0_ + akc);                                      \
        cpa16(ad + 4, arow + k0_ + akc + 4);                                  \
        float* bd = Bsm + s_ * PB_ELT + bkw * 132 + bnc;                      \
        cpa16(bd,     brow + (size_t)k0_ * 1024);                             \
        cpa16(bd + 4, brow + (size_t)k0_ * 1024 + 4);                         \
        CP_COMMIT();                                                          \
    }

    PROJ_ISSUE(0);
    PROJ_ISSUE(1);

    for (int it = 0; it < 64; it++) {
        if (it >= 62) { CP_WAIT0(); } else { CP_WAIT1(); }
        __syncthreads();
        if (it + 2 < 64) PROJ_ISSUE(it + 2);
        const float* As = Asm + (it % PSTG) * PA_ELT;
        const float* Bs = Bsm + (it % PSTG) * PB_ELT;
#pragma unroll
        for (int ks = 0; ks < 2; ks++) {
            const int kb = ks * 8 + thr;
            unsigned a[2][4], bb[8][2];
#pragma unroll
            for (int mf = 0; mf < 2; mf++) {
                int rr = wm * 32 + mf * 16 + grp;
                a[mf][0] = __float_as_uint(As[rr * 20 + kb]);
                a[mf][1] = __float_as_uint(As[(rr + 8) * 20 + kb]);
                a[mf][2] = __float_as_uint(As[rr * 20 + kb + 4]);
                a[mf][3] = __float_as_uint(As[(rr + 8) * 20 + kb + 4]);
            }
#pragma unroll
            for (int nf = 0; nf < 8; nf++) {
                int cc = wn * 64 + nf * 8 + grp;
                bb[nf][0] = __float_as_uint(Bs[kb * 132 + cc]);
                bb[nf][1] = __float_as_uint(Bs[(kb + 4) * 132 + cc]);
            }
#pragma unroll
            for (int mf = 0; mf < 2; mf++)
#pragma unroll
                for (int nf = 0; nf < 8; nf++)
                    mma_tf32(acc[mf][nf], a[mf], bb[nf]);
        }
        __syncthreads();
    }
#pragma unroll
    for (int mf = 0; mf < 2; mf++)
#pragma unroll
        for (int nf = 0; nf < 8; nf++) {
            int rr = crb + wm * 32 + mf * 16 + grp;
            int cc = colbase + wn * 64 + nf * 8 + thr * 2;
            *(float2*)&C[(size_t)rr * 1024 + cc] = make_float2(acc[mf][nf][0], acc[mf][nf][1]);
            *(float2*)&C[(size_t)(rr + 8) * 1024 + cc] = make_float2(acc[mf][nf][2], acc[mf][nf][3]);
        }
#undef PROJ_ISSUE
}

// ---------------------------------------------------------------------------
// Output GEMM (tf32, cp.async 3-stage): g_ao = g_av @ wo^T.
// A stage [128 m][20], B stage [128 n][20] (both k-contiguous in gmem).
// ---------------------------------------------------------------------------
#define OUT_SMEM ((PSTG * 2 * PA_ELT) * 4)    // 61,440 B

__global__ __launch_bounds__(256, 2) void out_mma(const float* __restrict__ wo)
{
    extern __shared__ float psm[];
    float* Asm = psm;                       // [PSTG][128][20]
    float* Bsm = psm + PSTG * PA_ELT;       // [PSTG][128][20]

    const int rowbase = blockIdx.y * 128;
    const int colbase = blockIdx.x * 128;
    const int tid = threadIdx.x;
    const int lane = tid & 31, warp = tid >> 5;
    const int wm = warp & 3, wn = warp >> 2;
    const int grp = lane >> 2, thr = lane & 3;

    const int arw = tid >> 1;
    const int akc = (tid & 1) * 8;

    const float* arow = g_av + (size_t)(rowbase + arw) * 1024;
    const float* brow = wo + (size_t)(colbase + arw) * 1024;

    float acc[2][8][4];
#pragma unroll
    for (int mf = 0; mf < 2; mf++)
#pragma unroll
        for (int nf = 0; nf < 8; nf++)
#pragma unroll
            for (int q = 0; q < 4; q++) acc[mf][nf][q] = 0.f;

#define OUT_ISSUE(it)                                                         \
    {                                                                         \
        int s_ = (it) % PSTG;                                                 \
        int k0_ = (it) * 16;                                                  \
        float* ad = Asm + s_ * PA_ELT + arw * 20 + akc;                       \
        cpa16(ad,     arow + k0_ + akc);                                      \
        cpa16(ad + 4, arow + k0_ + akc + 4);                                  \
        float* bd = Bsm + s_ * PA_ELT + arw * 20 + akc;                       \
        cpa16(bd,     brow + k0_ + akc);                                      \
        cpa16(bd + 4, brow + k0_ + akc + 4);                                  \
        CP_COMMIT();                                                          \
    }

    OUT_ISSUE(0);
    OUT_ISSUE(1);

    for (int it = 0; it < 64; it++) {
        if (it >= 62) { CP_WAIT0(); } else { CP_WAIT1(); }
        __syncthreads();
        if (it + 2 < 64) OUT_ISSUE(it + 2);
        const float* As = Asm + (it % PSTG) * PA_ELT;
        const float* Bs = Bsm + (it % PSTG) * PA_ELT;
#pragma unroll
        for (int ks = 0; ks < 2; ks++) {
            const int kb = ks * 8 + thr;
            unsigned a[2][4], bb[8][2];
#pragma unroll
            for (int mf = 0; mf < 2; mf++) {
                int rr = wm * 32 + mf * 16 + grp;
                a[mf][0] = __float_as_uint(As[rr * 20 + kb]);
                a[mf][1] = __float_as_uint(As[(rr + 8) * 20 + kb]);
                a[mf][2] = __float_as_uint(As[rr * 20 + kb + 4]);
                a[mf][3] = __float_as_uint(As[(rr + 8) * 20 + kb + 4]);
            }
#pragma unroll
            for (int nf = 0; nf < 8; nf++) {
                int cc = wn * 64 + nf * 8 + grp;
                bb[nf][0] = __float_as_uint(Bs[cc * 20 + kb]);
                bb[nf][1] = __float_as_uint(Bs[cc * 20 + kb + 4]);
            }
#pragma unroll
            for (int mf = 0; mf < 2; mf++)
#pragma unroll
                for (int nf = 0; nf < 8; nf++)
                    mma_tf32(acc[mf][nf], a[mf], bb[nf]);
        }
        __syncthreads();
    }
#pragma unroll
    for (int mf = 0; mf < 2; mf++)
#pragma unroll
        for (int nf = 0; nf < 8; nf++) {
            int rr = rowbase + wm * 32 + mf * 16 + grp;
            int cc = colbase + wn * 64 + nf * 8 + thr * 2;
            *(float2*)&g_ao[(size_t)rr * 1024 + cc] = make_float2(acc[mf][nf][0], acc[mf][nf][1]);
            *(float2*)&g_ao[(size_t)(rr + 8) * 1024 + cc] = make_float2(acc[mf][nf][2], acc[mf][nf][3]);
        }
#undef OUT_ISSUE
}

// ---------------------------------------------------------------------------
// ef head projections
// ---------------------------------------------------------------------------
__global__ __launch_bounds__(512) void e_kernel(
    const float* __restrict__ rsb, const float* __restrict__ seg_embed)
{
    const int row = blockIdx.x;                 // i*4+b
    const int i = row >> 2, b = row & 3;
    const int n = threadIdx.x >> 5, lane = threadIdx.x & 31;

    float q1 = g_q[(size_t)row * 1024 + n * 64 + lane]      + rsb[n * 64 + lane];
    float q2 = g_q[(size_t)row * 1024 + n * 64 + lane + 32] + rsb[n * 64 + lane + 32];
    float p0 = q1 * seg_embed[(0 * 16 + n) * 64 + lane] + q2 * seg_embed[(0 * 16 + n) * 64 + lane + 32];
    float p1 = q1 * seg_embed[(1 * 16 + n) * 64 + lane] + q2 * seg_embed[(1 * 16 + n) * 64 + lane + 32];
#pragma unroll
    for (int o = 16; o; o >>= 1) {
        p0 += __shfl_xor_sync(0xffffffffu, p0, o);
        p1 += __shfl_xor_sync(0xffffffffu, p1, o);
    }
    if (lane == 0) {
        g_e[((size_t)(0 * 512 + i) * 4 + b) * 16 + n] = p0;
        g_e[((size_t)(512 + i) * 4 + b) * 16 + n] = p1;
    }
}

// ---------------------------------------------------------------------------
// u = rwb·k ; t = rrb·kr
// ---------------------------------------------------------------------------
__global__ __launch_bounds__(512) void ut_kernel(
    const float* __restrict__ rwb, const float* __restrict__ rrb)
{
    int row = blockIdx.x;
    const float* src; const float* bias; float* dst;
    if (row < 4096) { src = g_k + (size_t)row * 1024;  bias = rwb; dst = g_u + (size_t)row * 16; }
    else { row -= 4096; src = g_kr + (size_t)row * 1024; bias = rrb; dst = g_t + (size_t)row * 16; }
    const int n = threadIdx.x >> 5, lane = threadIdx.x & 31;
    float p = src[n * 64 + lane] * bias[n * 64 + lane]
            + src[n * 64 + lane + 32] * bias[n * 64 + lane + 32];
#pragma unroll
    for (int o = 16; o; o >>= 1) p += __shfl_xor_sync(0xffffffffu, p, o);
    if (lane == 0) dst[n] = p;
}

// ---------------------------------------------------------------------------
// Pack seg-bit + mask-bit into one byte, layout [b][i][j].
// ---------------------------------------------------------------------------
__global__ __launch_bounds__(256) void code_kernel(
    const float* __restrict__ seg_mat, const float* __restrict__ attn_mask)
{
    int idx = blockIdx.x * 256 + threadIdx.x;   // (i*1024 + j)*4 + b
    if (idx < 512 * 1024 * 4) {
        int b = idx & 3;
        int ij = idx >> 2;
        unsigned char c = (seg_mat[(size_t)idx * 2 + 1] != 0.f) ? 1 : 0;
        if (attn_mask[idx] != 0.f) c |= 2;
        g_code[((size_t)b << 19) + ij] = c;
    }
}

// ---------------------------------------------------------------------------
// Fused attention on tf32 tensor cores (flash style) + krs ring buffer.
// base = j0-i0+448 is 64-aligned; the 128-row kr window = two aligned 64-row
// panels shifting by one panel per j-iter. 2-slot parity ring: slab row of
// global panel P, local row m  ->  ((P + (m>>6))&1)*64 + (m&63).
// In the band GEMM mc>>6 == wn, so slab base is a per-warp constant.
// smem: ks 64x68, krs 128x68(ring), vs 64x72, Gs 64x136 (Ps aliases Gs),
//       ub 64, tb2 128(ring), red 256  = 107,264 B -> 2 blocks/SM.
// ---------------------------------------------------------------------------
#define KST 68
#define VST 72
#define GST 136
#define ATT_SMEM_FLOATS (64*KST + 128*KST + 64*VST + 64*GST + 64 + 128 + 256)

__global__ __launch_bounds__(256, 2) void attn_kernel()
{
    extern __shared__ float sm[];
    float* ks  = sm;                  // 64 x 68
    float* krs = ks  + 64 * KST;      // 128 x 68 (2-panel ring)
    float* vs  = krs + 128 * KST;     // 64 x 72
    float* Gs  = vs  + 64 * VST;      // 64 x 136 (bd band tile)
    float* Ps  = Gs;                  // 64 x 68  (aliases Gs; liveness-safe)
    float* ub  = Gs  + 64 * GST;      // 64
    float* tb2 = ub  + 64;            // 128 (2-panel ring)
    float* red = tb2 + 128;           // [0:128) maxes, [128:256) sums

    const int bnix = blockIdx.x;
    const int b = bnix >> 4, n = bnix & 15;
    const int i0 = blockIdx.y * 64;
    const int tid = threadIdx.x;
    const int warp = tid >> 5, lane = tid & 31;
    const int wm = warp & 3, wn = warp >> 2;
    const int grp = lane >> 2, thr = lane & 3;
    const int r0 = wm * 16 + grp;      // local rows r0, r0+8

    // ---- stage q through ks buffer, load A-fragments, keep in regs ----
    unsigned qa[8][4];
    {
        for (int t = tid; t < 64 * 16; t += 256) {
            int row = t >> 4, c4 = (t & 15) * 4;
            *(float4*)&ks[row * KST + c4] =
                *(const float4*)(g_q + ((size_t)(i0 + row) * 4 + b) * 1024 + n * 64 + c4);
        }
        __syncthreads();
#pragma unroll
        for (int kc = 0; kc < 8; kc++) {
            qa[kc][0] = __float_as_uint(ks[r0 * KST + kc * 8 + thr]);
            qa[kc][1] = __float_as_uint(ks[(r0 + 8) * KST + kc * 8 + thr]);
            qa[kc][2] = __float_as_uint(ks[r0 * KST + kc * 8 + thr + 4]);
            qa[kc][3] = __float_as_uint(ks[(r0 + 8) * KST + kc * 8 + thr + 4]);
        }
    }

    float e0[2], e1[2];
    e0[0] = g_e[((size_t)(i0 + r0) * 4 + b) * 16 + n];
    e0[1] = g_e[((size_t)(i0 + r0 + 8) * 4 + b) * 16 + n];
    e1[0] = g_e[((size_t)(512 + i0 + r0) * 4 + b) * 16 + n];
    e1[1] = g_e[((size_t)(512 + i0 + r0 + 8) * 4 + b) * 16 + n];

    float oacc[4][4];
#pragma unroll
    for (int nt = 0; nt < 4; nt++)
#pragma unroll
        for (int q = 0; q < 4; q++) oacc[nt][q] = 0.f;
    float rmax[2] = {-3.0e38f, -3.0e38f};
    float rsum[2] = {0.f, 0.f};

    const unsigned char* codeRow0 = g_code + ((size_t)b << 19) + (size_t)(i0 + r0) * 1024;
    const unsigned char* codeRow1 = codeRow0 + 8 * 1024;

    int P = 7 - (i0 >> 6);   // panel index of window start; +1 per j-iter

    for (int j0 = 0; j0 < KLEN; j0 += 64, P++) {
        __syncthreads();
        const int base = j0 - i0 + 448;
        const int Pp = P & 1;
        // ---- async tile loads ----
        for (int t = tid; t < 64 * 16; t += 256) {
            int row = t >> 4, c4 = (t & 15) * 4;
            size_t goff = ((size_t)(j0 + row) * 4 + b) * 1024 + n * 64 + c4;
            cpa16(&ks[row * KST + c4], g_k + goff);
            cpa16(&vs[row * VST + c4], g_v + goff);
        }
        const int startrow = (j0 == 0) ? 0 : 64;
        for (int t = tid; t < (128 - startrow) * 16; t += 256) {
            int row = startrow + (t >> 4), c4 = (t & 15) * 4;
            int slab = ((Pp + (row >> 6)) & 1) * 64 + (row & 63);
            cpa16(&krs[slab * KST + c4],
                  g_kr + ((size_t)(base + row) * 4 + b) * 1024 + n * 64 + c4);
        }
        CP_COMMIT();
        // ---- scalar ub/tb loads ----
        if (tid < 64) {
            ub[tid] = g_u[((size_t)(j0 + tid) * 4 + b) * 16 + n];
        } else if (tid < 192) {
            int m = tid - 64 + startrow;
            if (m < 128) {
                int slab = ((Pp + (m >> 6)) & 1) * 64 + (m & 63);
                tb2[slab] = g_t[((size_t)(base + m) * 4 + b) * 16 + n];
            }
        }
        CP_WAIT0();
        __syncthreads();

        // ---- S = q @ k^T (warp's 32-col half) ----
        float sacc[4][4];
#pragma unroll
        for (int nt = 0; nt < 4; nt++)
#pragma unroll
            for (int q = 0; q < 4; q++) sacc[nt][q] = 0.f;
#pragma unroll
        for (int kc = 0; kc < 8; kc++) {
#pragma unroll
            for (int nt = 0; nt < 4; nt++) {
                unsigned bb[2];
                int jc = wn * 32 + nt * 8 + grp;
                bb[0] = __float_as_uint(ks[jc * KST + kc * 8 + thr]);
                bb[1] = __float_as_uint(ks[jc * KST + kc * 8 + thr + 4]);
                mma_tf32(sacc[nt], qa[kc], bb);
            }
        }

        // ---- G = q @ krs^T (warp's 64-col half of 128), +tb on store ----
        const int slabbase = ((Pp + wn) & 1) * 64;   // mc>>6 == wn
#pragma unroll
        for (int gh = 0; gh < 2; gh++) {
            float gacc[4][4];
#pragma unroll
            for (int nt = 0; nt < 4; nt++)
#pragma unroll
                for (int q = 0; q < 4; q++) gacc[nt][q] = 0.f;
#pragma unroll
            for (int kc = 0; kc < 8; kc++) {
#pragma unroll
                for (int nt = 0; nt < 4; nt++) {
                    unsigned bb[2];
                    int mrow = slabbase + gh * 32 + nt * 8 + grp;
                    bb[0] = __float_as_uint(krs[mrow * KST + kc * 8 + thr]);
                    bb[1] = __float_as_uint(krs[mrow * KST + kc * 8 + thr + 4]);
                    mma_tf32(gacc[nt], qa[kc], bb);
                }
            }
#pragma unroll
            for (int nt = 0; nt < 4; nt++) {
                int c63 = gh * 32 + nt * 8 + 2 * thr;     // mc & 63
                int c = wn * 64 + c63;                    // ordered local m
                float t0 = tb2[slabbase + c63], t1 = tb2[slabbase + c63 + 1];
                *(float2*)&Gs[r0 * GST + c] = make_float2(gacc[nt][0] + t0, gacc[nt][1] + t1);
                *(float2*)&Gs[(r0 + 8) * GST + c] = make_float2(gacc[nt][2] + t0, gacc[nt][3] + t1);
            }
        }
        __syncthreads();   // Gs ready (cross-warp reads)

        // ---- assemble logits, per-thread row maxes ----
        float mx0 = -3.0e38f, mx1 = -3.0e38f;
#pragma unroll
        for (int nt = 0; nt < 4; nt++) {
            int c = wn * 32 + nt * 8 + 2 * thr;
            unsigned char cc00 = codeRow0[j0 + c], cc01 = codeRow0[j0 + c + 1];
            unsigned char cc10 = codeRow1[j0 + c], cc11 = codeRow1[j0 + c + 1];
            float u0 = ub[c], u1 = ub[c + 1];
            float v;
            v = (sacc[nt][0] + Gs[r0 * GST + c     - r0 + 64] + u0 + ((cc00 & 1) ? e1[0] : e0[0])) * SCALE;
            if (cc00 & 2) v -= 1e30f;
            sacc[nt][0] = v; mx0 = fmaxf(mx0, v);
            v = (sacc[nt][1] + Gs[r0 * GST + c + 1 - r0 + 64] + u1 + ((cc01 & 1) ? e1[0] : e0[0])) * SCALE;
            if (cc01 & 2) v -= 1e30f;
            sacc[nt][1] = v; mx0 = fmaxf(mx0, v);
            v = (sacc[nt][2] + Gs[(r0 + 8) * GST + c     - r0 + 56] + u0 + ((cc10 & 1) ? e1[1] : e0[1])) * SCALE;
            if (cc10 & 2) v -= 1e30f;
            sacc[nt][2] = v; mx1 = fmaxf(mx1, v);
            v = (sacc[nt][3] + Gs[(r0 + 8) * GST + c + 1 - r0 + 56] + u1 + ((cc11 & 1) ? e1[1] : e0[1])) * SCALE;
            if (cc11 & 2) v -= 1e30f;
            sacc[nt][3] = v; mx1 = fmaxf(mx1, v);
        }
#pragma unroll
        for (int o = 1; o < 4; o <<= 1) {
            mx0 = fmaxf(mx0, __shfl_xor_sync(0xffffffffu, mx0, o));
            mx1 = fmaxf(mx1, __shfl_xor_sync(0xffffffffu, mx1, o));
        }
        if (thr == 0) {
            red[wn * 64 + wm * 16 + grp] = mx0;
            red[wn * 64 + wm * 16 + grp + 8] = mx1;
        }
        __syncthreads();   // maxes ready; Gs reads done -> Ps may overwrite

        float tm0 = fmaxf(red[wm * 16 + grp], red[64 + wm * 16 + grp]);
        float tm1 = fmaxf(red[wm * 16 + grp + 8], red[64 + wm * 16 + grp + 8]);
        float nm0 = fmaxf(rmax[0], tm0);
        float nm1 = fmaxf(rmax[1], tm1);
        float corr0 = __expf(rmax[0] - nm0);
        float corr1 = __expf(rmax[1] - nm1);
        rmax[0] = nm0; rmax[1] = nm1;

        float sum0 = 0.f, sum1 = 0.f;
#pragma unroll
        for (int nt = 0; nt < 4; nt++) {
            int c = wn * 32 + nt * 8 + 2 * thr;
            float p0 = __expf(sacc[nt][0] - nm0);
            float p1 = __expf(sacc[nt][1] - nm0);
            float p2 = __expf(sacc[nt][2] - nm1);
            float p3 = __expf(sacc[nt][3] - nm1);
            sum0 += p0 + p1; sum1 += p2 + p3;
            *(float2*)&Ps[r0 * KST + c] = make_float2(p0, p1);
            *(float2*)&Ps[(r0 + 8) * KST + c] = make_float2(p2, p3);
        }
#pragma unroll
        for (int o = 1; o < 4; o <<= 1) {
            sum0 += __shfl_xor_sync(0xffffffffu, sum0, o);
            sum1 += __shfl_xor_sync(0xffffffffu, sum1, o);
        }
        if (thr == 0) {
            red[128 + wn * 64 + wm * 16 + grp] = sum0;
            red[128 + wn * 64 + wm * 16 + grp + 8] = sum1;
        }
        __syncthreads();   // Ps + sums ready

        rsum[0] = rsum[0] * corr0 + red[128 + wm * 16 + grp] + red[192 + wm * 16 + grp];
        rsum[1] = rsum[1] * corr1 + red[128 + wm * 16 + grp + 8] + red[192 + wm * 16 + grp + 8];

        // ---- O = O*corr + P @ V ----
#pragma unroll
        for (int nt = 0; nt < 4; nt++) {
            oacc[nt][0] *= corr0; oacc[nt][1] *= corr0;
            oacc[nt][2] *= corr1; oacc[nt][3] *= corr1;
        }
#pragma unroll
        for (int kc = 0; kc < 8; kc++) {
            unsigned a[4];
            a[0] = __float_as_uint(Ps[r0 * KST + kc * 8 + thr]);
            a[1] = __float_as_uint(Ps[(r0 + 8) * KST + kc * 8 + thr]);
            a[2] = __float_as_uint(Ps[r0 * KST + kc * 8 + thr + 4]);
            a[3] = __float_as_uint(Ps[(r0 + 8) * KST + kc * 8 + thr + 4]);
#pragma unroll
            for (int nt = 0; nt < 4; nt++) {
                unsigned bb[2];
                int dc = wn * 32 + nt * 8 + grp;
                bb[0] = __float_as_uint(vs[(kc * 8 + thr) * VST + dc]);
                bb[1] = __float_as_uint(vs[(kc * 8 + thr + 4) * VST + dc]);
                mma_tf32(oacc[nt], a, bb);
            }
        }
    }

    // ---- write normalized output ----
    float inv0 = 1.f / rsum[0];
    float inv1 = 1.f / rsum[1];
#pragma unroll
    for (int nt = 0; nt < 4; nt++) {
        int d = wn * 32 + nt * 8 + 2 * thr;
        *(float2*)&g_av[((size_t)(i0 + r0) * 4 + b) * 1024 + n * 64 + d] =
            make_float2(oacc[nt][0] * inv0, oacc[nt][1] * inv0);
        *(float2*)&g_av[((size_t)(i0 + r0 + 8) * 4 + b) * 1024 + n * 64 + d] =
            make_float2(oacc[nt][2] * inv1, oacc[nt][3] * inv1);
    }
}

// ---------------------------------------------------------------------------
// Residual + LayerNorm
// ---------------------------------------------------------------------------
__global__ __launch_bounds__(256) void ln_kernel(
    const float* __restrict__ hres, const float* __restrict__ gamma,
    const float* __restrict__ beta, float* __restrict__ out)
{
    __shared__ float xb[1024];
    __shared__ float red[8];
    const int row = blockIdx.x;
    const int tid = threadIdx.x;
    const float* ao = g_ao + (size_t)row * 1024;
    const float* hh = hres + (size_t)row * 1024;

    float s = 0.f;
    for (int c = tid; c < 1024; c += 256) {
        float x = ao[c] + hh[c];
        xb[c] = x;
        s += x;
    }
#pragma unroll
    for (int o = 16; o; o >>= 1) s += __shfl_xor_sync(0xffffffffu, s, o);
    if ((tid & 31) == 0) red[tid >> 5] = s;
    __syncthreads();
    float tot = 0.f;
#pragma unroll
    for (int k = 0; k < 8; k++) tot += red[k];
    const float mean = tot * (1.f / 1024.f);
    __syncthreads();

    float s2 = 0.f;
    for (int c = tid; c < 1024; c += 256) {
        float dx = xb[c] - mean;
        s2 += dx * dx;
    }
#pragma unroll
    for (int o = 16; o; o >>= 1) s2 += __shfl_xor_sync(0xffffffffu, s2, o);
    if ((tid & 31) == 0) red[tid >> 5] = s2;
    __syncthreads();
    float tot2 = 0.f;
#pragma unroll
    for (int k = 0; k < 8; k++) tot2 += red[k];
    const float inv = rsqrtf(tot2 * (1.f / 1024.f) + LN_EPS);

    for (int c = tid; c < 1024; c += 256)
        out[(size_t)row * 1024 + c] = (xb[c] - mean) * inv * gamma[c] + beta[c];
}

// ---------------------------------------------------------------------------
extern "C" void kernel_launch(void* const* d_in, const int* in_sizes, int n_in,
                              void* d_out, int out_size)
{
    const float* rwb       = (const float*)d_in[0];
    const float* rsb       = (const float*)d_in[1];
    const float* rrb       = (const float*)d_in[2];
    const float* seg_embed = (const float*)d_in[3];
    const float* h         = (const float*)d_in[4];
    const float* r         = (const float*)d_in[5];
    const float* mems      = (const float*)d_in[6];
    const float* seg_mat   = (const float*)d_in[7];
    const float* attn_mask = (const float*)d_in[8];
    const float* wq        = (const float*)d_in[9];
    const float* wk        = (const float*)d_in[10];
    const float* wv        = (const float*)d_in[11];
    const float* wr        = (const float*)d_in[12];
    const float* wo        = (const float*)d_in[13];
    const float* gamma     = (const float*)d_in[14];
    const float* beta      = (const float*)d_in[15];

    const int att_smem = ATT_SMEM_FLOATS * (int)sizeof(float); // 107,264 B
    cudaFuncSetAttribute(attn_kernel, cudaFuncAttributeMaxDynamicSharedMemorySize, att_smem);
    cudaFuncSetAttribute(proj_mma, cudaFuncAttributeMaxDynamicSharedMemorySize, PROJ_SMEM);
    cudaFuncSetAttribute(out_mma, cudaFuncAttributeMaxDynamicSharedMemorySize, OUT_SMEM);

    proj_mma<<<dim3(8, 128), 256, PROJ_SMEM>>>(h, mems, r, wq, wk, wv, wr);
    e_kernel<<<2048, 512>>>(rsb, seg_embed);
    ut_kernel<<<10240, 512>>>(rwb, rrb);
    code_kernel<<<8192, 256>>>(seg_mat, attn_mask);
    attn_kernel<<<dim3(64, 8), 256, att_smem>>>();
    out_mma<<<dim3(8, 16), 256, OUT_SMEM>>>(wo);
    ln_kernel<<<2048, 256>>>(h, gamma, beta, (float*)d_out);
}

// round 7
// speedup vs baseline: 4.4862x; 1.4630x over previous
#include <cuda_runtime.h>
#include <cuda_bf16.h>
#include <math.h>

// Problem constants
#define QLEN 512
#define MLEN 512
#define KLEN 1024
#define RLEN 1536
#define BATCH 4
#define DM 1024
#define NH 16
#define DH 64
#define SCALE 0.125f
#define LN_EPS 1e-3f

// Scratch (device globals; no allocation allowed).  All "_u" arrays hold
// packed bf16 pairs (low 16 bits = even index).
__device__ unsigned g_ab_u [10240 * 512];  // [mems(2048); h(2048); r(6144)] rows x 1024 bf16
__device__ unsigned g_wpk_u[4 * 512 * 1024]; // proj weights, [w][k2][n] bf16-pairs along k
__device__ unsigned g_wob_u[1024 * 512];   // wo bf16 [h][1024]
__device__ unsigned g_qb_u [2048 * 512];   // q_head  bf16 [i*4+b][n*64+d]
__device__ unsigned g_kb_u [4096 * 512];   // k_head  bf16
__device__ unsigned g_vb_u [4096 * 512];   // v_head  bf16
__device__ unsigned g_krb_u[6144 * 512];   // k_r     bf16
__device__ unsigned g_avb_u[2048 * 512];   // attn_vec bf16
__device__ float g_e [2 * 512 * 4 * 16];   // ef  [s][i][b][n]
__device__ float g_u [4096 * 16];          // rwb·k
__device__ float g_t [6144 * 16];          // rrb·kr
__device__ unsigned char g_code[4 * 512 * 1024]; // [b][i][j]: bit0=seg, bit1=mask
__device__ float g_ao[2048 * 1024];        // attn_out (pre-LN, fp32)

// ---------------------------------------------------------------------------
// helpers
// ---------------------------------------------------------------------------
__device__ __forceinline__ unsigned pk2(float lo, float hi) {
    unsigned r;
    asm("cvt.rn.bf16x2.f32 %0, %1, %2;" : "=r"(r) : "f"(hi), "f"(lo));
    return r;
}

__device__ __forceinline__ void mma_bf16(float* d, const unsigned* a,
                                         unsigned b0, unsigned b1) {
    asm volatile(
        "mma.sync.aligned.m16n8k16.row.col.f32.bf16.bf16.f32 "
        "{%0,%1,%2,%3}, {%4,%5,%6,%7}, {%8,%9}, {%0,%1,%2,%3};\n"
        : "+f"(d[0]), "+f"(d[1]), "+f"(d[2]), "+f"(d[3])
        : "r"(a[0]), "r"(a[1]), "r"(a[2]), "r"(a[3]), "r"(b0), "r"(b1));
}

__device__ __forceinline__ void cpa16(void* dst, const void* src) {
    unsigned d = (unsigned)__cvta_generic_to_shared(dst);
    asm volatile("cp.async.cg.shared.global [%0], [%1], 16;\n" :: "r"(d), "l"(src));
}
#define CP_COMMIT() asm volatile("cp.async.commit_group;\n")
#define CP_WAIT0()  asm volatile("cp.async.wait_group 0;\n")
#define CP_WAIT1()  asm volatile("cp.async.wait_group 1;\n")

__device__ __forceinline__ void ldsm_x2_t(unsigned& r0, unsigned& r1, const void* p) {
    unsigned a = (unsigned)__cvta_generic_to_shared(p);
    asm volatile("ldmatrix.sync.aligned.m8n8.x2.trans.shared.b16 {%0,%1}, [%2];"
                 : "=r"(r0), "=r"(r1) : "r"(a));
}

// ---------------------------------------------------------------------------
// Conversion kernels (fp32 -> bf16)
// ---------------------------------------------------------------------------
// rows 0..10239 -> g_ab_u ([mems; h; r]); rows 10240..11263 -> g_wob_u (wo)
__global__ __launch_bounds__(256) void conv_cast(
    const float* __restrict__ mems, const float* __restrict__ h,
    const float* __restrict__ r, const float* __restrict__ wo)
{
    int idx = blockIdx.x * 256 + threadIdx.x;   // < 11264*512
    int row = idx >> 9, p = idx & 511;
    const float* src;
    unsigned* dst;
    if (row < 2048)      { src = mems + (size_t)row * 1024;          dst = g_ab_u + (size_t)row * 512; }
    else if (row < 4096) { src = h + (size_t)(row - 2048) * 1024;    dst = g_ab_u + (size_t)row * 512; }
    else if (row < 10240){ src = r + (size_t)(row - 4096) * 1024;    dst = g_ab_u + (size_t)row * 512; }
    else                 { src = wo + (size_t)(row - 10240) * 1024;  dst = g_wob_u + (size_t)(row - 10240) * 512; }
    float2 v = *(const float2*)(src + p * 2);
    dst[p] = pk2(v.x, v.y);
}

// proj weights: pack pairs along k (row dim): wpk[w][k2][n]
__global__ __launch_bounds__(256) void conv_pack(
    const float* __restrict__ wq, const float* __restrict__ wk,
    const float* __restrict__ wv, const float* __restrict__ wr)
{
    int idx = blockIdx.x * 256 + threadIdx.x;   // < 4*512*1024
    int w = idx >> 19;
    int rem = idx & ((1 << 19) - 1);
    int k2 = rem >> 10, nn = rem & 1023;
    const float* W = (w == 0) ? wq : (w == 1) ? wk : (w == 2) ? wv : wr;
    float a = W[(size_t)(2 * k2) * 1024 + nn];
    float bq = W[(size_t)(2 * k2 + 1) * 1024 + nn];
    g_wpk_u[(size_t)w * 524288 + rem] = pk2(a, bq);
}

// ---------------------------------------------------------------------------
// Projection GEMM (bf16 m16n8k16, cp.async 3-stage, k32/iter).
// A stage: [2 sub][128 m][12 b32] (8 data + 4 pad; conflict-free frag loads)
// B stage: [2 sub][8 k2][132 n]
// ---------------------------------------------------------------------------
#define PSTG 3
#define PJA 3072
#define PJB 2112
#define PROJ_SMEM ((PSTG * (PJA + PJB)) * 4)   // 62,208 B

__global__ __launch_bounds__(256, 2) void proj_mma()
{
    extern __shared__ unsigned psm[];
    unsigned* Asm = psm;
    unsigned* Bsm = psm + PSTG * PJA;

    const int rowbase = blockIdx.y * 128;
    const int colbase = blockIdx.x * 128;

    int abase, wsel, segbase;
    unsigned* Cu;
    if (rowbase < 2048)        { wsel = 0; segbase = 0;     abase = 2048; Cu = g_qb_u;  }
    else if (rowbase < 6144)   { wsel = 1; segbase = 2048;  abase = 0;    Cu = g_kb_u;  }
    else if (rowbase < 10240)  { wsel = 2; segbase = 6144;  abase = 0;    Cu = g_vb_u;  }
    else                       { wsel = 3; segbase = 10240; abase = 4096; Cu = g_krb_u; }
    const int crb = rowbase - segbase;

    const int tid = threadIdx.x;
    const int lane = tid & 31, warp = tid >> 5;
    const int wm = warp & 3, wn = warp >> 2;
    const int grp = lane >> 2, thr = lane & 3;

    const int arw = tid >> 1;      // A row (0..127)
    const int asub = tid & 1;      // k16 sub-block
    const unsigned* asrc = g_ab_u + (size_t)(abase + crb + arw) * 512 + asub * 8;
    const unsigned* wsrc = g_wpk_u + (size_t)wsel * 524288 + colbase;

    float acc[2][8][4];
#pragma unroll
    for (int mf = 0; mf < 2; mf++)
#pragma unroll
        for (int nf = 0; nf < 8; nf++)
#pragma unroll
            for (int q = 0; q < 4; q++) acc[mf][nf][q] = 0.f;

#define PROJ_ISSUE(it)                                                          \
    {                                                                           \
        int s_ = (it) % PSTG;                                                   \
        int k2base_ = (it) * 16;  /* k0/2 */                                    \
        unsigned* ad = Asm + s_ * PJA + asub * 1536 + arw * 12;                 \
        cpa16(ad,     asrc + k2base_);                                          \
        cpa16(ad + 4, asrc + k2base_ + 4);                                      \
        for (int t_ = tid; t_ < 512; t_ += 256) {                               \
            int brow_ = t_ >> 5;          /* 0..15: sub*8 + k2r */              \
            int bc_ = (t_ & 31) * 4;                                            \
            cpa16(Bsm + s_ * PJB + brow_ * 132 + bc_,                           \
                  wsrc + (size_t)(k2base_ + brow_) * 1024 + bc_);               \
        }                                                                       \
        CP_COMMIT();                                                            \
    }

    PROJ_ISSUE(0);
    PROJ_ISSUE(1);

    for (int it = 0; it < 32; it++) {
        if (it >= 30) { CP_WAIT0(); } else { CP_WAIT1(); }
        __syncthreads();
        if (it + 2 < 32) PROJ_ISSUE(it + 2);
        const unsigned* Ast = Asm + (it % PSTG) * PJA;
        const unsigned* Bst = Bsm + (it % PSTG) * PJB;
#pragma unroll
        for (int s = 0; s < 2; s++) {
            const unsigned* As_ = Ast + s * 1536;
            const unsigned* Bs_ = Bst + s * 1056;
            unsigned a[2][4], bb[8][2];
#pragma unroll
            for (int mf = 0; mf < 2; mf++) {
                int rr = wm * 32 + mf * 16 + grp;
                a[mf][0] = As_[rr * 12 + thr];
                a[mf][1] = As_[(rr + 8) * 12 + thr];
                a[mf][2] = As_[rr * 12 + thr + 4];
                a[mf][3] = As_[(rr + 8) * 12 + thr + 4];
            }
#pragma unroll
            for (int nf = 0; nf < 8; nf++) {
                int cc = wn * 64 + nf * 8 + grp;
                bb[nf][0] = Bs_[thr * 132 + cc];
                bb[nf][1] = Bs_[(thr + 4) * 132 + cc];
            }
#pragma unroll
            for (int mf = 0; mf < 2; mf++)
#pragma unroll
                for (int nf = 0; nf < 8; nf++)
                    mma_bf16(acc[mf][nf], a[mf], bb[nf][0], bb[nf][1]);
        }
        __syncthreads();
    }
#pragma unroll
    for (int mf = 0; mf < 2; mf++)
#pragma unroll
        for (int nf = 0; nf < 8; nf++) {
            int rr = crb + wm * 32 + mf * 16 + grp;
            int c2 = (colbase >> 1) + wn * 32 + nf * 4 + thr;
            Cu[(size_t)rr * 512 + c2] = pk2(acc[mf][nf][0], acc[mf][nf][1]);
            Cu[(size_t)(rr + 8) * 512 + c2] = pk2(acc[mf][nf][2], acc[mf][nf][3]);
        }
#undef PROJ_ISSUE
}

// ---------------------------------------------------------------------------
// Output GEMM (bf16): g_ao = g_avb @ wob^T.  Both operands k-contiguous bf16.
// A/B stages: [2 sub][128][12 b32]
// ---------------------------------------------------------------------------
#define OJS 6144
#define OUT_SMEM ((PSTG * OJS) * 4)    // 73,728 B

__global__ __launch_bounds__(256, 2) void out_mma()
{
    extern __shared__ unsigned psm[];

    const int rowbase = blockIdx.y * 128;
    const int colbase = blockIdx.x * 128;
    const int tid = threadIdx.x;
    const int lane = tid & 31, warp = tid >> 5;
    const int wm = warp & 3, wn = warp >> 2;
    const int grp = lane >> 2, thr = lane & 3;

    float acc[2][8][4];
#pragma unroll
    for (int mf = 0; mf < 2; mf++)
#pragma unroll
        for (int nf = 0; nf < 8; nf++)
#pragma unroll
            for (int q = 0; q < 4; q++) acc[mf][nf][q] = 0.f;

#define OUT_ISSUE(it)                                                           \
    {                                                                           \
        int s_ = (it) % PSTG;                                                   \
        int k2base_ = (it) * 16;                                                \
        for (int t_ = tid; t_ < 512; t_ += 256) {                               \
            int row_ = (t_ & 255) >> 1;                                         \
            int sub_ = t_ & 1;                                                  \
            const unsigned* src_;                                               \
            unsigned* dst_;                                                     \
            if (t_ < 256) {                                                     \
                src_ = g_avb_u + (size_t)(rowbase + row_) * 512;                \
                dst_ = psm + s_ * OJS + sub_ * 1536 + row_ * 12;                \
            } else {                                                            \
                src_ = g_wob_u + (size_t)(colbase + row_) * 512;                \
                dst_ = psm + s_ * OJS + 3072 + sub_ * 1536 + row_ * 12;         \
            }                                                                   \
            cpa16(dst_,     src_ + k2base_ + sub_ * 8);                         \
            cpa16(dst_ + 4, src_ + k2base_ + sub_ * 8 + 4);                     \
        }                                                                       \
        CP_COMMIT();                                                            \
    }

    OUT_ISSUE(0);
    OUT_ISSUE(1);

    for (int it = 0; it < 32; it++) {
        if (it >= 30) { CP_WAIT0(); } else { CP_WAIT1(); }
        __syncthreads();
        if (it + 2 < 32) OUT_ISSUE(it + 2);
        const unsigned* stg = psm + (it % PSTG) * OJS;
#pragma unroll
        for (int s = 0; s < 2; s++) {
            const unsigned* As_ = stg + s * 1536;
            const unsigned* Bs_ = stg + 3072 + s * 1536;
            unsigned a[2][4], bb[8][2];
#pragma unroll
            for (int mf = 0; mf < 2; mf++) {
                int rr = wm * 32 + mf * 16 + grp;
                a[mf][0] = As_[rr * 12 + thr];
                a[mf][1] = As_[(rr + 8) * 12 + thr];
                a[mf][2] = As_[rr * 12 + thr + 4];
                a[mf][3] = As_[(rr + 8) * 12 + thr + 4];
            }
#pragma unroll
            for (int nf = 0; nf < 8; nf++) {
                int cc = wn * 64 + nf * 8 + grp;
                bb[nf][0] = Bs_[cc * 12 + thr];
                bb[nf][1] = Bs_[cc * 12 + thr + 4];
            }
#pragma unroll
            for (int mf = 0; mf < 2; mf++)
#pragma unroll
                for (int nf = 0; nf < 8; nf++)
                    mma_bf16(acc[mf][nf], a[mf], bb[nf][0], bb[nf][1]);
        }
        __syncthreads();
    }
#pragma unroll
    for (int mf = 0; mf < 2; mf++)
#pragma unroll
        for (int nf = 0; nf < 8; nf++) {
            int rr = rowbase + wm * 32 + mf * 16 + grp;
            int cc = colbase + wn * 64 + nf * 8 + thr * 2;
            *(float2*)&g_ao[(size_t)rr * 1024 + cc] = make_float2(acc[mf][nf][0], acc[mf][nf][1]);
            *(float2*)&g_ao[(size_t)(rr + 8) * 1024 + cc] = make_float2(acc[mf][nf][2], acc[mf][nf][3]);
        }
#undef OUT_ISSUE
}

// ---------------------------------------------------------------------------
// ef head projections (reads bf16 q)
// ---------------------------------------------------------------------------
__global__ __launch_bounds__(512) void e_kernel(
    const float* __restrict__ rsb, const float* __restrict__ seg_embed)
{
    const int row = blockIdx.x;                 // i*4+b
    const int i = row >> 2, b = row & 3;
    const int n = threadIdx.x >> 5, lane = threadIdx.x & 31;
    const __nv_bfloat16* qb = (const __nv_bfloat16*)g_qb_u;

    float q1 = __bfloat162float(qb[(size_t)row * 1024 + n * 64 + lane]) + rsb[n * 64 + lane];
    float q2 = __bfloat162float(qb[(size_t)row * 1024 + n * 64 + lane + 32]) + rsb[n * 64 + lane + 32];
    float p0 = q1 * seg_embed[(0 * 16 + n) * 64 + lane] + q2 * seg_embed[(0 * 16 + n) * 64 + lane + 32];
    float p1 = q1 * seg_embed[(1 * 16 + n) * 64 + lane] + q2 * seg_embed[(1 * 16 + n) * 64 + lane + 32];
#pragma unroll
    for (int o = 16; o; o >>= 1) {
        p0 += __shfl_xor_sync(0xffffffffu, p0, o);
        p1 += __shfl_xor_sync(0xffffffffu, p1, o);
    }
    if (lane == 0) {
        g_e[((size_t)(0 * 512 + i) * 4 + b) * 16 + n] = p0;
        g_e[((size_t)(512 + i) * 4 + b) * 16 + n] = p1;
    }
}

// ---------------------------------------------------------------------------
// u = rwb·k ; t = rrb·kr  (reads bf16)
// ---------------------------------------------------------------------------
__global__ __launch_bounds__(512) void ut_kernel(
    const float* __restrict__ rwb, const float* __restrict__ rrb)
{
    int row = blockIdx.x;
    const __nv_bfloat16* src;
    const float* bias;
    float* dst;
    if (row < 4096) {
        src = (const __nv_bfloat16*)g_kb_u + (size_t)row * 1024;
        bias = rwb; dst = g_u + (size_t)row * 16;
    } else {
        row -= 4096;
        src = (const __nv_bfloat16*)g_krb_u + (size_t)row * 1024;
        bias = rrb; dst = g_t + (size_t)row * 16;
    }
    const int n = threadIdx.x >> 5, lane = threadIdx.x & 31;
    float p = __bfloat162float(src[n * 64 + lane]) * bias[n * 64 + lane]
            + __bfloat162float(src[n * 64 + lane + 32]) * bias[n * 64 + lane + 32];
#pragma unroll
    for (int o = 16; o; o >>= 1) p += __shfl_xor_sync(0xffffffffu, p, o);
    if (lane == 0) dst[n] = p;
}

// ---------------------------------------------------------------------------
// Pack seg-bit + mask-bit into one byte, layout [b][i][j].
// ---------------------------------------------------------------------------
__global__ __launch_bounds__(256) void code_kernel(
    const float* __restrict__ seg_mat, const float* __restrict__ attn_mask)
{
    int idx = blockIdx.x * 256 + threadIdx.x;   // (i*1024 + j)*4 + b
    if (idx < 512 * 1024 * 4) {
        int b = idx & 3;
        int ij = idx >> 2;
        unsigned char c = (seg_mat[(size_t)idx * 2 + 1] != 0.f) ? 1 : 0;
        if (attn_mask[idx] != 0.f) c |= 2;
        g_code[((size_t)b << 19) + ij] = c;
    }
}

// ---------------------------------------------------------------------------
// Fused attention on bf16 tensor cores (flash style) + krs ring buffer.
// smem (b32): ks 64x36, krs 128x36 (ring), vs 64x36 (bf16 [j][d], ldmatrix'd),
//             Ps 64x36 (bf16 pairs), Gs fp32 64x136, ub 64, tb2 128, red 256
// total 20,672 b32 = 82,688 B -> 2 blocks/SM.
// ---------------------------------------------------------------------------
#define GST 136
#define ATT_SMEM_BYTES ((64*36 + 128*36 + 64*36 + 64*36 + 64*GST + 64 + 128 + 256) * 4)

__global__ __launch_bounds__(256, 2) void attn_kernel()
{
    extern __shared__ unsigned smu[];
    unsigned* ksu = smu;                        // 64 x 36
    unsigned* kru = ksu + 64 * 36;              // 128 x 36 (2-panel ring)
    unsigned* vsu = kru + 128 * 36;             // 64 x 36 (bf16 [j][d+pad])
    unsigned* Psu = vsu + 64 * 36;              // 64 x 36 (bf16 P pairs)
    float* Gs  = (float*)(Psu + 64 * 36);       // 64 x 136
    float* ub  = Gs + 64 * GST;                 // 64
    float* tb2 = ub + 64;                       // 128 (ring)
    float* red = tb2 + 128;                     // 256
    const __nv_bfloat16* vsb = (const __nv_bfloat16*)vsu;  // row stride 72 bf16

    const int bnix = blockIdx.x;
    const int b = bnix >> 4, n = bnix & 15;
    const int i0 = blockIdx.y * 64;
    const int tid = threadIdx.x;
    const int warp = tid >> 5, lane = tid & 31;
    const int wm = warp & 3, wn = warp >> 2;
    const int grp = lane >> 2, thr = lane & 3;
    const int r0 = wm * 16 + grp;      // local rows r0, r0+8

    // ---- q fragments straight from global bf16 ----
    unsigned qa[4][4];
    {
        const unsigned* qbu = g_qb_u;
#pragma unroll
        for (int kc = 0; kc < 4; kc++) {
            size_t b0 = ((size_t)(i0 + r0) * 4 + b) * 512 + n * 32 + kc * 8;
            size_t b1 = ((size_t)(i0 + r0 + 8) * 4 + b) * 512 + n * 32 + kc * 8;
            qa[kc][0] = qbu[b0 + thr];
            qa[kc][1] = qbu[b1 + thr];
            qa[kc][2] = qbu[b0 + thr + 4];
            qa[kc][3] = qbu[b1 + thr + 4];
        }
    }

    float e0[2], e1[2];
    e0[0] = g_e[((size_t)(i0 + r0) * 4 + b) * 16 + n];
    e0[1] = g_e[((size_t)(i0 + r0 + 8) * 4 + b) * 16 + n];
    e1[0] = g_e[((size_t)(512 + i0 + r0) * 4 + b) * 16 + n];
    e1[1] = g_e[((size_t)(512 + i0 + r0 + 8) * 4 + b) * 16 + n];

    float oacc[4][4];
#pragma unroll
    for (int nt = 0; nt < 4; nt++)
#pragma unroll
        for (int q = 0; q < 4; q++) oacc[nt][q] = 0.f;
    float rmax[2] = {-3.0e38f, -3.0e38f};
    float rsum[2] = {0.f, 0.f};

    const unsigned char* codeRow0 = g_code + ((size_t)b << 19) + (size_t)(i0 + r0) * 1024;
    const unsigned char* codeRow1 = codeRow0 + 8 * 1024;

    int P = 7 - (i0 >> 6);   // panel index of window start; +1 per j-iter

    for (int j0 = 0; j0 < KLEN; j0 += 64, P++) {
        __syncthreads();
        const int base = j0 - i0 + 448;
        const int Pp = P & 1;
        // ---- async tile loads (bf16: 32 b32/row data) ----
        for (int t = tid; t < 512; t += 256) {
            int row = t >> 3, c = (t & 7) * 4;
            size_t goff = ((size_t)(j0 + row) * 4 + b) * 512 + n * 32 + c;
            cpa16(&ksu[row * 36 + c], g_kb_u + goff);
            cpa16(&vsu[row * 36 + c], g_vb_u + goff);
        }
        const int startrow = (j0 == 0) ? 0 : 64;
        for (int t = tid; t < (128 - startrow) * 8; t += 256) {
            int row = startrow + (t >> 3), c = (t & 7) * 4;
            int slab = ((Pp + (row >> 6)) & 1) * 64 + (row & 63);
            cpa16(&kru[slab * 36 + c],
                  g_krb_u + ((size_t)(base + row) * 4 + b) * 512 + n * 32 + c);
        }
        CP_COMMIT();
        // ---- scalar ub/tb loads ----
        if (tid < 64) {
            ub[tid] = g_u[((size_t)(j0 + tid) * 4 + b) * 16 + n];
        } else if (tid < 192) {
            int m = tid - 64 + startrow;
            if (m < 128) {
                int slab = ((Pp + (m >> 6)) & 1) * 64 + (m & 63);
                tb2[slab] = g_t[((size_t)(base + m) * 4 + b) * 16 + n];
            }
        }
        CP_WAIT0();
        __syncthreads();

        // ---- S = q @ k^T (warp's 32-col half) ----
        float sacc[4][4];
#pragma unroll
        for (int nt = 0; nt < 4; nt++)
#pragma unroll
            for (int q = 0; q < 4; q++) sacc[nt][q] = 0.f;
#pragma unroll
        for (int kc = 0; kc < 4; kc++) {
#pragma unroll
            for (int nt = 0; nt < 4; nt++) {
                int jc = wn * 32 + nt * 8 + grp;
                mma_bf16(sacc[nt], qa[kc],
                         ksu[jc * 36 + kc * 8 + thr],
                         ksu[jc * 36 + kc * 8 + thr + 4]);
            }
        }

        // ---- G = q @ krs^T (warp's 64-col half of 128), +tb on store ----
        const int slabbase = ((Pp + wn) & 1) * 64;   // mc>>6 == wn
#pragma unroll
        for (int gh = 0; gh < 2; gh++) {
            float gacc[4][4];
#pragma unroll
            for (int nt = 0; nt < 4; nt++)
#pragma unroll
                for (int q = 0; q < 4; q++) gacc[nt][q] = 0.f;
#pragma unroll
            for (int kc = 0; kc < 4; kc++) {
#pragma unroll
                for (int nt = 0; nt < 4; nt++) {
                    int mrow = slabbase + gh * 32 + nt * 8 + grp;
                    mma_bf16(gacc[nt], qa[kc],
                             kru[mrow * 36 + kc * 8 + thr],
                             kru[mrow * 36 + kc * 8 + thr + 4]);
                }
            }
#pragma unroll
            for (int nt = 0; nt < 4; nt++) {
                int c63 = gh * 32 + nt * 8 + 2 * thr;     // mc & 63
                int c = wn * 64 + c63;                    // ordered local m
                float t0 = tb2[slabbase + c63], t1 = tb2[slabbase + c63 + 1];
                *(float2*)&Gs[r0 * GST + c] = make_float2(gacc[nt][0] + t0, gacc[nt][1] + t1);
                *(float2*)&Gs[(r0 + 8) * GST + c] = make_float2(gacc[nt][2] + t0, gacc[nt][3] + t1);
            }
        }
        __syncthreads();   // Gs ready (cross-warp reads)

        // ---- assemble logits, per-thread row maxes ----
        float mx0 = -3.0e38f, mx1 = -3.0e38f;
#pragma unroll
        for (int nt = 0; nt < 4; nt++) {
            int c = wn * 32 + nt * 8 + 2 * thr;
            unsigned char cc00 = codeRow0[j0 + c], cc01 = codeRow0[j0 + c + 1];
            unsigned char cc10 = codeRow1[j0 + c], cc11 = codeRow1[j0 + c + 1];
            float u0 = ub[c], u1 = ub[c + 1];
            float v;
            v = (sacc[nt][0] + Gs[r0 * GST + c     - r0 + 64] + u0 + ((cc00 & 1) ? e1[0] : e0[0])) * SCALE;
            if (cc00 & 2) v -= 1e30f;
            sacc[nt][0] = v; mx0 = fmaxf(mx0, v);
            v = (sacc[nt][1] + Gs[r0 * GST + c + 1 - r0 + 64] + u1 + ((cc01 & 1) ? e1[0] : e0[0])) * SCALE;
            if (cc01 & 2) v -= 1e30f;
            sacc[nt][1] = v; mx0 = fmaxf(mx0, v);
            v = (sacc[nt][2] + Gs[(r0 + 8) * GST + c     - r0 + 56] + u0 + ((cc10 & 1) ? e1[1] : e0[1])) * SCALE;
            if (cc10 & 2) v -= 1e30f;
            sacc[nt][2] = v; mx1 = fmaxf(mx1, v);
            v = (sacc[nt][3] + Gs[(r0 + 8) * GST + c + 1 - r0 + 56] + u1 + ((cc11 & 1) ? e1[1] : e0[1])) * SCALE;
            if (cc11 & 2) v -= 1e30f;
            sacc[nt][3] = v; mx1 = fmaxf(mx1, v);
        }
#pragma unroll
        for (int o = 1; o < 4; o <<= 1) {
            mx0 = fmaxf(mx0, __shfl_xor_sync(0xffffffffu, mx0, o));
            mx1 = fmaxf(mx1, __shfl_xor_sync(0xffffffffu, mx1, o));
        }
        if (thr == 0) {
            red[wn * 64 + wm * 16 + grp] = mx0;
            red[wn * 64 + wm * 16 + grp + 8] = mx1;
        }
        __syncthreads();   // both halves' maxes ready

        float tm0 = fmaxf(red[wm * 16 + grp], red[64 + wm * 16 + grp]);
        float tm1 = fmaxf(red[wm * 16 + grp + 8], red[64 + wm * 16 + grp + 8]);
        float nm0 = fmaxf(rmax[0], tm0);
        float nm1 = fmaxf(rmax[1], tm1);
        float corr0 = __expf(rmax[0] - nm0);
        float corr1 = __expf(rmax[1] - nm1);
        rmax[0] = nm0; rmax[1] = nm1;

        float sum0 = 0.f, sum1 = 0.f;
#pragma unroll
        for (int nt = 0; nt < 4; nt++) {
            int c2 = wn * 16 + nt * 4 + thr;
            float p0 = __expf(sacc[nt][0] - nm0);
            float p1 = __expf(sacc[nt][1] - nm0);
            float p2 = __expf(sacc[nt][2] - nm1);
            float p3 = __expf(sacc[nt][3] - nm1);
            sum0 += p0 + p1; sum1 += p2 + p3;
            Psu[r0 * 36 + c2] = pk2(p0, p1);
            Psu[(r0 + 8) * 36 + c2] = pk2(p2, p3);
        }
#pragma unroll
        for (int o = 1; o < 4; o <<= 1) {
            sum0 += __shfl_xor_sync(0xffffffffu, sum0, o);
            sum1 += __shfl_xor_sync(0xffffffffu, sum1, o);
        }
        if (thr == 0) {
            red[128 + wn * 64 + wm * 16 + grp] = sum0;
            red[128 + wn * 64 + wm * 16 + grp + 8] = sum1;
        }
        __syncthreads();   // Ps + sums ready

        rsum[0] = rsum[0] * corr0 + red[128 + wm * 16 + grp] + red[192 + wm * 16 + grp];
        rsum[1] = rsum[1] * corr1 + red[128 + wm * 16 + grp + 8] + red[192 + wm * 16 + grp + 8];

        // ---- O = O*corr + P @ V (V^T via ldmatrix.trans) ----
#pragma unroll
        for (int nt = 0; nt < 4; nt++) {
            oacc[nt][0] *= corr0; oacc[nt][1] *= corr0;
            oacc[nt][2] *= corr1; oacc[nt][3] *= corr1;
        }
#pragma unroll
        for (int kc = 0; kc < 4; kc++) {
            unsigned a[4];
            a[0] = Psu[r0 * 36 + kc * 8 + thr];
            a[1] = Psu[(r0 + 8) * 36 + kc * 8 + thr];
            a[2] = Psu[r0 * 36 + kc * 8 + thr + 4];
            a[3] = Psu[(r0 + 8) * 36 + kc * 8 + thr + 4];
#pragma unroll
            for (int nt = 0; nt < 4; nt++) {
                unsigned b0, b1;
                ldsm_x2_t(b0, b1, vsb + (kc * 16 + (lane & 15)) * 72 + wn * 32 + nt * 8);
                mma_bf16(oacc[nt], a, b0, b1);
            }
        }
    }

    // ---- write normalized output (bf16) ----
    float inv0 = 1.f / rsum[0];
    float inv1 = 1.f / rsum[1];
#pragma unroll
    for (int nt = 0; nt < 4; nt++) {
        int d2 = n * 32 + wn * 16 + nt * 4 + thr;
        g_avb_u[((size_t)(i0 + r0) * 4 + b) * 512 + d2] =
            pk2(oacc[nt][0] * inv0, oacc[nt][1] * inv0);
        g_avb_u[((size_t)(i0 + r0 + 8) * 4 + b) * 512 + d2] =
            pk2(oacc[nt][2] * inv1, oacc[nt][3] * inv1);
    }
}

// ---------------------------------------------------------------------------
// Residual + LayerNorm
// ---------------------------------------------------------------------------
__global__ __launch_bounds__(256) void ln_kernel(
    const float* __restrict__ hres, const float* __restrict__ gamma,
    const float* __restrict__ beta, float* __restrict__ out)
{
    __shared__ float xb[1024];
    __shared__ float red[8];
    const int row = blockIdx.x;
    const int tid = threadIdx.x;
    const float* ao = g_ao + (size_t)row * 1024;
    const float* hh = hres + (size_t)row * 1024;

    float s = 0.f;
    for (int c = tid; c < 1024; c += 256) {
        float x = ao[c] + hh[c];
        xb[c] = x;
        s += x;
    }
#pragma unroll
    for (int o = 16; o; o >>= 1) s += __shfl_xor_sync(0xffffffffu, s, o);
    if ((tid & 31) == 0) red[tid >> 5] = s;
    __syncthreads();
    float tot = 0.f;
#pragma unroll
    for (int k = 0; k < 8; k++) tot += red[k];
    const float mean = tot * (1.f / 1024.f);
    __syncthreads();

    float s2 = 0.f;
    for (int c = tid; c < 1024; c += 256) {
        float dx = xb[c] - mean;
        s2 += dx * dx;
    }
#pragma unroll
    for (int o = 16; o; o >>= 1) s2 += __shfl_xor_sync(0xffffffffu, s2, o);
    if ((tid & 31) == 0) red[tid >> 5] = s2;
    __syncthreads();
    float tot2 = 0.f;
#pragma unroll
    for (int k = 0; k < 8; k++) tot2 += red[k];
    const float inv = rsqrtf(tot2 * (1.f / 1024.f) + LN_EPS);

    for (int c = tid; c < 1024; c += 256)
        out[(size_t)row * 1024 + c] = (xb[c] - mean) * inv * gamma[c] + beta[c];
}

// ---------------------------------------------------------------------------
extern "C" void kernel_launch(void* const* d_in, const int* in_sizes, int n_in,
                              void* d_out, int out_size)
{
    const float* rwb       = (const float*)d_in[0];
    const float* rsb       = (const float*)d_in[1];
    const float* rrb       = (const float*)d_in[2];
    const float* seg_embed = (const float*)d_in[3];
    const float* h         = (const float*)d_in[4];
    const float* r         = (const float*)d_in[5];
    const float* mems      = (const float*)d_in[6];
    const float* seg_mat   = (const float*)d_in[7];
    const float* attn_mask = (const float*)d_in[8];
    const float* wq        = (const float*)d_in[9];
    const float* wk        = (const float*)d_in[10];
    const float* wv        = (const float*)d_in[11];
    const float* wr        = (const float*)d_in[12];
    const float* wo        = (const float*)d_in[13];
    const float* gamma     = (const float*)d_in[14];
    const float* beta      = (const float*)d_in[15];

    cudaFuncSetAttribute(attn_kernel, cudaFuncAttributeMaxDynamicSharedMemorySize, ATT_SMEM_BYTES);
    cudaFuncSetAttribute(proj_mma, cudaFuncAttributeMaxDynamicSharedMemorySize, PROJ_SMEM);
    cudaFuncSetAttribute(out_mma, cudaFuncAttributeMaxDynamicSharedMemorySize, OUT_SMEM);

    conv_cast<<<22528, 256>>>(mems, h, r, wo);
    conv_pack<<<8192, 256>>>(wq, wk, wv, wr);
    proj_mma<<<dim3(8, 128), 256, PROJ_SMEM>>>();
    e_kernel<<<2048, 512>>>(rsb, seg_embed);
    ut_kernel<<<10240, 512>>>(rwb, rrb);
    code_kernel<<<8192, 256>>>(seg_mat, attn_mask);
    attn_kernel<<<dim3(64, 8), 256, ATT_SMEM_BYTES>>>();
    out_mma<<<dim3(8, 16), 256, OUT_SMEM>>>();
    ln_kernel<<<2048, 256>>>(h, gamma, beta, (float*)d_out);
}

// round 8
// speedup vs baseline: 4.7735x; 1.0640x over previous
#include <cuda_runtime.h>
#include <cuda_bf16.h>
#include <math.h>

// Problem constants
#define QLEN 512
#define MLEN 512
#define KLEN 1024
#define RLEN 1536
#define BATCH 4
#define DM 1024
#define NH 16
#define DH 64
#define SCALE 0.125f
#define LN_EPS 1e-3f

// Scratch (device globals; no allocation allowed).  All "_u" arrays hold
// packed bf16 pairs (low 16 bits = even index).
__device__ unsigned g_ab_u [10240 * 512];  // [mems(2048); h(2048); r(6144)] rows x 1024 bf16
__device__ unsigned g_wpk_u[4 * 512 * 1024]; // proj weights, [w][k2][n] bf16-pairs along k
__device__ unsigned g_wob_u[1024 * 512];   // wo bf16 [h][1024]
__device__ unsigned g_qb_u [2048 * 512];   // q_head  bf16 [i*4+b][n*64+d]
__device__ unsigned g_kb_u [4096 * 512];   // k_head  bf16
__device__ unsigned g_vb_u [4096 * 512];   // v_head  bf16
__device__ unsigned g_krb_u[6144 * 512];   // k_r     bf16
__device__ unsigned g_avb_u[2048 * 512];   // attn_vec bf16
__device__ float g_e [2 * 512 * 4 * 16];   // ef  [s][i][b][n]
__device__ float g_u [4096 * 16];          // rwb·k
__device__ float g_t [6144 * 16];          // rrb·kr
__device__ unsigned char g_code[4 * 512 * 1024]; // [b][i][j]: bit0=seg, bit1=mask
__device__ float g_ao[2048 * 1024];        // attn_out (pre-LN, fp32)

// ---------------------------------------------------------------------------
// helpers
// ---------------------------------------------------------------------------
__device__ __forceinline__ unsigned pk2(float lo, float hi) {
    unsigned r;
    asm("cvt.rn.bf16x2.f32 %0, %1, %2;" : "=r"(r) : "f"(hi), "f"(lo));
    return r;
}

__device__ __forceinline__ void mma_bf16(float* d, const unsigned* a,
                                         unsigned b0, unsigned b1) {
    asm volatile(
        "mma.sync.aligned.m16n8k16.row.col.f32.bf16.bf16.f32 "
        "{%0,%1,%2,%3}, {%4,%5,%6,%7}, {%8,%9}, {%0,%1,%2,%3};\n"
        : "+f"(d[0]), "+f"(d[1]), "+f"(d[2]), "+f"(d[3])
        : "r"(a[0]), "r"(a[1]), "r"(a[2]), "r"(a[3]), "r"(b0), "r"(b1));
}

__device__ __forceinline__ void cpa16(void* dst, const void* src) {
    unsigned d = (unsigned)__cvta_generic_to_shared(dst);
    asm volatile("cp.async.cg.shared.global [%0], [%1], 16;\n" :: "r"(d), "l"(src));
}
#define CP_COMMIT() asm volatile("cp.async.commit_group;\n")
#define CP_WAIT0()  asm volatile("cp.async.wait_group 0;\n")
#define CP_WAIT1()  asm volatile("cp.async.wait_group 1;\n")

__device__ __forceinline__ void ldsm_x2_t(unsigned& r0, unsigned& r1, const void* p) {
    unsigned a = (unsigned)__cvta_generic_to_shared(p);
    asm volatile("ldmatrix.sync.aligned.m8n8.x2.trans.shared.b16 {%0,%1}, [%2];"
                 : "=r"(r0), "=r"(r1) : "r"(a));
}

// ---------------------------------------------------------------------------
// Conversion kernels (fp32 -> bf16)
// ---------------------------------------------------------------------------
__global__ __launch_bounds__(256) void conv_cast(
    const float* __restrict__ mems, const float* __restrict__ h,
    const float* __restrict__ r, const float* __restrict__ wo)
{
    int idx = blockIdx.x * 256 + threadIdx.x;   // < 11264*512
    int row = idx >> 9, p = idx & 511;
    const float* src;
    unsigned* dst;
    if (row < 2048)      { src = mems + (size_t)row * 1024;          dst = g_ab_u + (size_t)row * 512; }
    else if (row < 4096) { src = h + (size_t)(row - 2048) * 1024;    dst = g_ab_u + (size_t)row * 512; }
    else if (row < 10240){ src = r + (size_t)(row - 4096) * 1024;    dst = g_ab_u + (size_t)row * 512; }
    else                 { src = wo + (size_t)(row - 10240) * 1024;  dst = g_wob_u + (size_t)(row - 10240) * 512; }
    float2 v = *(const float2*)(src + p * 2);
    dst[p] = pk2(v.x, v.y);
}

__global__ __launch_bounds__(256) void conv_pack(
    const float* __restrict__ wq, const float* __restrict__ wk,
    const float* __restrict__ wv, const float* __restrict__ wr)
{
    int idx = blockIdx.x * 256 + threadIdx.x;   // < 4*512*1024
    int w = idx >> 19;
    int rem = idx & ((1 << 19) - 1);
    int k2 = rem >> 10, nn = rem & 1023;
    const float* W = (w == 0) ? wq : (w == 1) ? wk : (w == 2) ? wv : wr;
    float a = W[(size_t)(2 * k2) * 1024 + nn];
    float bq = W[(size_t)(2 * k2 + 1) * 1024 + nn];
    g_wpk_u[(size_t)w * 524288 + rem] = pk2(a, bq);
}

// ---------------------------------------------------------------------------
// Projection GEMM (bf16 m16n8k16, cp.async 3-stage, k32/iter).
// ---------------------------------------------------------------------------
#define PSTG 3
#define PJA 3072
#define PJB 2112
#define PROJ_SMEM ((PSTG * (PJA + PJB)) * 4)   // 62,208 B

__global__ __launch_bounds__(256, 2) void proj_mma()
{
    extern __shared__ unsigned psm[];
    unsigned* Asm = psm;
    unsigned* Bsm = psm + PSTG * PJA;

    const int rowbase = blockIdx.y * 128;
    const int colbase = blockIdx.x * 128;

    int abase, wsel, segbase;
    unsigned* Cu;
    if (rowbase < 2048)        { wsel = 0; segbase = 0;     abase = 2048; Cu = g_qb_u;  }
    else if (rowbase < 6144)   { wsel = 1; segbase = 2048;  abase = 0;    Cu = g_kb_u;  }
    else if (rowbase < 10240)  { wsel = 2; segbase = 6144;  abase = 0;    Cu = g_vb_u;  }
    else                       { wsel = 3; segbase = 10240; abase = 4096; Cu = g_krb_u; }
    const int crb = rowbase - segbase;

    const int tid = threadIdx.x;
    const int lane = tid & 31, warp = tid >> 5;
    const int wm = warp & 3, wn = warp >> 2;
    const int grp = lane >> 2, thr = lane & 3;

    const int arw = tid >> 1;
    const int asub = tid & 1;
    const unsigned* asrc = g_ab_u + (size_t)(abase + crb + arw) * 512 + asub * 8;
    const unsigned* wsrc = g_wpk_u + (size_t)wsel * 524288 + colbase;

    float acc[2][8][4];
#pragma unroll
    for (int mf = 0; mf < 2; mf++)
#pragma unroll
        for (int nf = 0; nf < 8; nf++)
#pragma unroll
            for (int q = 0; q < 4; q++) acc[mf][nf][q] = 0.f;

#define PROJ_ISSUE(it)                                                          \
    {                                                                           \
        int s_ = (it) % PSTG;                                                   \
        int k2base_ = (it) * 16;                                                \
        unsigned* ad = Asm + s_ * PJA + asub * 1536 + arw * 12;                 \
        cpa16(ad,     asrc + k2base_);                                          \
        cpa16(ad + 4, asrc + k2base_ + 4);                                      \
        for (int t_ = tid; t_ < 512; t_ += 256) {                               \
            int brow_ = t_ >> 5;                                                \
            int bc_ = (t_ & 31) * 4;                                            \
            cpa16(Bsm + s_ * PJB + brow_ * 132 + bc_,                           \
                  wsrc + (size_t)(k2base_ + brow_) * 1024 + bc_);               \
        }                                                                       \
        CP_COMMIT();                                                            \
    }

    PROJ_ISSUE(0);
    PROJ_ISSUE(1);

    for (int it = 0; it < 32; it++) {
        if (it >= 30) { CP_WAIT0(); } else { CP_WAIT1(); }
        __syncthreads();
        if (it + 2 < 32) PROJ_ISSUE(it + 2);
        const unsigned* Ast = Asm + (it % PSTG) * PJA;
        const unsigned* Bst = Bsm + (it % PSTG) * PJB;
#pragma unroll
        for (int s = 0; s < 2; s++) {
            const unsigned* As_ = Ast + s * 1536;
            const unsigned* Bs_ = Bst + s * 1056;
            unsigned a[2][4], bb[8][2];
#pragma unroll
            for (int mf = 0; mf < 2; mf++) {
                int rr = wm * 32 + mf * 16 + grp;
                a[mf][0] = As_[rr * 12 + thr];
                a[mf][1] = As_[(rr + 8) * 12 + thr];
                a[mf][2] = As_[rr * 12 + thr + 4];
                a[mf][3] = As_[(rr + 8) * 12 + thr + 4];
            }
#pragma unroll
            for (int nf = 0; nf < 8; nf++) {
                int cc = wn * 64 + nf * 8 + grp;
                bb[nf][0] = Bs_[thr * 132 + cc];
                bb[nf][1] = Bs_[(thr + 4) * 132 + cc];
            }
#pragma unroll
            for (int mf = 0; mf < 2; mf++)
#pragma unroll
                for (int nf = 0; nf < 8; nf++)
                    mma_bf16(acc[mf][nf], a[mf], bb[nf][0], bb[nf][1]);
        }
        __syncthreads();
    }
#pragma unroll
    for (int mf = 0; mf < 2; mf++)
#pragma unroll
        for (int nf = 0; nf < 8; nf++) {
            int rr = crb + wm * 32 + mf * 16 + grp;
            int c2 = (colbase >> 1) + wn * 32 + nf * 4 + thr;
            Cu[(size_t)rr * 512 + c2] = pk2(acc[mf][nf][0], acc[mf][nf][1]);
            Cu[(size_t)(rr + 8) * 512 + c2] = pk2(acc[mf][nf][2], acc[mf][nf][3]);
        }
#undef PROJ_ISSUE
}

// ---------------------------------------------------------------------------
// Output GEMM (bf16): g_ao = g_avb @ wob^T.
// ---------------------------------------------------------------------------
#define OJS 6144
#define OUT_SMEM ((PSTG * OJS) * 4)    // 73,728 B

__global__ __launch_bounds__(256, 2) void out_mma()
{
    extern __shared__ unsigned psm[];

    const int rowbase = blockIdx.y * 128;
    const int colbase = blockIdx.x * 128;
    const int tid = threadIdx.x;
    const int lane = tid & 31, warp = tid >> 5;
    const int wm = warp & 3, wn = warp >> 2;
    const int grp = lane >> 2, thr = lane & 3;

    float acc[2][8][4];
#pragma unroll
    for (int mf = 0; mf < 2; mf++)
#pragma unroll
        for (int nf = 0; nf < 8; nf++)
#pragma unroll
            for (int q = 0; q < 4; q++) acc[mf][nf][q] = 0.f;

#define OUT_ISSUE(it)                                                           \
    {                                                                           \
        int s_ = (it) % PSTG;                                                   \
        int k2base_ = (it) * 16;                                                \
        for (int t_ = tid; t_ < 512; t_ += 256) {                               \
            int row_ = (t_ & 255) >> 1;                                         \
            int sub_ = t_ & 1;                                                  \
            const unsigned* src_;                                               \
            unsigned* dst_;                                                     \
            if (t_ < 256) {                                                     \
                src_ = g_avb_u + (size_t)(rowbase + row_) * 512;                \
                dst_ = psm + s_ * OJS + sub_ * 1536 + row_ * 12;                \
            } else {                                                            \
                src_ = g_wob_u + (size_t)(colbase + row_) * 512;                \
                dst_ = psm + s_ * OJS + 3072 + sub_ * 1536 + row_ * 12;         \
            }                                                                   \
            cpa16(dst_,     src_ + k2base_ + sub_ * 8);                         \
            cpa16(dst_ + 4, src_ + k2base_ + sub_ * 8 + 4);                     \
        }                                                                       \
        CP_COMMIT();                                                            \
    }

    OUT_ISSUE(0);
    OUT_ISSUE(1);

    for (int it = 0; it < 32; it++) {
        if (it >= 30) { CP_WAIT0(); } else { CP_WAIT1(); }
        __syncthreads();
        if (it + 2 < 32) OUT_ISSUE(it + 2);
        const unsigned* stg = psm + (it % PSTG) * OJS;
#pragma unroll
        for (int s = 0; s < 2; s++) {
            const unsigned* As_ = stg + s * 1536;
            const unsigned* Bs_ = stg + 3072 + s * 1536;
            unsigned a[2][4], bb[8][2];
#pragma unroll
            for (int mf = 0; mf < 2; mf++) {
                int rr = wm * 32 + mf * 16 + grp;
                a[mf][0] = As_[rr * 12 + thr];
                a[mf][1] = As_[(rr + 8) * 12 + thr];
                a[mf][2] = As_[rr * 12 + thr + 4];
                a[mf][3] = As_[(rr + 8) * 12 + thr + 4];
            }
#pragma unroll
            for (int nf = 0; nf < 8; nf++) {
                int cc = wn * 64 + nf * 8 + grp;
                bb[nf][0] = Bs_[cc * 12 + thr];
                bb[nf][1] = Bs_[cc * 12 + thr + 4];
            }
#pragma unroll
            for (int mf = 0; mf < 2; mf++)
#pragma unroll
                for (int nf = 0; nf < 8; nf++)
                    mma_bf16(acc[mf][nf], a[mf], bb[nf][0], bb[nf][1]);
        }
        __syncthreads();
    }
#pragma unroll
    for (int mf = 0; mf < 2; mf++)
#pragma unroll
        for (int nf = 0; nf < 8; nf++) {
            int rr = rowbase + wm * 32 + mf * 16 + grp;
            int cc = colbase + wn * 64 + nf * 8 + thr * 2;
            *(float2*)&g_ao[(size_t)rr * 1024 + cc] = make_float2(acc[mf][nf][0], acc[mf][nf][1]);
            *(float2*)&g_ao[(size_t)(rr + 8) * 1024 + cc] = make_float2(acc[mf][nf][2], acc[mf][nf][3]);
        }
#undef OUT_ISSUE
}

// ---------------------------------------------------------------------------
// ef head projections (reads bf16 q)
// ---------------------------------------------------------------------------
__global__ __launch_bounds__(512) void e_kernel(
    const float* __restrict__ rsb, const float* __restrict__ seg_embed)
{
    const int row = blockIdx.x;                 // i*4+b
    const int i = row >> 2, b = row & 3;
    const int n = threadIdx.x >> 5, lane = threadIdx.x & 31;
    const __nv_bfloat16* qb = (const __nv_bfloat16*)g_qb_u;

    float q1 = __bfloat162float(qb[(size_t)row * 1024 + n * 64 + lane]) + rsb[n * 64 + lane];
    float q2 = __bfloat162float(qb[(size_t)row * 1024 + n * 64 + lane + 32]) + rsb[n * 64 + lane + 32];
    float p0 = q1 * seg_embed[(0 * 16 + n) * 64 + lane] + q2 * seg_embed[(0 * 16 + n) * 64 + lane + 32];
    float p1 = q1 * seg_embed[(1 * 16 + n) * 64 + lane] + q2 * seg_embed[(1 * 16 + n) * 64 + lane + 32];
#pragma unroll
    for (int o = 16; o; o >>= 1) {
        p0 += __shfl_xor_sync(0xffffffffu, p0, o);
        p1 += __shfl_xor_sync(0xffffffffu, p1, o);
    }
    if (lane == 0) {
        g_e[((size_t)(0 * 512 + i) * 4 + b) * 16 + n] = p0;
        g_e[((size_t)(512 + i) * 4 + b) * 16 + n] = p1;
    }
}

// ---------------------------------------------------------------------------
// u = rwb·k ; t = rrb·kr  (reads bf16)
// ---------------------------------------------------------------------------
__global__ __launch_bounds__(512) void ut_kernel(
    const float* __restrict__ rwb, const float* __restrict__ rrb)
{
    int row = blockIdx.x;
    const __nv_bfloat16* src;
    const float* bias;
    float* dst;
    if (row < 4096) {
        src = (const __nv_bfloat16*)g_kb_u + (size_t)row * 1024;
        bias = rwb; dst = g_u + (size_t)row * 16;
    } else {
        row -= 4096;
        src = (const __nv_bfloat16*)g_krb_u + (size_t)row * 1024;
        bias = rrb; dst = g_t + (size_t)row * 16;
    }
    const int n = threadIdx.x >> 5, lane = threadIdx.x & 31;
    float p = __bfloat162float(src[n * 64 + lane]) * bias[n * 64 + lane]
            + __bfloat162float(src[n * 64 + lane + 32]) * bias[n * 64 + lane + 32];
#pragma unroll
    for (int o = 16; o; o >>= 1) p += __shfl_xor_sync(0xffffffffu, p, o);
    if (lane == 0) dst[n] = p;
}

// ---------------------------------------------------------------------------
// Pack seg-bit + mask-bit into one byte, layout [b][i][j].
// ---------------------------------------------------------------------------
__global__ __launch_bounds__(256) void code_kernel(
    const float* __restrict__ seg_mat, const float* __restrict__ attn_mask)
{
    int idx = blockIdx.x * 256 + threadIdx.x;
    if (idx < 512 * 1024 * 4) {
        int b = idx & 3;
        int ij = idx >> 2;
        unsigned char c = (seg_mat[(size_t)idx * 2 + 1] != 0.f) ? 1 : 0;
        if (attn_mask[idx] != 0.f) c |= 2;
        g_code[((size_t)b << 19) + ij] = c;
    }
}

// ---------------------------------------------------------------------------
// Fused attention, warp-local design.
// Block = 128 i-rows x (b,n); 8 warps, warp wm owns rows wm*16..wm*16+15 and
// ALL 64 j-cols of each tile -> softmax is quad-shuffle only (no smem red).
// kr window = 3 aligned 64-row panels, mod-3 absolute ring:
//   slab(m) = ((m>>6)%3)*64 + (m&63).
// Per-warp band G (16x80 fp32, stride 84):
//   mw0 = j0-i0+496-wm*16 ; row il', col c reads g = c-il'+16 in [1,79].
// smem u32: ks 2304, kr 6912, vs 2304, Ps 4608, Gw 10752, ub 64, tb 192
//   = 27,136 u32 = 108,544 B -> 2 blocks/SM.
// ---------------------------------------------------------------------------
#define ATT_SMEM_BYTES (27136 * 4)

__global__ __launch_bounds__(256, 2) void attn_kernel()
{
    extern __shared__ unsigned smu[];
    unsigned* ksu = smu;                        // 64 x 36
    unsigned* kru = smu + 2304;                 // 192 x 36 (3-panel ring)
    unsigned* vsu = smu + 9216;                 // 64 x 36
    unsigned* Psu = smu + 11520;                // 8 x [16 x 36]
    float* Gw  = (float*)(smu + 16128);         // 8 x [16 x 84]
    float* ub  = (float*)(smu + 26880);         // 64
    float* tb2 = (float*)(smu + 26944);         // 192 (ring)
    const __nv_bfloat16* vsb = (const __nv_bfloat16*)vsu;  // row stride 72 bf16

    const int b = blockIdx.x >> 4, n = blockIdx.x & 15;
    const int i0 = blockIdx.y * 128;
    const int tid = threadIdx.x;
    const int wm = tid >> 5, lane = tid & 31;
    const int grp = lane >> 2, thr = lane & 3;
    const int r0 = wm * 16 + grp;               // local rows r0, r0+8

    float* Gwp = Gw + wm * (16 * 84);
    unsigned* Pwp = Psu + wm * (16 * 36);

    // ---- q fragments straight from global bf16 ----
    unsigned qa[4][4];
    {
#pragma unroll
        for (int kc = 0; kc < 4; kc++) {
            size_t b0 = ((size_t)(i0 + r0) * 4 + b) * 512 + n * 32 + kc * 8;
            size_t b1 = ((size_t)(i0 + r0 + 8) * 4 + b) * 512 + n * 32 + kc * 8;
            qa[kc][0] = g_qb_u[b0 + thr];
            qa[kc][1] = g_qb_u[b1 + thr];
            qa[kc][2] = g_qb_u[b0 + thr + 4];
            qa[kc][3] = g_qb_u[b1 + thr + 4];
        }
    }

    float e0[2], e1[2];
    e0[0] = g_e[((size_t)(i0 + r0) * 4 + b) * 16 + n];
    e0[1] = g_e[((size_t)(i0 + r0 + 8) * 4 + b) * 16 + n];
    e1[0] = g_e[((size_t)(512 + i0 + r0) * 4 + b) * 16 + n];
    e1[1] = g_e[((size_t)(512 + i0 + r0 + 8) * 4 + b) * 16 + n];

    float oacc[8][4];
#pragma unroll
    for (int nt = 0; nt < 8; nt++)
#pragma unroll
        for (int q = 0; q < 4; q++) oacc[nt][q] = 0.f;
    float rmax[2] = {-3.0e38f, -3.0e38f};
    float rsum[2] = {0.f, 0.f};

    const unsigned char* codeRow0 = g_code + ((size_t)b << 19) + (size_t)(i0 + r0) * 1024;
    const unsigned char* codeRow1 = codeRow0 + 8 * 1024;

    for (int j0 = 0; j0 < KLEN; j0 += 64) {
        __syncthreads();                         // prior reads done; safe to overwrite
        const int base = j0 - i0 + 384;          // 64-aligned window start
        // ---- async tile loads ----
        for (int t = tid; t < 512; t += 256) {
            int row = t >> 3, c = (t & 7) * 4;
            size_t goff = ((size_t)(j0 + row) * 4 + b) * 512 + n * 32 + c;
            cpa16(&ksu[row * 36 + c], g_kb_u + goff);
            cpa16(&vsu[row * 36 + c], g_vb_u + goff);
        }
        const int startrow = (j0 == 0) ? 0 : 128;
        const int nload = 192 - startrow;
        for (int t = tid; t < nload * 8; t += 256) {
            int roff = startrow + (t >> 3), c = (t & 7) * 4;
            int mabs = base + roff;
            int slab = ((mabs >> 6) % 3) * 64 + (mabs & 63);
            cpa16(&kru[slab * 36 + c],
                  g_krb_u + ((size_t)mabs * 4 + b) * 512 + n * 32 + c);
        }
        CP_COMMIT();
        // ---- scalar ub/tb loads ----
        if (tid < 64) {
            ub[tid] = g_u[((size_t)(j0 + tid) * 4 + b) * 16 + n];
        } else if (tid < 64 + nload) {
            int mabs = base + startrow + (tid - 64);
            int slab = ((mabs >> 6) % 3) * 64 + (mabs & 63);
            tb2[slab] = g_t[((size_t)mabs * 4 + b) * 16 + n];
        }
        CP_WAIT0();
        __syncthreads();                         // tiles + ub/tb ready

        // ---- S = q @ k^T (full 64 cols per warp) ----
        float sacc[8][4];
#pragma unroll
        for (int nt = 0; nt < 8; nt++)
#pragma unroll
            for (int q = 0; q < 4; q++) sacc[nt][q] = 0.f;
#pragma unroll
        for (int kc = 0; kc < 4; kc++) {
#pragma unroll
            for (int nt = 0; nt < 8; nt++) {
                int jc = nt * 8 + grp;
                mma_bf16(sacc[nt], qa[kc],
                         ksu[jc * 36 + kc * 8 + thr],
                         ksu[jc * 36 + kc * 8 + thr + 4]);
            }
        }

        // ---- per-warp band G (16 x 80), +tb folded at store ----
        const int mw0 = j0 - i0 + 496 - wm * 16;
#pragma unroll
        for (int nt = 0; nt < 10; nt++) {
            float gacc[4] = {0.f, 0.f, 0.f, 0.f};
            int mb = mw0 + nt * 8 + grp;
            int srow = ((mb >> 6) % 3) * 64 + (mb & 63);
#pragma unroll
            for (int kc = 0; kc < 4; kc++)
                mma_bf16(gacc, qa[kc],
                         kru[srow * 36 + kc * 8 + thr],
                         kru[srow * 36 + kc * 8 + thr + 4]);
            int g0 = nt * 8 + 2 * thr;
            int ms = mw0 + g0;
            int sl0 = ((ms >> 6) % 3) * 64 + (ms & 63);
            int sl1 = (((ms + 1) >> 6) % 3) * 64 + ((ms + 1) & 63);
            float t0 = tb2[sl0], t1 = tb2[sl1];
            Gwp[grp * 84 + g0]           = gacc[0] + t0;
            Gwp[grp * 84 + g0 + 1]       = gacc[1] + t1;
            Gwp[(grp + 8) * 84 + g0]     = gacc[2] + t0;
            Gwp[(grp + 8) * 84 + g0 + 1] = gacc[3] + t1;
        }
        __syncwarp();

        // ---- assemble logits, warp-local row maxes ----
        float mx0 = -3.0e38f, mx1 = -3.0e38f;
#pragma unroll
        for (int nt = 0; nt < 8; nt++) {
            int c = nt * 8 + 2 * thr;
            unsigned char cc00 = codeRow0[j0 + c], cc01 = codeRow0[j0 + c + 1];
            unsigned char cc10 = codeRow1[j0 + c], cc11 = codeRow1[j0 + c + 1];
            float u0 = ub[c], u1 = ub[c + 1];
            float v;
            v = (sacc[nt][0] + Gwp[grp * 84 + c - grp + 16] + u0 + ((cc00 & 1) ? e1[0] : e0[0])) * SCALE;
            if (cc00 & 2) v -= 1e30f;
            sacc[nt][0] = v; mx0 = fmaxf(mx0, v);
            v = (sacc[nt][1] + Gwp[grp * 84 + c + 1 - grp + 16] + u1 + ((cc01 & 1) ? e1[0] : e0[0])) * SCALE;
            if (cc01 & 2) v -= 1e30f;
            sacc[nt][1] = v; mx0 = fmaxf(mx0, v);
            v = (sacc[nt][2] + Gwp[(grp + 8) * 84 + c - grp + 8] + u0 + ((cc10 & 1) ? e1[1] : e0[1])) * SCALE;
            if (cc10 & 2) v -= 1e30f;
            sacc[nt][2] = v; mx1 = fmaxf(mx1, v);
            v = (sacc[nt][3] + Gwp[(grp + 8) * 84 + c + 1 - grp + 8] + u1 + ((cc11 & 1) ? e1[1] : e0[1])) * SCALE;
            if (cc11 & 2) v -= 1e30f;
            sacc[nt][3] = v; mx1 = fmaxf(mx1, v);
        }
#pragma unroll
        for (int o = 1; o < 4; o <<= 1) {
            mx0 = fmaxf(mx0, __shfl_xor_sync(0xffffffffu, mx0, o));
            mx1 = fmaxf(mx1, __shfl_xor_sync(0xffffffffu, mx1, o));
        }
        float nm0 = fmaxf(rmax[0], mx0);
        float nm1 = fmaxf(rmax[1], mx1);
        float corr0 = __expf(rmax[0] - nm0);
        float corr1 = __expf(rmax[1] - nm1);
        rmax[0] = nm0; rmax[1] = nm1;

        float sum0 = 0.f, sum1 = 0.f;
#pragma unroll
        for (int nt = 0; nt < 8; nt++) {
            float p0 = __expf(sacc[nt][0] - nm0);
            float p1 = __expf(sacc[nt][1] - nm0);
            float p2 = __expf(sacc[nt][2] - nm1);
            float p3 = __expf(sacc[nt][3] - nm1);
            sum0 += p0 + p1; sum1 += p2 + p3;
            Pwp[grp * 36 + nt * 4 + thr] = pk2(p0, p1);
            Pwp[(grp + 8) * 36 + nt * 4 + thr] = pk2(p2, p3);
        }
#pragma unroll
        for (int o = 1; o < 4; o <<= 1) {
            sum0 += __shfl_xor_sync(0xffffffffu, sum0, o);
            sum1 += __shfl_xor_sync(0xffffffffu, sum1, o);
        }
        rsum[0] = rsum[0] * corr0 + sum0;
        rsum[1] = rsum[1] * corr1 + sum1;
        __syncwarp();

        // ---- O = O*corr + P @ V ----
#pragma unroll
        for (int nt = 0; nt < 8; nt++) {
            oacc[nt][0] *= corr0; oacc[nt][1] *= corr0;
            oacc[nt][2] *= corr1; oacc[nt][3] *= corr1;
        }
#pragma unroll
        for (int kc = 0; kc < 4; kc++) {
            unsigned a[4];
            a[0] = Pwp[grp * 36 + kc * 8 + thr];
            a[1] = Pwp[(grp + 8) * 36 + kc * 8 + thr];
            a[2] = Pwp[grp * 36 + kc * 8 + thr + 4];
            a[3] = Pwp[(grp + 8) * 36 + kc * 8 + thr + 4];
#pragma unroll
            for (int nt = 0; nt < 8; nt++) {
                unsigned b0, b1;
                ldsm_x2_t(b0, b1, vsb + (kc * 16 + (lane & 15)) * 72 + nt * 8);
                mma_bf16(oacc[nt], a, b0, b1);
            }
        }
    }

    // ---- write normalized output (bf16) ----
    float inv0 = 1.f / rsum[0];
    float inv1 = 1.f / rsum[1];
#pragma unroll
    for (int nt = 0; nt < 8; nt++) {
        int d2 = n * 32 + nt * 4 + thr;
        g_avb_u[((size_t)(i0 + r0) * 4 + b) * 512 + d2] =
            pk2(oacc[nt][0] * inv0, oacc[nt][1] * inv0);
        g_avb_u[((size_t)(i0 + r0 + 8) * 4 + b) * 512 + d2] =
            pk2(oacc[nt][2] * inv1, oacc[nt][3] * inv1);
    }
}

// ---------------------------------------------------------------------------
// Residual + LayerNorm (single pass: sum + sumsq)
// ---------------------------------------------------------------------------
__global__ __launch_bounds__(256) void ln_kernel(
    const float* __restrict__ hres, const float* __restrict__ gamma,
    const float* __restrict__ beta, float* __restrict__ out)
{
    __shared__ float xb[1024];
    __shared__ float red1[8], red2[8];
    const int row = blockIdx.x;
    const int tid = threadIdx.x;
    const float* ao = g_ao + (size_t)row * 1024;
    const float* hh = hres + (size_t)row * 1024;

    float s = 0.f, s2 = 0.f;
    for (int c = tid; c < 1024; c += 256) {
        float x = ao[c] + hh[c];
        xb[c] = x;
        s += x;
        s2 += x * x;
    }
#pragma unroll
    for (int o = 16; o; o >>= 1) {
        s += __shfl_xor_sync(0xffffffffu, s, o);
        s2 += __shfl_xor_sync(0xffffffffu, s2, o);
    }
    if ((tid & 31) == 0) { red1[tid >> 5] = s; red2[tid >> 5] = s2; }
    __syncthreads();
    float tot = 0.f, tot2 = 0.f;
#pragma unroll
    for (int k = 0; k < 8; k++) { tot += red1[k]; tot2 += red2[k]; }
    const float mean = tot * (1.f / 1024.f);
    const float var = tot2 * (1.f / 1024.f) - mean * mean;
    const float inv = rsqrtf(var + LN_EPS);

    for (int c = tid; c < 1024; c += 256)
        out[(size_t)row * 1024 + c] = (xb[c] - mean) * inv * gamma[c] + beta[c];
}

// ---------------------------------------------------------------------------
extern "C" void kernel_launch(void* const* d_in, const int* in_sizes, int n_in,
                              void* d_out, int out_size)
{
    const float* rwb       = (const float*)d_in[0];
    const float* rsb       = (const float*)d_in[1];
    const float* rrb       = (const float*)d_in[2];
    const float* seg_embed = (const float*)d_in[3];
    const float* h         = (const float*)d_in[4];
    const float* r         = (const float*)d_in[5];
    const float* mems      = (const float*)d_in[6];
    const float* seg_mat   = (const float*)d_in[7];
    const float* attn_mask = (const float*)d_in[8];
    const float* wq        = (const float*)d_in[9];
    const float* wk        = (const float*)d_in[10];
    const float* wv        = (const float*)d_in[11];
    const float* wr        = (const float*)d_in[12];
    const float* wo        = (const float*)d_in[13];
    const float* gamma     = (const float*)d_in[14];
    const float* beta      = (const float*)d_in[15];

    cudaFuncSetAttribute(attn_kernel, cudaFuncAttributeMaxDynamicSharedMemorySize, ATT_SMEM_BYTES);
    cudaFuncSetAttribute(proj_mma, cudaFuncAttributeMaxDynamicSharedMemorySize, PROJ_SMEM);
    cudaFuncSetAttribute(out_mma, cudaFuncAttributeMaxDynamicSharedMemorySize, OUT_SMEM);

    conv_cast<<<22528, 256>>>(mems, h, r, wo);
    conv_pack<<<8192, 256>>>(wq, wk, wv, wr);
    proj_mma<<<dim3(8, 128), 256, PROJ_SMEM>>>();
    e_kernel<<<2048, 512>>>(rsb, seg_embed);
    ut_kernel<<<10240, 512>>>(rwb, rrb);
    code_kernel<<<8192, 256>>>(seg_mat, attn_mask);
    attn_kernel<<<dim3(64, 4), 256, ATT_SMEM_BYTES>>>();
    out_mma<<<dim3(8, 16), 256, OUT_SMEM>>>();
    ln_kernel<<<2048, 256>>>(h, gamma, beta, (float*)d_out);
}

// round 9
// speedup vs baseline: 5.1543x; 1.0798x over previous
#include <cuda_runtime.h>
#include <cuda_bf16.h>
#include <math.h>

// Problem constants
#define QLEN 512
#define MLEN 512
#define KLEN 1024
#define RLEN 1536
#define BATCH 4
#define DM 1024
#define NH 16
#define DH 64
#define SCALE 0.125f
#define LN_EPS 1e-3f

// Scratch (device globals).  "_u" arrays hold packed bf16 pairs.
__device__ unsigned g_ab_u [10240 * 512];  // [mems(2048); h(2048); r(6144)]
__device__ unsigned g_wpk_u[4 * 512 * 1024]; // proj weights [w][k2][n]
__device__ unsigned g_wob_u[1024 * 512];   // wo bf16 [h][1024]
__device__ unsigned g_qb_u [2048 * 512];   // q_head bf16
__device__ unsigned g_kb_u [4096 * 512];   // k_head bf16
__device__ unsigned g_vb_u [4096 * 512];   // v_head bf16
__device__ unsigned g_krb_u[6144 * 512];   // k_r bf16
__device__ unsigned g_avb_u[2048 * 512];   // attn_vec bf16
__device__ float g_e [2 * 512 * 4 * 16];   // ef [s][i][b][n]
__device__ float g_u [4096 * 16];          // rwb·k
__device__ float g_t [6144 * 16];          // rrb·kr
__device__ unsigned char g_code[4 * 512 * 1024]; // [b][i][j]
__device__ float g_ao[2048 * 1024];        // attn_out (pre-LN, fp32)

// ---------------------------------------------------------------------------
// helpers
// ---------------------------------------------------------------------------
__device__ __forceinline__ unsigned pk2(float lo, float hi) {
    unsigned r;
    asm("cvt.rn.bf16x2.f32 %0, %1, %2;" : "=r"(r) : "f"(hi), "f"(lo));
    return r;
}

__device__ __forceinline__ void mma_bf16(float* d, const unsigned* a,
                                         unsigned b0, unsigned b1) {
    asm volatile(
        "mma.sync.aligned.m16n8k16.row.col.f32.bf16.bf16.f32 "
        "{%0,%1,%2,%3}, {%4,%5,%6,%7}, {%8,%9}, {%0,%1,%2,%3};\n"
        : "+f"(d[0]), "+f"(d[1]), "+f"(d[2]), "+f"(d[3])
        : "r"(a[0]), "r"(a[1]), "r"(a[2]), "r"(a[3]), "r"(b0), "r"(b1));
}

__device__ __forceinline__ void cpa16(void* dst, const void* src) {
    unsigned d = (unsigned)__cvta_generic_to_shared(dst);
    asm volatile("cp.async.cg.shared.global [%0], [%1], 16;\n" :: "r"(d), "l"(src));
}
#define CP_COMMIT() asm volatile("cp.async.commit_group;\n")
#define CP_WAIT0()  asm volatile("cp.async.wait_group 0;\n")
#define CP_WAIT2()  asm volatile("cp.async.wait_group 2;\n")

__device__ __forceinline__ void ldsm_x4(unsigned& r0, unsigned& r1,
                                        unsigned& r2, unsigned& r3, const void* p) {
    unsigned a = (unsigned)__cvta_generic_to_shared(p);
    asm volatile("ldmatrix.sync.aligned.m8n8.x4.shared.b16 {%0,%1,%2,%3}, [%4];"
                 : "=r"(r0), "=r"(r1), "=r"(r2), "=r"(r3) : "r"(a));
}
__device__ __forceinline__ void ldsm_x4_t(unsigned& r0, unsigned& r1,
                                          unsigned& r2, unsigned& r3, const void* p) {
    unsigned a = (unsigned)__cvta_generic_to_shared(p);
    asm volatile("ldmatrix.sync.aligned.m8n8.x4.trans.shared.b16 {%0,%1,%2,%3}, [%4];"
                 : "=r"(r0), "=r"(r1), "=r"(r2), "=r"(r3) : "r"(a));
}

// ---------------------------------------------------------------------------
// prep: fp32->bf16 casts, weight k-pair packing, code bytes. One launch.
// bid [0,22528): cast ; [22528,30720): pack ; [30720,38912): code
// ---------------------------------------------------------------------------
__global__ __launch_bounds__(256) void prep_kernel(
    const float* __restrict__ mems, const float* __restrict__ h,
    const float* __restrict__ r, const float* __restrict__ wo,
    const float* __restrict__ wq, const float* __restrict__ wk,
    const float* __restrict__ wv, const float* __restrict__ wr,
    const float* __restrict__ seg_mat, const float* __restrict__ attn_mask)
{
    int bid = blockIdx.x;
    if (bid < 22528) {
        int idx = bid * 256 + threadIdx.x;      // < 11264*512
        int row = idx >> 9, p = idx & 511;
        const float* src;
        unsigned* dst;
        if (row < 2048)      { src = mems + (size_t)row * 1024;          dst = g_ab_u + (size_t)row * 512; }
        else if (row < 4096) { src = h + (size_t)(row - 2048) * 1024;    dst = g_ab_u + (size_t)row * 512; }
        else if (row < 10240){ src = r + (size_t)(row - 4096) * 1024;    dst = g_ab_u + (size_t)row * 512; }
        else                 { src = wo + (size_t)(row - 10240) * 1024;  dst = g_wob_u + (size_t)(row - 10240) * 512; }
        float2 v = *(const float2*)(src + p * 2);
        dst[p] = pk2(v.x, v.y);
    } else if (bid < 30720) {
        int idx = (bid - 22528) * 256 + threadIdx.x;   // < 4*512*1024
        int w = idx >> 19;
        int rem = idx & ((1 << 19) - 1);
        int k2 = rem >> 10, nn = rem & 1023;
        const float* W = (w == 0) ? wq : (w == 1) ? wk : (w == 2) ? wv : wr;
        float a = W[(size_t)(2 * k2) * 1024 + nn];
        float bq = W[(size_t)(2 * k2 + 1) * 1024 + nn];
        g_wpk_u[(size_t)w * 524288 + rem] = pk2(a, bq);
    } else {
        int idx = (bid - 30720) * 256 + threadIdx.x;   // < 512*1024*4
        int b = idx & 3;
        int ij = idx >> 2;
        unsigned char c = (seg_mat[(size_t)idx * 2 + 1] != 0.f) ? 1 : 0;
        if (attn_mask[idx] != 0.f) c |= 2;
        g_code[((size_t)b << 19) + ij] = c;
    }
}

// ---------------------------------------------------------------------------
// Projection GEMM (bf16 m16n8k16, cp.async 4-stage, 1 barrier/iter).
// ---------------------------------------------------------------------------
#define PSTG 4
#define PJA 3072
#define PJB 2112
#define PROJ_SMEM ((PSTG * (PJA + PJB)) * 4)   // 82,944 B

__global__ __launch_bounds__(256, 2) void proj_mma()
{
    extern __shared__ unsigned psm[];
    unsigned* Asm = psm;
    unsigned* Bsm = psm + PSTG * PJA;

    const int rowbase = blockIdx.y * 128;
    const int colbase = blockIdx.x * 128;

    int abase, wsel, segbase;
    unsigned* Cu;
    if (rowbase < 2048)        { wsel = 0; segbase = 0;     abase = 2048; Cu = g_qb_u;  }
    else if (rowbase < 6144)   { wsel = 1; segbase = 2048;  abase = 0;    Cu = g_kb_u;  }
    else if (rowbase < 10240)  { wsel = 2; segbase = 6144;  abase = 0;    Cu = g_vb_u;  }
    else                       { wsel = 3; segbase = 10240; abase = 4096; Cu = g_krb_u; }
    const int crb = rowbase - segbase;

    const int tid = threadIdx.x;
    const int lane = tid & 31, warp = tid >> 5;
    const int wm = warp & 3, wn = warp >> 2;
    const int grp = lane >> 2, thr = lane & 3;

    const int arw = tid >> 1;
    const int asub = tid & 1;
    const unsigned* asrc = g_ab_u + (size_t)(abase + crb + arw) * 512 + asub * 8;
    const unsigned* wsrc = g_wpk_u + (size_t)wsel * 524288 + colbase;

    float acc[2][8][4];
#pragma unroll
    for (int mf = 0; mf < 2; mf++)
#pragma unroll
        for (int nf = 0; nf < 8; nf++)
#pragma unroll
            for (int q = 0; q < 4; q++) acc[mf][nf][q] = 0.f;

#define PROJ_ISSUE(it)                                                          \
    {                                                                           \
        int s_ = (it) & 3;                                                      \
        int k2base_ = (it) * 16;                                                \
        unsigned* ad = Asm + s_ * PJA + asub * 1536 + arw * 12;                 \
        cpa16(ad,     asrc + k2base_);                                          \
        cpa16(ad + 4, asrc + k2base_ + 4);                                      \
        for (int t_ = tid; t_ < 512; t_ += 256) {                               \
            int brow_ = t_ >> 5;                                                \
            int bc_ = (t_ & 31) * 4;                                            \
            cpa16(Bsm + s_ * PJB + brow_ * 132 + bc_,                           \
                  wsrc + (size_t)(k2base_ + brow_) * 1024 + bc_);               \
        }                                                                       \
        CP_COMMIT();                                                            \
    }

    PROJ_ISSUE(0);
    PROJ_ISSUE(1);
    PROJ_ISSUE(2);

    for (int it = 0; it < 32; it++) {
        if (it >= 30) { CP_WAIT0(); } else { CP_WAIT2(); }
        __syncthreads();
        if (it + 3 < 32) PROJ_ISSUE(it + 3);
        const unsigned* Ast = Asm + (it & 3) * PJA;
        const unsigned* Bst = Bsm + (it & 3) * PJB;
#pragma unroll
        for (int s = 0; s < 2; s++) {
            const unsigned* As_ = Ast + s * 1536;
            const unsigned* Bs_ = Bst + s * 1056;
            unsigned a[2][4], bb[8][2];
#pragma unroll
            for (int mf = 0; mf < 2; mf++) {
                int rr = wm * 32 + mf * 16 + grp;
                a[mf][0] = As_[rr * 12 + thr];
                a[mf][1] = As_[(rr + 8) * 12 + thr];
                a[mf][2] = As_[rr * 12 + thr + 4];
                a[mf][3] = As_[(rr + 8) * 12 + thr + 4];
            }
#pragma unroll
            for (int nf = 0; nf < 8; nf++) {
                int cc = wn * 64 + nf * 8 + grp;
                bb[nf][0] = Bs_[thr * 132 + cc];
                bb[nf][1] = Bs_[(thr + 4) * 132 + cc];
            }
#pragma unroll
            for (int mf = 0; mf < 2; mf++)
#pragma unroll
                for (int nf = 0; nf < 8; nf++)
                    mma_bf16(acc[mf][nf], a[mf], bb[nf][0], bb[nf][1]);
        }
    }
#pragma unroll
    for (int mf = 0; mf < 2; mf++)
#pragma unroll
        for (int nf = 0; nf < 8; nf++) {
            int rr = crb + wm * 32 + mf * 16 + grp;
            int c2 = (colbase >> 1) + wn * 32 + nf * 4 + thr;
            Cu[(size_t)rr * 512 + c2] = pk2(acc[mf][nf][0], acc[mf][nf][1]);
            Cu[(size_t)(rr + 8) * 512 + c2] = pk2(acc[mf][nf][2], acc[mf][nf][3]);
        }
#undef PROJ_ISSUE
}

// ---------------------------------------------------------------------------
// Output GEMM (bf16, 4-stage, 1 barrier/iter): g_ao = g_avb @ wob^T.
// ---------------------------------------------------------------------------
#define OJS 6144
#define OUT_SMEM ((PSTG * OJS) * 4)    // 98,304 B

__global__ __launch_bounds__(256, 2) void out_mma()
{
    extern __shared__ unsigned psm[];

    const int rowbase = blockIdx.y * 128;
    const int colbase = blockIdx.x * 128;
    const int tid = threadIdx.x;
    const int lane = tid & 31, warp = tid >> 5;
    const int wm = warp & 3, wn = warp >> 2;
    const int grp = lane >> 2, thr = lane & 3;

    float acc[2][8][4];
#pragma unroll
    for (int mf = 0; mf < 2; mf++)
#pragma unroll
        for (int nf = 0; nf < 8; nf++)
#pragma unroll
            for (int q = 0; q < 4; q++) acc[mf][nf][q] = 0.f;

#define OUT_ISSUE(it)                                                           \
    {                                                                           \
        int s_ = (it) & 3;                                                      \
        int k2base_ = (it) * 16;                                                \
        for (int t_ = tid; t_ < 512; t_ += 256) {                               \
            int row_ = (t_ & 255) >> 1;                                         \
            int sub_ = t_ & 1;                                                  \
            const unsigned* src_;                                               \
            unsigned* dst_;                                                     \
            if (t_ < 256) {                                                     \
                src_ = g_avb_u + (size_t)(rowbase + row_) * 512;                \
                dst_ = psm + s_ * OJS + sub_ * 1536 + row_ * 12;                \
            } else {                                                            \
                src_ = g_wob_u + (size_t)(colbase + row_) * 512;                \
                dst_ = psm + s_ * OJS + 3072 + sub_ * 1536 + row_ * 12;         \
            }                                                                   \
            cpa16(dst_,     src_ + k2base_ + sub_ * 8);                         \
            cpa16(dst_ + 4, src_ + k2base_ + sub_ * 8 + 4);                     \
        }                                                                       \
        CP_COMMIT();                                                            \
    }

    OUT_ISSUE(0);
    OUT_ISSUE(1);
    OUT_ISSUE(2);

    for (int it = 0; it < 32; it++) {
        if (it >= 30) { CP_WAIT0(); } else { CP_WAIT2(); }
        __syncthreads();
        if (it + 3 < 32) OUT_ISSUE(it + 3);
        const unsigned* stg = psm + (it & 3) * OJS;
#pragma unroll
        for (int s = 0; s < 2; s++) {
            const unsigned* As_ = stg + s * 1536;
            const unsigned* Bs_ = stg + 3072 + s * 1536;
            unsigned a[2][4], bb[8][2];
#pragma unroll
            for (int mf = 0; mf < 2; mf++) {
                int rr = wm * 32 + mf * 16 + grp;
                a[mf][0] = As_[rr * 12 + thr];
                a[mf][1] = As_[(rr + 8) * 12 + thr];
                a[mf][2] = As_[rr * 12 + thr + 4];
                a[mf][3] = As_[(rr + 8) * 12 + thr + 4];
            }
#pragma unroll
            for (int nf = 0; nf < 8; nf++) {
                int cc = wn * 64 + nf * 8 + grp;
                bb[nf][0] = Bs_[cc * 12 + thr];
                bb[nf][1] = Bs_[cc * 12 + thr + 4];
            }
#pragma unroll
            for (int mf = 0; mf < 2; mf++)
#pragma unroll
                for (int nf = 0; nf < 8; nf++)
                    mma_bf16(acc[mf][nf], a[mf], bb[nf][0], bb[nf][1]);
        }
    }
#pragma unroll
    for (int mf = 0; mf < 2; mf++)
#pragma unroll
        for (int nf = 0; nf < 8; nf++) {
            int rr = rowbase + wm * 32 + mf * 16 + grp;
            int cc = colbase + wn * 64 + nf * 8 + thr * 2;
            *(float2*)&g_ao[(size_t)rr * 1024 + cc] = make_float2(acc[mf][nf][0], acc[mf][nf][1]);
            *(float2*)&g_ao[(size_t)(rr + 8) * 1024 + cc] = make_float2(acc[mf][nf][2], acc[mf][nf][3]);
        }
#undef OUT_ISSUE
}

// ---------------------------------------------------------------------------
// post: ef projections (bid<2048) + u/t bias dots (bid>=2048). 512 threads.
// ---------------------------------------------------------------------------
__global__ __launch_bounds__(512) void post_kernel(
    const float* __restrict__ rsb, const float* __restrict__ seg_embed,
    const float* __restrict__ rwb, const float* __restrict__ rrb)
{
    const int n = threadIdx.x >> 5, lane = threadIdx.x & 31;
    if (blockIdx.x < 2048) {
        const int row = blockIdx.x;             // i*4+b
        const int i = row >> 2, b = row & 3;
        const __nv_bfloat16* qb = (const __nv_bfloat16*)g_qb_u;
        float q1 = __bfloat162float(qb[(size_t)row * 1024 + n * 64 + lane]) + rsb[n * 64 + lane];
        float q2 = __bfloat162float(qb[(size_t)row * 1024 + n * 64 + lane + 32]) + rsb[n * 64 + lane + 32];
        float p0 = q1 * seg_embed[(0 * 16 + n) * 64 + lane] + q2 * seg_embed[(0 * 16 + n) * 64 + lane + 32];
        float p1 = q1 * seg_embed[(1 * 16 + n) * 64 + lane] + q2 * seg_embed[(1 * 16 + n) * 64 + lane + 32];
#pragma unroll
        for (int o = 16; o; o >>= 1) {
            p0 += __shfl_xor_sync(0xffffffffu, p0, o);
            p1 += __shfl_xor_sync(0xffffffffu, p1, o);
        }
        if (lane == 0) {
            g_e[((size_t)(0 * 512 + i) * 4 + b) * 16 + n] = p0;
            g_e[((size_t)(512 + i) * 4 + b) * 16 + n] = p1;
        }
    } else {
        int row = blockIdx.x - 2048;
        const __nv_bfloat16* src;
        const float* bias;
        float* dst;
        if (row < 4096) {
            src = (const __nv_bfloat16*)g_kb_u + (size_t)row * 1024;
            bias = rwb; dst = g_u + (size_t)row * 16;
        } else {
            row -= 4096;
            src = (const __nv_bfloat16*)g_krb_u + (size_t)row * 1024;
            bias = rrb; dst = g_t + (size_t)row * 16;
        }
        float p = __bfloat162float(src[n * 64 + lane]) * bias[n * 64 + lane]
                + __bfloat162float(src[n * 64 + lane + 32]) * bias[n * 64 + lane + 32];
#pragma unroll
        for (int o = 16; o; o >>= 1) p += __shfl_xor_sync(0xffffffffu, p, o);
        if (lane == 0) dst[n] = p;
    }
}

// ---------------------------------------------------------------------------
// Fused attention, warp-local, ldmatrix fragment loads.
// smem layout identical to R8 (108,544 B -> 2 blocks/SM).
// ---------------------------------------------------------------------------
#define ATT_SMEM_BYTES (27136 * 4)

__global__ __launch_bounds__(256, 2) void attn_kernel()
{
    extern __shared__ unsigned smu[];
    unsigned* ksu = smu;                        // 64 x 36
    unsigned* kru = smu + 2304;                 // 192 x 36 (3-panel ring)
    unsigned* vsu = smu + 9216;                 // 64 x 36
    unsigned* Psu = smu + 11520;                // 8 x [16 x 36]
    float* Gw  = (float*)(smu + 16128);         // 8 x [16 x 84]
    float* ub  = (float*)(smu + 26880);         // 64
    float* tb2 = (float*)(smu + 26944);         // 192 (ring)
    const __nv_bfloat16* vsb = (const __nv_bfloat16*)vsu;  // row stride 72 bf16

    const int b = blockIdx.x >> 4, n = blockIdx.x & 15;
    const int i0 = blockIdx.y * 128;
    const int tid = threadIdx.x;
    const int wm = tid >> 5, lane = tid & 31;
    const int grp = lane >> 2, thr = lane & 3;
    const int r0 = wm * 16 + grp;               // local rows r0, r0+8

    float* Gwp = Gw + wm * (16 * 84);
    unsigned* Pwp = Psu + wm * (16 * 36);

    // ldmatrix per-lane address components
    const int row16 = (lane & 7) + ((lane & 16) >> 1);  // B-frag: 0..15
    const int koB   = (lane & 8) >> 1;                  // 0 / 4 u32
    const int rowA  = (lane & 7) + (lane & 8);          // A-frag: 0..15
    const int koA   = (lane & 16) >> 2;                 // 0 / 4 u32
    const int rowV  = lane & 15;
    const int colV8 = (lane & 16) >> 1;                 // 0 / 8 bf16

    // ---- q fragments straight from global bf16 ----
    unsigned qa[4][4];
#pragma unroll
    for (int kc = 0; kc < 4; kc++) {
        size_t b0 = ((size_t)(i0 + r0) * 4 + b) * 512 + n * 32 + kc * 8;
        size_t b1 = ((size_t)(i0 + r0 + 8) * 4 + b) * 512 + n * 32 + kc * 8;
        qa[kc][0] = g_qb_u[b0 + thr];
        qa[kc][1] = g_qb_u[b1 + thr];
        qa[kc][2] = g_qb_u[b0 + thr + 4];
        qa[kc][3] = g_qb_u[b1 + thr + 4];
    }

    float e0[2], e1[2];
    e0[0] = g_e[((size_t)(i0 + r0) * 4 + b) * 16 + n];
    e0[1] = g_e[((size_t)(i0 + r0 + 8) * 4 + b) * 16 + n];
    e1[0] = g_e[((size_t)(512 + i0 + r0) * 4 + b) * 16 + n];
    e1[1] = g_e[((size_t)(512 + i0 + r0 + 8) * 4 + b) * 16 + n];

    float oacc[8][4];
#pragma unroll
    for (int nt = 0; nt < 8; nt++)
#pragma unroll
        for (int q = 0; q < 4; q++) oacc[nt][q] = 0.f;
    float rmax[2] = {-3.0e38f, -3.0e38f};
    float rsum[2] = {0.f, 0.f};

    const unsigned char* codeRow0 = g_code + ((size_t)b << 19) + (size_t)(i0 + r0) * 1024;
    const unsigned char* codeRow1 = codeRow0 + 8 * 1024;

    for (int j0 = 0; j0 < KLEN; j0 += 64) {
        __syncthreads();
        const int base = j0 - i0 + 384;
        for (int t = tid; t < 512; t += 256) {
            int row = t >> 3, c = (t & 7) * 4;
            size_t goff = ((size_t)(j0 + row) * 4 + b) * 512 + n * 32 + c;
            cpa16(&ksu[row * 36 + c], g_kb_u + goff);
            cpa16(&vsu[row * 36 + c], g_vb_u + goff);
        }
        const int startrow = (j0 == 0) ? 0 : 128;
        const int nload = 192 - startrow;
        for (int t = tid; t < nload * 8; t += 256) {
            int roff = startrow + (t >> 3), c = (t & 7) * 4;
            int mabs = base + roff;
            int slab = ((mabs >> 6) % 3) * 64 + (mabs & 63);
            cpa16(&kru[slab * 36 + c],
                  g_krb_u + ((size_t)mabs * 4 + b) * 512 + n * 32 + c);
        }
        CP_COMMIT();
        if (tid < 64) {
            ub[tid] = g_u[((size_t)(j0 + tid) * 4 + b) * 16 + n];
        } else if (tid < 64 + nload) {
            int mabs = base + startrow + (tid - 64);
            int slab = ((mabs >> 6) % 3) * 64 + (mabs & 63);
            tb2[slab] = g_t[((size_t)mabs * 4 + b) * 16 + n];
        }
        CP_WAIT0();
        __syncthreads();

        // ---- S = q @ k^T (ldmatrix.x4 B-frags) ----
        float sacc[8][4];
#pragma unroll
        for (int nt = 0; nt < 8; nt++)
#pragma unroll
            for (int q = 0; q < 4; q++) sacc[nt][q] = 0.f;
#pragma unroll
        for (int kc = 0; kc < 4; kc++) {
#pragma unroll
            for (int p = 0; p < 4; p++) {
                unsigned k0, k1, k2, k3;
                ldsm_x4(k0, k1, k2, k3, &ksu[(16 * p + row16) * 36 + kc * 8 + koB]);
                mma_bf16(sacc[2 * p], qa[kc], k0, k1);
                mma_bf16(sacc[2 * p + 1], qa[kc], k2, k3);
            }
        }

        // ---- per-warp band G (16 x 80), ldmatrix frags, +tb at store ----
        const int mw0 = j0 - i0 + 496 - wm * 16;
#pragma unroll
        for (int p = 0; p < 5; p++) {
            int mbL = mw0 + 16 * p + row16;
            int srow = ((mbL >> 6) % 3) * 64 + (mbL & 63);
            float ga[4] = {0.f, 0.f, 0.f, 0.f};
            float gb[4] = {0.f, 0.f, 0.f, 0.f};
#pragma unroll
            for (int kc = 0; kc < 4; kc++) {
                unsigned k0, k1, k2, k3;
                ldsm_x4(k0, k1, k2, k3, &kru[srow * 36 + kc * 8 + koB]);
                mma_bf16(ga, qa[kc], k0, k1);
                mma_bf16(gb, qa[kc], k2, k3);
            }
            int g0 = 16 * p + 2 * thr;
            int msA = mw0 + g0;
            int msB = msA + 8;
            int slA0 = ((msA >> 6) % 3) * 64 + (msA & 63);
            int slA1 = (((msA + 1) >> 6) % 3) * 64 + ((msA + 1) & 63);
            int slB0 = ((msB >> 6) % 3) * 64 + (msB & 63);
            int slB1 = (((msB + 1) >> 6) % 3) * 64 + ((msB + 1) & 63);
            float tA0 = tb2[slA0], tA1 = tb2[slA1];
            float tB0 = tb2[slB0], tB1 = tb2[slB1];
            Gwp[grp * 84 + g0]               = ga[0] + tA0;
            Gwp[grp * 84 + g0 + 1]           = ga[1] + tA1;
            Gwp[(grp + 8) * 84 + g0]         = ga[2] + tA0;
            Gwp[(grp + 8) * 84 + g0 + 1]     = ga[3] + tA1;
            Gwp[grp * 84 + g0 + 8]           = gb[0] + tB0;
            Gwp[grp * 84 + g0 + 9]           = gb[1] + tB1;
            Gwp[(grp + 8) * 84 + g0 + 8]     = gb[2] + tB0;
            Gwp[(grp + 8) * 84 + g0 + 9]     = gb[3] + tB1;
        }
        __syncwarp();

        // ---- assemble logits, warp-local row maxes ----
        float mx0 = -3.0e38f, mx1 = -3.0e38f;
#pragma unroll
        for (int nt = 0; nt < 8; nt++) {
            int c = nt * 8 + 2 * thr;
            unsigned short w0 = *(const unsigned short*)(codeRow0 + j0 + c);
            unsigned short w1 = *(const unsigned short*)(codeRow1 + j0 + c);
            unsigned char cc00 = (unsigned char)w0, cc01 = (unsigned char)(w0 >> 8);
            unsigned char cc10 = (unsigned char)w1, cc11 = (unsigned char)(w1 >> 8);
            float u0 = ub[c], u1 = ub[c + 1];
            float v;
            v = (sacc[nt][0] + Gwp[grp * 84 + c - grp + 16] + u0 + ((cc00 & 1) ? e1[0] : e0[0])) * SCALE;
            if (cc00 & 2) v -= 1e30f;
            sacc[nt][0] = v; mx0 = fmaxf(mx0, v);
            v = (sacc[nt][1] + Gwp[grp * 84 + c + 1 - grp + 16] + u1 + ((cc01 & 1) ? e1[0] : e0[0])) * SCALE;
            if (cc01 & 2) v -= 1e30f;
            sacc[nt][1] = v; mx0 = fmaxf(mx0, v);
            v = (sacc[nt][2] + Gwp[(grp + 8) * 84 + c - grp + 8] + u0 + ((cc10 & 1) ? e1[1] : e0[1])) * SCALE;
            if (cc10 & 2) v -= 1e30f;
            sacc[nt][2] = v; mx1 = fmaxf(mx1, v);
            v = (sacc[nt][3] + Gwp[(grp + 8) * 84 + c + 1 - grp + 8] + u1 + ((cc11 & 1) ? e1[1] : e0[1])) * SCALE;
            if (cc11 & 2) v -= 1e30f;
            sacc[nt][3] = v; mx1 = fmaxf(mx1, v);
        }
#pragma unroll
        for (int o = 1; o < 4; o <<= 1) {
            mx0 = fmaxf(mx0, __shfl_xor_sync(0xffffffffu, mx0, o));
            mx1 = fmaxf(mx1, __shfl_xor_sync(0xffffffffu, mx1, o));
        }
        float nm0 = fmaxf(rmax[0], mx0);
        float nm1 = fmaxf(rmax[1], mx1);
        float corr0 = __expf(rmax[0] - nm0);
        float corr1 = __expf(rmax[1] - nm1);
        rmax[0] = nm0; rmax[1] = nm1;

        float sum0 = 0.f, sum1 = 0.f;
#pragma unroll
        for (int nt = 0; nt < 8; nt++) {
            float p0 = __expf(sacc[nt][0] - nm0);
            float p1 = __expf(sacc[nt][1] - nm0);
            float p2 = __expf(sacc[nt][2] - nm1);
            float p3 = __expf(sacc[nt][3] - nm1);
            sum0 += p0 + p1; sum1 += p2 + p3;
            Pwp[grp * 36 + nt * 4 + thr] = pk2(p0, p1);
            Pwp[(grp + 8) * 36 + nt * 4 + thr] = pk2(p2, p3);
        }
#pragma unroll
        for (int o = 1; o < 4; o <<= 1) {
            sum0 += __shfl_xor_sync(0xffffffffu, sum0, o);
            sum1 += __shfl_xor_sync(0xffffffffu, sum1, o);
        }
        rsum[0] = rsum[0] * corr0 + sum0;
        rsum[1] = rsum[1] * corr1 + sum1;
        __syncwarp();

        // ---- O = O*corr + P @ V (ldmatrix A + trans-V frags) ----
#pragma unroll
        for (int nt = 0; nt < 8; nt++) {
            oacc[nt][0] *= corr0; oacc[nt][1] *= corr0;
            oacc[nt][2] *= corr1; oacc[nt][3] *= corr1;
        }
#pragma unroll
        for (int kc = 0; kc < 4; kc++) {
            unsigned a[4];
            ldsm_x4(a[0], a[1], a[2], a[3], &Pwp[rowA * 36 + kc * 8 + koA]);
#pragma unroll
            for (int p = 0; p < 4; p++) {
                unsigned v0, v1, v2, v3;
                ldsm_x4_t(v0, v1, v2, v3,
                          vsb + (kc * 16 + rowV) * 72 + p * 16 + colV8);
                mma_bf16(oacc[2 * p], a, v0, v1);
                mma_bf16(oacc[2 * p + 1], a, v2, v3);
            }
        }
    }

    // ---- write normalized output (bf16) ----
    float inv0 = 1.f / rsum[0];
    float inv1 = 1.f / rsum[1];
#pragma unroll
    for (int nt = 0; nt < 8; nt++) {
        int d2 = n * 32 + nt * 4 + thr;
        g_avb_u[((size_t)(i0 + r0) * 4 + b) * 512 + d2] =
            pk2(oacc[nt][0] * inv0, oacc[nt][1] * inv0);
        g_avb_u[((size_t)(i0 + r0 + 8) * 4 + b) * 512 + d2] =
            pk2(oacc[nt][2] * inv1, oacc[nt][3] * inv1);
    }
}

// ---------------------------------------------------------------------------
// Residual + LayerNorm (single pass)
// ---------------------------------------------------------------------------
__global__ __launch_bounds__(256) void ln_kernel(
    const float* __restrict__ hres, const float* __restrict__ gamma,
    const float* __restrict__ beta, float* __restrict__ out)
{
    __shared__ float xb[1024];
    __shared__ float red1[8], red2[8];
    const int row = blockIdx.x;
    const int tid = threadIdx.x;
    const float* ao = g_ao + (size_t)row * 1024;
    const float* hh = hres + (size_t)row * 1024;

    float s = 0.f, s2 = 0.f;
    for (int c = tid; c < 1024; c += 256) {
        float x = ao[c] + hh[c];
        xb[c] = x;
        s += x;
        s2 += x * x;
    }
#pragma unroll
    for (int o = 16; o; o >>= 1) {
        s += __shfl_xor_sync(0xffffffffu, s, o);
        s2 += __shfl_xor_sync(0xffffffffu, s2, o);
    }
    if ((tid & 31) == 0) { red1[tid >> 5] = s; red2[tid >> 5] = s2; }
    __syncthreads();
    float tot = 0.f, tot2 = 0.f;
#pragma unroll
    for (int k = 0; k < 8; k++) { tot += red1[k]; tot2 += red2[k]; }
    const float mean = tot * (1.f / 1024.f);
    const float var = tot2 * (1.f / 1024.f) - mean * mean;
    const float inv = rsqrtf(var + LN_EPS);

    for (int c = tid; c < 1024; c += 256)
        out[(size_t)row * 1024 + c] = (xb[c] - mean) * inv * gamma[c] + beta[c];
}

// ---------------------------------------------------------------------------
extern "C" void kernel_launch(void* const* d_in, const int* in_sizes, int n_in,
                              void* d_out, int out_size)
{
    const float* rwb       = (const float*)d_in[0];
    const float* rsb       = (const float*)d_in[1];
    const float* rrb       = (const float*)d_in[2];
    const float* seg_embed = (const float*)d_in[3];
    const float* h         = (const float*)d_in[4];
    const float* r         = (const float*)d_in[5];
    const float* mems      = (const float*)d_in[6];
    const float* seg_mat   = (const float*)d_in[7];
    const float* attn_mask = (const float*)d_in[8];
    const float* wq        = (const float*)d_in[9];
    const float* wk        = (const float*)d_in[10];
    const float* wv        = (const float*)d_in[11];
    const float* wr        = (const float*)d_in[12];
    const float* wo        = (const float*)d_in[13];
    const float* gamma     = (const float*)d_in[14];
    const float* beta      = (const float*)d_in[15];

    cudaFuncSetAttribute(attn_kernel, cudaFuncAttributeMaxDynamicSharedMemorySize, ATT_SMEM_BYTES);
    cudaFuncSetAttribute(proj_mma, cudaFuncAttributeMaxDynamicSharedMemorySize, PROJ_SMEM);
    cudaFuncSetAttribute(out_mma, cudaFuncAttributeMaxDynamicSharedMemorySize, OUT_SMEM);

    prep_kernel<<<38912, 256>>>(mems, h, r, wo, wq, wk, wv, wr, seg_mat, attn_mask);
    proj_mma<<<dim3(8, 128), 256, PROJ_SMEM>>>();
    post_kernel<<<12288, 512>>>(rsb, seg_embed, rwb, rrb);
    attn_kernel<<<dim3(64, 4), 256, ATT_SMEM_BYTES>>>();
    out_mma<<<dim3(8, 16), 256, OUT_SMEM>>>();
    ln_kernel<<<2048, 256>>>(h, gamma, beta, (float*)d_out);
}

// round 10
// speedup vs baseline: 5.2098x; 1.0108x over previous
#include <cuda_runtime.h>
#include <cuda_bf16.h>
#include <math.h>

// Problem constants
#define QLEN 512
#define MLEN 512
#define KLEN 1024
#define RLEN 1536
#define BATCH 4
#define DM 1024
#define NH 16
#define DH 64
#define SCALE 0.125f
#define LN_EPS 1e-3f

// Scratch (device globals).  "_u" arrays hold packed bf16 pairs.
__device__ unsigned g_ab_u [10240 * 512];  // [mems(2048); h(2048); r(6144)]
__device__ unsigned g_wpk_u[4 * 1024 * 512]; // proj weights [w][n][k2] (k-contig)
__device__ unsigned g_wob_u[1024 * 512];   // wo bf16 [h][1024]
__device__ unsigned g_qb_u [2048 * 512];   // q_head bf16
__device__ unsigned g_kb_u [4096 * 512];   // k_head bf16 (pre-scaled by SCALE)
__device__ unsigned g_vb_u [4096 * 512];   // v_head bf16
__device__ unsigned g_krb_u[6144 * 512];   // k_r bf16 (pre-scaled by SCALE)
__device__ unsigned g_avb_u[2048 * 512];   // attn_vec bf16
__device__ float g_e [512 * 4 * 16];       // de = SCALE*(e1-e0) [i][b][n]
__device__ float g_u [4096 * 16];          // rwb·k_scaled
__device__ float g_t [6144 * 16];          // rrb·kr_scaled
__device__ unsigned char g_code[4 * 512 * 1024]; // [b][i][j]
__device__ float g_ao[2048 * 1024];        // attn_out (pre-LN, fp32)

// ---------------------------------------------------------------------------
// helpers
// ---------------------------------------------------------------------------
__device__ __forceinline__ unsigned pk2(float lo, float hi) {
    unsigned r;
    asm("cvt.rn.bf16x2.f32 %0, %1, %2;" : "=r"(r) : "f"(hi), "f"(lo));
    return r;
}

__device__ __forceinline__ void mma_bf16(float* d, const unsigned* a,
                                         unsigned b0, unsigned b1) {
    asm volatile(
        "mma.sync.aligned.m16n8k16.row.col.f32.bf16.bf16.f32 "
        "{%0,%1,%2,%3}, {%4,%5,%6,%7}, {%8,%9}, {%0,%1,%2,%3};\n"
        : "+f"(d[0]), "+f"(d[1]), "+f"(d[2]), "+f"(d[3])
        : "r"(a[0]), "r"(a[1]), "r"(a[2]), "r"(a[3]), "r"(b0), "r"(b1));
}

__device__ __forceinline__ void cpa16(void* dst, const void* src) {
    unsigned d = (unsigned)__cvta_generic_to_shared(dst);
    asm volatile("cp.async.cg.shared.global [%0], [%1], 16;\n" :: "r"(d), "l"(src));
}
#define CP_COMMIT() asm volatile("cp.async.commit_group;\n")
#define CP_WAIT0()  asm volatile("cp.async.wait_group 0;\n")
#define CP_WAIT2()  asm volatile("cp.async.wait_group 2;\n")

__device__ __forceinline__ void ldsm_x4(unsigned& r0, unsigned& r1,
                                        unsigned& r2, unsigned& r3, const void* p) {
    unsigned a = (unsigned)__cvta_generic_to_shared(p);
    asm volatile("ldmatrix.sync.aligned.m8n8.x4.shared.b16 {%0,%1,%2,%3}, [%4];"
                 : "=r"(r0), "=r"(r1), "=r"(r2), "=r"(r3) : "r"(a));
}
__device__ __forceinline__ void ldsm_x4_t(unsigned& r0, unsigned& r1,
                                          unsigned& r2, unsigned& r3, const void* p) {
    unsigned a = (unsigned)__cvta_generic_to_shared(p);
    asm volatile("ldmatrix.sync.aligned.m8n8.x4.trans.shared.b16 {%0,%1,%2,%3}, [%4];"
                 : "=r"(r0), "=r"(r1), "=r"(r2), "=r"(r3) : "r"(a));
}

// ---------------------------------------------------------------------------
// prep: fp32->bf16 casts + code bytes.
// bid [0,22528): cast ; [22528,30720): code
// ---------------------------------------------------------------------------
__global__ __launch_bounds__(256) void prep_kernel(
    const float* __restrict__ mems, const float* __restrict__ h,
    const float* __restrict__ r, const float* __restrict__ wo,
    const float* __restrict__ seg_mat, const float* __restrict__ attn_mask)
{
    int bid = blockIdx.x;
    if (bid < 22528) {
        int idx = bid * 256 + threadIdx.x;   // < 11264*512
        int row = idx >> 9, p = idx & 511;
        const float* src;
        unsigned* dst;
        if (row < 2048)      { src = mems + (size_t)row * 1024;          dst = g_ab_u + (size_t)row * 512; }
        else if (row < 4096) { src = h + (size_t)(row - 2048) * 1024;    dst = g_ab_u + (size_t)row * 512; }
        else if (row < 10240){ src = r + (size_t)(row - 4096) * 1024;    dst = g_ab_u + (size_t)row * 512; }
        else                 { src = wo + (size_t)(row - 10240) * 1024;  dst = g_wob_u + (size_t)(row - 10240) * 512; }
        float2 v = *(const float2*)(src + p * 2);
        dst[p] = pk2(v.x, v.y);
    } else {
        int idx = (bid - 22528) * 256 + threadIdx.x;   // < 512*1024*4
        int b = idx & 3;
        int ij = idx >> 2;
        unsigned char c = (seg_mat[(size_t)idx * 2 + 1] != 0.f) ? 1 : 0;
        if (attn_mask[idx] != 0.f) c |= 2;
        g_code[((size_t)b << 19) + ij] = c;
    }
}

// ---------------------------------------------------------------------------
// pack: proj weights fp32 [k][n] -> bf16 pairs [w][n][k2] (smem transpose).
// grid (16 k2-tiles, 32 n-tiles, 4 w), block (32, 8).
// ---------------------------------------------------------------------------
__global__ void pack_kernel(
    const float* __restrict__ wq, const float* __restrict__ wk,
    const float* __restrict__ wv, const float* __restrict__ wr)
{
    __shared__ unsigned tile[32][33];
    const int w = blockIdx.z;
    const float* W = (w == 0) ? wq : (w == 1) ? wk : (w == 2) ? wv : wr;
    const int k2base = blockIdx.x * 32;
    const int nnbase = blockIdx.y * 32;
    const int tx = threadIdx.x, ty = threadIdx.y;
#pragma unroll
    for (int i = 0; i < 4; i++) {
        int k2 = k2base + ty + 8 * i;
        tile[ty + 8 * i][tx] = pk2(W[(size_t)(2 * k2) * 1024 + nnbase + tx],
                                   W[(size_t)(2 * k2 + 1) * 1024 + nnbase + tx]);
    }
    __syncthreads();
#pragma unroll
    for (int i = 0; i < 4; i++) {
        int nn = nnbase + ty + 8 * i;
        g_wpk_u[(size_t)w * 524288 + (size_t)nn * 512 + k2base + tx] = tile[tx][ty + 8 * i];
    }
}

// ---------------------------------------------------------------------------
// Projection GEMM (bf16, cp.async 4-stage, ldmatrix frags).
// A stage [2 sub][128 m][12], B stage [2 sub][128 n][12] (both k-contig).
// k/kr outputs pre-scaled by SCALE (exact pow2).
// ---------------------------------------------------------------------------
#define PSTG 4
#define PJA 3072
#define PROJ_SMEM ((PSTG * 2 * PJA) * 4)   // 98,304 B

__global__ __launch_bounds__(256, 2) void proj_mma()
{
    extern __shared__ unsigned psm[];
    unsigned* Asm = psm;
    unsigned* Bsm = psm + PSTG * PJA;

    const int rowbase = blockIdx.y * 128;
    const int colbase = blockIdx.x * 128;

    int abase, wsel, segbase;
    unsigned* Cu;
    float csc;
    if (rowbase < 2048)        { wsel = 0; segbase = 0;     abase = 2048; Cu = g_qb_u;  csc = 1.f;   }
    else if (rowbase < 6144)   { wsel = 1; segbase = 2048;  abase = 0;    Cu = g_kb_u;  csc = SCALE; }
    else if (rowbase < 10240)  { wsel = 2; segbase = 6144;  abase = 0;    Cu = g_vb_u;  csc = 1.f;   }
    else                       { wsel = 3; segbase = 10240; abase = 4096; Cu = g_krb_u; csc = SCALE; }
    const int crb = rowbase - segbase;

    const int tid = threadIdx.x;
    const int lane = tid & 31, warp = tid >> 5;
    const int wm = warp & 3, wn = warp >> 2;
    const int grp = lane >> 2, thr = lane & 3;
    const int rowA = (lane & 7) + (lane & 8);
    const int koA  = (lane & 16) >> 2;
    const int rowB = (lane & 7) + ((lane & 16) >> 1);
    const int kB   = (lane & 8) >> 1;

    const int arw = tid >> 1;
    const int asub = tid & 1;
    const unsigned* asrc = g_ab_u + (size_t)(abase + crb + arw) * 512 + asub * 8;
    const unsigned* bsrc = g_wpk_u + (size_t)wsel * 524288 + (size_t)(colbase + arw) * 512 + asub * 8;

    float acc[2][8][4];
#pragma unroll
    for (int mf = 0; mf < 2; mf++)
#pragma unroll
        for (int nf = 0; nf < 8; nf++)
#pragma unroll
            for (int q = 0; q < 4; q++) acc[mf][nf][q] = 0.f;

#define PROJ_ISSUE(it)                                                          \
    {                                                                           \
        int s_ = (it) & 3;                                                      \
        int k2base_ = (it) * 16;                                                \
        unsigned* ad = Asm + s_ * PJA + asub * 1536 + arw * 12;                 \
        cpa16(ad,     asrc + k2base_);                                          \
        cpa16(ad + 4, asrc + k2base_ + 4);                                      \
        unsigned* bd = Bsm + s_ * PJA + asub * 1536 + arw * 12;                 \
        cpa16(bd,     bsrc + k2base_);                                          \
        cpa16(bd + 4, bsrc + k2base_ + 4);                                      \
        CP_COMMIT();                                                            \
    }

    PROJ_ISSUE(0);
    PROJ_ISSUE(1);
    PROJ_ISSUE(2);

    for (int it = 0; it < 32; it++) {
        if (it >= 30) { CP_WAIT0(); } else { CP_WAIT2(); }
        __syncthreads();
        if (it + 3 < 32) PROJ_ISSUE(it + 3);
        const unsigned* Ast = Asm + (it & 3) * PJA;
        const unsigned* Bst = Bsm + (it & 3) * PJA;
#pragma unroll
        for (int s = 0; s < 2; s++) {
            const unsigned* As_ = Ast + s * 1536;
            const unsigned* Bs_ = Bst + s * 1536;
            unsigned a[2][4], bb[8][2];
#pragma unroll
            for (int mf = 0; mf < 2; mf++)
                ldsm_x4(a[mf][0], a[mf][1], a[mf][2], a[mf][3],
                        As_ + (wm * 32 + mf * 16 + rowA) * 12 + koA);
#pragma unroll
            for (int nf0 = 0; nf0 < 8; nf0 += 2) {
                unsigned t0, t1, t2, t3;
                ldsm_x4(t0, t1, t2, t3, Bs_ + (wn * 64 + nf0 * 8 + rowB) * 12 + kB);
                bb[nf0][0] = t0; bb[nf0][1] = t1;
                bb[nf0 + 1][0] = t2; bb[nf0 + 1][1] = t3;
            }
#pragma unroll
            for (int mf = 0; mf < 2; mf++)
#pragma unroll
                for (int nf = 0; nf < 8; nf++)
                    mma_bf16(acc[mf][nf], a[mf], bb[nf][0], bb[nf][1]);
        }
    }
#pragma unroll
    for (int mf = 0; mf < 2; mf++)
#pragma unroll
        for (int nf = 0; nf < 8; nf++) {
            int rr = crb + wm * 32 + mf * 16 + grp;
            int c2 = (colbase >> 1) + wn * 32 + nf * 4 + thr;
            Cu[(size_t)rr * 512 + c2] = pk2(acc[mf][nf][0] * csc, acc[mf][nf][1] * csc);
            Cu[(size_t)(rr + 8) * 512 + c2] = pk2(acc[mf][nf][2] * csc, acc[mf][nf][3] * csc);
        }
#undef PROJ_ISSUE
}

// ---------------------------------------------------------------------------
// Output GEMM (bf16, 4-stage, ldmatrix frags): g_ao = g_avb @ wob^T.
// ---------------------------------------------------------------------------
#define OJS 6144
#define OUT_SMEM ((PSTG * OJS) * 4)    // 98,304 B

__global__ __launch_bounds__(256, 2) void out_mma()
{
    extern __shared__ unsigned psm[];

    const int rowbase = blockIdx.y * 128;
    const int colbase = blockIdx.x * 128;
    const int tid = threadIdx.x;
    const int lane = tid & 31, warp = tid >> 5;
    const int wm = warp & 3, wn = warp >> 2;
    const int grp = lane >> 2, thr = lane & 3;
    const int rowA = (lane & 7) + (lane & 8);
    const int koA  = (lane & 16) >> 2;
    const int rowB = (lane & 7) + ((lane & 16) >> 1);
    const int kB   = (lane & 8) >> 1;

    float acc[2][8][4];
#pragma unroll
    for (int mf = 0; mf < 2; mf++)
#pragma unroll
        for (int nf = 0; nf < 8; nf++)
#pragma unroll
            for (int q = 0; q < 4; q++) acc[mf][nf][q] = 0.f;

#define OUT_ISSUE(it)                                                           \
    {                                                                           \
        int s_ = (it) & 3;                                                      \
        int k2base_ = (it) * 16;                                                \
        for (int t_ = tid; t_ < 512; t_ += 256) {                               \
            int row_ = (t_ & 255) >> 1;                                         \
            int sub_ = t_ & 1;                                                  \
            const unsigned* src_;                                               \
            unsigned* dst_;                                                     \
            if (t_ < 256) {                                                     \
                src_ = g_avb_u + (size_t)(rowbase + row_) * 512;                \
                dst_ = psm + s_ * OJS + sub_ * 1536 + row_ * 12;                \
            } else {                                                            \
                src_ = g_wob_u + (size_t)(colbase + row_) * 512;                \
                dst_ = psm + s_ * OJS + 3072 + sub_ * 1536 + row_ * 12;         \
            }                                                                   \
            cpa16(dst_,     src_ + k2base_ + sub_ * 8);                         \
            cpa16(dst_ + 4, src_ + k2base_ + sub_ * 8 + 4);                     \
        }                                                                       \
        CP_COMMIT();                                                            \
    }

    OUT_ISSUE(0);
    OUT_ISSUE(1);
    OUT_ISSUE(2);

    for (int it = 0; it < 32; it++) {
        if (it >= 30) { CP_WAIT0(); } else { CP_WAIT2(); }
        __syncthreads();
        if (it + 3 < 32) OUT_ISSUE(it + 3);
        const unsigned* stg = psm + (it & 3) * OJS;
#pragma unroll
        for (int s = 0; s < 2; s++) {
            const unsigned* As_ = stg + s * 1536;
            const unsigned* Bs_ = stg + 3072 + s * 1536;
            unsigned a[2][4], bb[8][2];
#pragma unroll
            for (int mf = 0; mf < 2; mf++)
                ldsm_x4(a[mf][0], a[mf][1], a[mf][2], a[mf][3],
                        As_ + (wm * 32 + mf * 16 + rowA) * 12 + koA);
#pragma unroll
            for (int nf0 = 0; nf0 < 8; nf0 += 2) {
                unsigned t0, t1, t2, t3;
                ldsm_x4(t0, t1, t2, t3, Bs_ + (wn * 64 + nf0 * 8 + rowB) * 12 + kB);
                bb[nf0][0] = t0; bb[nf0][1] = t1;
                bb[nf0 + 1][0] = t2; bb[nf0 + 1][1] = t3;
            }
#pragma unroll
            for (int mf = 0; mf < 2; mf++)
#pragma unroll
                for (int nf = 0; nf < 8; nf++)
                    mma_bf16(acc[mf][nf], a[mf], bb[nf][0], bb[nf][1]);
        }
    }
#pragma unroll
    for (int mf = 0; mf < 2; mf++)
#pragma unroll
        for (int nf = 0; nf < 8; nf++) {
            int rr = rowbase + wm * 32 + mf * 16 + grp;
            int cc = colbase + wn * 64 + nf * 8 + thr * 2;
            *(float2*)&g_ao[(size_t)rr * 1024 + cc] = make_float2(acc[mf][nf][0], acc[mf][nf][1]);
            *(float2*)&g_ao[(size_t)(rr + 8) * 1024 + cc] = make_float2(acc[mf][nf][2], acc[mf][nf][3]);
        }
#undef OUT_ISSUE
}

// ---------------------------------------------------------------------------
// post: de = SCALE*(ef1-ef0) (bid<2048) + u/t bias dots (bid>=2048).
// k/kr already pre-scaled -> u,t come out pre-scaled automatically.
// ---------------------------------------------------------------------------
__global__ __launch_bounds__(512) void post_kernel(
    const float* __restrict__ rsb, const float* __restrict__ seg_embed,
    const float* __restrict__ rwb, const float* __restrict__ rrb)
{
    const int n = threadIdx.x >> 5, lane = threadIdx.x & 31;
    if (blockIdx.x < 2048) {
        const int row = blockIdx.x;             // i*4+b
        const __nv_bfloat16* qb = (const __nv_bfloat16*)g_qb_u;
        float q1 = __bfloat162float(qb[(size_t)row * 1024 + n * 64 + lane]) + rsb[n * 64 + lane];
        float q2 = __bfloat162float(qb[(size_t)row * 1024 + n * 64 + lane + 32]) + rsb[n * 64 + lane + 32];
        float p0 = q1 * seg_embed[(0 * 16 + n) * 64 + lane] + q2 * seg_embed[(0 * 16 + n) * 64 + lane + 32];
        float p1 = q1 * seg_embed[(1 * 16 + n) * 64 + lane] + q2 * seg_embed[(1 * 16 + n) * 64 + lane + 32];
#pragma unroll
        for (int o = 16; o; o >>= 1) {
            p0 += __shfl_xor_sync(0xffffffffu, p0, o);
            p1 += __shfl_xor_sync(0xffffffffu, p1, o);
        }
        if (lane == 0)
            g_e[(size_t)row * 16 + n] = (p1 - p0) * SCALE;
    } else {
        int row = blockIdx.x - 2048;
        const __nv_bfloat16* src;
        const float* bias;
        float* dst;
        if (row < 4096) {
            src = (const __nv_bfloat16*)g_kb_u + (size_t)row * 1024;
            bias = rwb; dst = g_u + (size_t)row * 16;
        } else {
            row -= 4096;
            src = (const __nv_bfloat16*)g_krb_u + (size_t)row * 1024;
            bias = rrb; dst = g_t + (size_t)row * 16;
        }
        float p = __bfloat162float(src[n * 64 + lane]) * bias[n * 64 + lane]
                + __bfloat162float(src[n * 64 + lane + 32]) * bias[n * 64 + lane + 32];
#pragma unroll
        for (int o = 16; o; o >>= 1) p += __shfl_xor_sync(0xffffffffu, p, o);
        if (lane == 0) dst[n] = p;
    }
}

// ---------------------------------------------------------------------------
// Fused attention, warp-local, ldmatrix frags, pre-scaled inputs.
// Gw stride 88 (STS.64 conflict-free); rotating slab bases (no %3 in loops).
// smem u32: ks 2304, kru 6912, vs 2304, Ps 4608, Gw 11264, ub 64, tb 192
//   = 27,648 u32 = 110,592 B -> 2 blocks/SM.
// ---------------------------------------------------------------------------
#define ATT_SMEM_BYTES (27648 * 4)

__global__ __launch_bounds__(256, 2) void attn_kernel()
{
    extern __shared__ unsigned smu[];
    unsigned* ksu = smu;                        // 64 x 36
    unsigned* kru = smu + 2304;                 // 192 x 36 (3-panel ring)
    unsigned* vsu = smu + 9216;                 // 64 x 36
    unsigned* Psu = smu + 11520;                // 8 x [16 x 36]
    float* Gw  = (float*)(smu + 16128);         // 8 x [16 x 88]
    float* ub  = (float*)(smu + 27392);         // 64
    float* tb2 = (float*)(smu + 27456);         // 192 (ring)
    const __nv_bfloat16* vsb = (const __nv_bfloat16*)vsu;  // row stride 72 bf16

    const int b = blockIdx.x >> 4, n = blockIdx.x & 15;
    const int i0 = blockIdx.y * 128;
    const int tid = threadIdx.x;
    const int wm = tid >> 5, lane = tid & 31;
    const int grp = lane >> 2, thr = lane & 3;
    const int r0 = wm * 16 + grp;               // local rows r0, r0+8

    float* Gwp = Gw + wm * (16 * 88);
    unsigned* Pwp = Psu + wm * (16 * 36);

    const int row16 = (lane & 7) + ((lane & 16) >> 1);  // B-frag rows
    const int koB   = (lane & 8) >> 1;
    const int rowA  = (lane & 7) + (lane & 8);          // A-frag rows
    const int koA   = (lane & 16) >> 2;
    const int rowV  = lane & 15;
    const int colV8 = (lane & 16) >> 1;

    // ---- q fragments straight from global bf16 ----
    unsigned qa[4][4];
#pragma unroll
    for (int kc = 0; kc < 4; kc++) {
        size_t b0 = ((size_t)(i0 + r0) * 4 + b) * 512 + n * 32 + kc * 8;
        size_t b1 = ((size_t)(i0 + r0 + 8) * 4 + b) * 512 + n * 32 + kc * 8;
        qa[kc][0] = g_qb_u[b0 + thr];
        qa[kc][1] = g_qb_u[b1 + thr];
        qa[kc][2] = g_qb_u[b0 + thr + 4];
        qa[kc][3] = g_qb_u[b1 + thr + 4];
    }

    float de0 = g_e[((size_t)(i0 + r0) * 4 + b) * 16 + n];
    float de1 = g_e[((size_t)(i0 + r0 + 8) * 4 + b) * 16 + n];

    float oacc[8][4];
#pragma unroll
    for (int nt = 0; nt < 8; nt++)
#pragma unroll
        for (int q = 0; q < 4; q++) oacc[nt][q] = 0.f;
    float rmax[2] = {-3.0e38f, -3.0e38f};
    float rsum[2] = {0.f, 0.f};

    const unsigned char* codeRow0 = g_code + ((size_t)b << 19) + (size_t)(i0 + r0) * 1024;
    const unsigned char* codeRow1 = codeRow0 + 8 * 1024;

    // rotating slab bases for 3-panel ring (base advances 64/iter)
    int pp = ((384 - i0) >> 6) % 3;
    int sB0 = pp * 64;
    int sB1 = ((pp + 1) % 3) * 64;
    int sB2 = ((pp + 2) % 3) * 64;

    for (int j0 = 0; j0 < KLEN; j0 += 64) {
        __syncthreads();
        const int base = j0 - i0 + 384;
        for (int t = tid; t < 512; t += 256) {
            int row = t >> 3, c = (t & 7) * 4;
            size_t goff = ((size_t)(j0 + row) * 4 + b) * 512 + n * 32 + c;
            cpa16(&ksu[row * 36 + c], g_kb_u + goff);
            cpa16(&vsu[row * 36 + c], g_vb_u + goff);
        }
        const int startrow = (j0 == 0) ? 0 : 128;
        const int nload = 192 - startrow;
        for (int t = tid; t < nload * 8; t += 256) {
            int roff = startrow + (t >> 3), c = (t & 7) * 4;
            int sel = roff >> 6;
            int sb = (sel == 0) ? sB0 : ((sel == 1) ? sB1 : sB2);
            cpa16(&kru[(sb + (roff & 63)) * 36 + c],
                  g_krb_u + ((size_t)(base + roff) * 4 + b) * 512 + n * 32 + c);
        }
        CP_COMMIT();
        if (tid < 64) {
            ub[tid] = g_u[((size_t)(j0 + tid) * 4 + b) * 16 + n];
        } else if (tid < 64 + nload) {
            int o = startrow + (tid - 64);
            int sel = o >> 6;
            int sb = (sel == 0) ? sB0 : ((sel == 1) ? sB1 : sB2);
            tb2[sb + (o & 63)] = g_t[((size_t)(base + o) * 4 + b) * 16 + n];
        }
        CP_WAIT0();
        __syncthreads();

        // ---- S = q @ k^T ----
        float sacc[8][4];
#pragma unroll
        for (int nt = 0; nt < 8; nt++)
#pragma unroll
            for (int q = 0; q < 4; q++) sacc[nt][q] = 0.f;
#pragma unroll
        for (int kc = 0; kc < 4; kc++) {
#pragma unroll
            for (int p = 0; p < 4; p++) {
                unsigned k0, k1, k2, k3;
                ldsm_x4(k0, k1, k2, k3, &ksu[(16 * p + row16) * 36 + kc * 8 + koB]);
                mma_bf16(sacc[2 * p], qa[kc], k0, k1);
                mma_bf16(sacc[2 * p + 1], qa[kc], k2, k3);
            }
        }

        // ---- per-warp band G (16 x 80), +t folded at store (float2) ----
        const int woff = 112 - wm * 16;
#pragma unroll
        for (int p = 0; p < 5; p++) {
            int o = woff + 16 * p + row16;
            int sel = o >> 6;
            int sb = (sel == 0) ? sB0 : ((sel == 1) ? sB1 : sB2);
            int srow = sb + (o & 63);
            float ga[4] = {0.f, 0.f, 0.f, 0.f};
            float gb[4] = {0.f, 0.f, 0.f, 0.f};
#pragma unroll
            for (int kc = 0; kc < 4; kc++) {
                unsigned k0, k1, k2, k3;
                ldsm_x4(k0, k1, k2, k3, &kru[srow * 36 + kc * 8 + koB]);
                mma_bf16(ga, qa[kc], k0, k1);
                mma_bf16(gb, qa[kc], k2, k3);
            }
            int g0 = 16 * p + 2 * thr;
            int oA = woff + g0;
            int selA = oA >> 6;
            int sbA = (selA == 0) ? sB0 : ((selA == 1) ? sB1 : sB2);
            float2 tA = *(float2*)&tb2[sbA + (oA & 63)];
            int oB = oA + 8;
            int selB = oB >> 6;
            int sbB = (selB == 0) ? sB0 : ((selB == 1) ? sB1 : sB2);
            float2 tB = *(float2*)&tb2[sbB + (oB & 63)];
            *(float2*)&Gwp[grp * 88 + g0]           = make_float2(ga[0] + tA.x, ga[1] + tA.y);
            *(float2*)&Gwp[(grp + 8) * 88 + g0]     = make_float2(ga[2] + tA.x, ga[3] + tA.y);
            *(float2*)&Gwp[grp * 88 + g0 + 8]       = make_float2(gb[0] + tB.x, gb[1] + tB.y);
            *(float2*)&Gwp[(grp + 8) * 88 + g0 + 8] = make_float2(gb[2] + tB.x, gb[3] + tB.y);
        }
        __syncwarp();

        // ---- assemble logits (pre-scaled), warp-local row maxes ----
        float mx0 = -3.0e38f, mx1 = -3.0e38f;
#pragma unroll
        for (int nt = 0; nt < 8; nt++) {
            int c = nt * 8 + 2 * thr;
            int gi  = c - grp + 16;   // row r0 band index (parity = grp parity)
            int gi2 = c - grp + 8;    // row r0+8
            float G00, G01, G10, G11;
            if ((grp & 1) == 0) {
                float2 fa = *(float2*)&Gwp[grp * 88 + gi];
                float2 fb = *(float2*)&Gwp[(grp + 8) * 88 + gi2];
                G00 = fa.x; G01 = fa.y; G10 = fb.x; G11 = fb.y;
            } else {
                G00 = Gwp[grp * 88 + gi];
                G01 = Gwp[grp * 88 + gi + 1];
                G10 = Gwp[(grp + 8) * 88 + gi2];
                G11 = Gwp[(grp + 8) * 88 + gi2 + 1];
            }
            unsigned short w0 = *(const unsigned short*)(codeRow0 + j0 + c);
            unsigned short w1 = *(const unsigned short*)(codeRow1 + j0 + c);
            float2 uu = *(float2*)&ub[c];
            float v;
            v = sacc[nt][0] + G00 + uu.x + ((w0 & 1) ? de0 : 0.f);
            if (w0 & 2) v -= 1e30f;
            sacc[nt][0] = v; mx0 = fmaxf(mx0, v);
            v = sacc[nt][1] + G01 + uu.y + ((w0 & 256) ? de0 : 0.f);
            if (w0 & 512) v -= 1e30f;
            sacc[nt][1] = v; mx0 = fmaxf(mx0, v);
            v = sacc[nt][2] + G10 + uu.x + ((w1 & 1) ? de1 : 0.f);
            if (w1 & 2) v -= 1e30f;
            sacc[nt][2] = v; mx1 = fmaxf(mx1, v);
            v = sacc[nt][3] + G11 + uu.y + ((w1 & 256) ? de1 : 0.f);
            if (w1 & 512) v -= 1e30f;
            sacc[nt][3] = v; mx1 = fmaxf(mx1, v);
        }
#pragma unroll
        for (int o = 1; o < 4; o <<= 1) {
            mx0 = fmaxf(mx0, __shfl_xor_sync(0xffffffffu, mx0, o));
            mx1 = fmaxf(mx1, __shfl_xor_sync(0xffffffffu, mx1, o));
        }
        float nm0 = fmaxf(rmax[0], mx0);
        float nm1 = fmaxf(rmax[1], mx1);
        float corr0 = __expf(rmax[0] - nm0);
        float corr1 = __expf(rmax[1] - nm1);
        rmax[0] = nm0; rmax[1] = nm1;

        float sum0 = 0.f, sum1 = 0.f;
#pragma unroll
        for (int nt = 0; nt < 8; nt++) {
            float p0 = __expf(sacc[nt][0] - nm0);
            float p1 = __expf(sacc[nt][1] - nm0);
            float p2 = __expf(sacc[nt][2] - nm1);
            float p3 = __expf(sacc[nt][3] - nm1);
            sum0 += p0 + p1; sum1 += p2 + p3;
            Pwp[grp * 36 + nt * 4 + thr] = pk2(p0, p1);
            Pwp[(grp + 8) * 36 + nt * 4 + thr] = pk2(p2, p3);
        }
#pragma unroll
        for (int o = 1; o < 4; o <<= 1) {
            sum0 += __shfl_xor_sync(0xffffffffu, sum0, o);
            sum1 += __shfl_xor_sync(0xffffffffu, sum1, o);
        }
        rsum[0] = rsum[0] * corr0 + sum0;
        rsum[1] = rsum[1] * corr1 + sum1;
        __syncwarp();

        // ---- O = O*corr + P @ V ----
#pragma unroll
        for (int nt = 0; nt < 8; nt++) {
            oacc[nt][0] *= corr0; oacc[nt][1] *= corr0;
            oacc[nt][2] *= corr1; oacc[nt][3] *= corr1;
        }
#pragma unroll
        for (int kc = 0; kc < 4; kc++) {
            unsigned a[4];
            ldsm_x4(a[0], a[1], a[2], a[3], &Pwp[rowA * 36 + kc * 8 + koA]);
#pragma unroll
            for (int p = 0; p < 4; p++) {
                unsigned v0, v1, v2, v3;
                ldsm_x4_t(v0, v1, v2, v3,
                          vsb + (kc * 16 + rowV) * 72 + p * 16 + colV8);
                mma_bf16(oacc[2 * p], a, v0, v1);
                mma_bf16(oacc[2 * p + 1], a, v2, v3);
            }
        }

        // rotate slab bases (window advances one panel)
        int tmp = sB0; sB0 = sB1; sB1 = sB2; sB2 = tmp;
    }

    // ---- write normalized output (bf16) ----
    float inv0 = 1.f / rsum[0];
    float inv1 = 1.f / rsum[1];
#pragma unroll
    for (int nt = 0; nt < 8; nt++) {
        int d2 = n * 32 + nt * 4 + thr;
        g_avb_u[((size_t)(i0 + r0) * 4 + b) * 512 + d2] =
            pk2(oacc[nt][0] * inv0, oacc[nt][1] * inv0);
        g_avb_u[((size_t)(i0 + r0 + 8) * 4 + b) * 512 + d2] =
            pk2(oacc[nt][2] * inv1, oacc[nt][3] * inv1);
    }
}

// ---------------------------------------------------------------------------
// Residual + LayerNorm (single pass)
// ---------------------------------------------------------------------------
__global__ __launch_bounds__(256) void ln_kernel(
    const float* __restrict__ hres, const float* __restrict__ gamma,
    const float* __restrict__ beta, float* __restrict__ out)
{
    __shared__ float xb[1024];
    __shared__ float red1[8], red2[8];
    const int row = blockIdx.x;
    const int tid = threadIdx.x;
    const float* ao = g_ao + (size_t)row * 1024;
    const float* hh = hres + (size_t)row * 1024;

    float s = 0.f, s2 = 0.f;
    for (int c = tid; c < 1024; c += 256) {
        float x = ao[c] + hh[c];
        xb[c] = x;
        s += x;
        s2 += x * x;
    }
#pragma unroll
    for (int o = 16; o; o >>= 1) {
        s += __shfl_xor_sync(0xffffffffu, s, o);
        s2 += __shfl_xor_sync(0xffffffffu, s2, o);
    }
    if ((tid & 31) == 0) { red1[tid >> 5] = s; red2[tid >> 5] = s2; }
    __syncthreads();
    float tot = 0.f, tot2 = 0.f;
#pragma unroll
    for (int k = 0; k < 8; k++) { tot += red1[k]; tot2 += red2[k]; }
    const float mean = tot * (1.f / 1024.f);
    const float var = tot2 * (1.f / 1024.f) - mean * mean;
    const float inv = rsqrtf(var + LN_EPS);

    for (int c = tid; c < 1024; c += 256)
        out[(size_t)row * 1024 + c] = (xb[c] - mean) * inv * gamma[c] + beta[c];
}

// ---------------------------------------------------------------------------
extern "C" void kernel_launch(void* const* d_in, const int* in_sizes, int n_in,
                              void* d_out, int out_size)
{
    const float* rwb       = (const float*)d_in[0];
    const float* rsb       = (const float*)d_in[1];
    const float* rrb       = (const float*)d_in[2];
    const float* seg_embed = (const float*)d_in[3];
    const float* h         = (const float*)d_in[4];
    const float* r         = (const float*)d_in[5];
    const float* mems      = (const float*)d_in[6];
    const float* seg_mat   = (const float*)d_in[7];
    const float* attn_mask = (const float*)d_in[8];
    const float* wq        = (const float*)d_in[9];
    const float* wk        = (const float*)d_in[10];
    const float* wv        = (const float*)d_in[11];
    const float* wr        = (const float*)d_in[12];
    const float* wo        = (const float*)d_in[13];
    const float* gamma     = (const float*)d_in[14];
    const float* beta      = (const float*)d_in[15];

    cudaFuncSetAttribute(attn_kernel, cudaFuncAttributeMaxDynamicSharedMemorySize, ATT_SMEM_BYTES);
    cudaFuncSetAttribute(proj_mma, cudaFuncAttributeMaxDynamicSharedMemorySize, PROJ_SMEM);
    cudaFuncSetAttribute(out_mma, cudaFuncAttributeMaxDynamicSharedMemorySize, OUT_SMEM);

    prep_kernel<<<30720, 256>>>(mems, h, r, wo, seg_mat, attn_mask);
    pack_kernel<<<dim3(16, 32, 4), dim3(32, 8)>>>(wq, wk, wv, wr);
    proj_mma<<<dim3(8, 128), 256, PROJ_SMEM>>>();
    post_kernel<<<12288, 512>>>(rsb, seg_embed, rwb, rrb);
    attn_kernel<<<dim3(64, 4), 256, ATT_SMEM_BYTES>>>();
    out_mma<<<dim3(8, 16), 256, OUT_SMEM>>>();
    ln_kernel<<<2048, 256>>>(h, gamma, beta, (float*)d_out);
}